// round 3
// baseline (speedup 1.0000x reference)
#include <cuda_runtime.h>
#include <math.h>

#define BB 2
#define SQ 2048
#define SK 2048
#define DD 1024
#define HH 16
#define DK 64
#define MROWS (BB*SQ)   // 4096

// ---------------- scratch (device globals; no allocation allowed) ----------------
__device__ float g_Qp[BB*SQ*DD];   // Q projection, row-major (B*SQ, D)
__device__ float g_Vp[BB*SK*DD];   // V projection
__device__ float g_Rp[BB*SK*DD];   // R projection
__device__ float g_Hs[BB*SK*DD];   // recurrent states H_t
__device__ float g_O [BB*SQ*DD];   // attention output (pre-Wo)
__device__ float g_wrow[HH*DK];    // W_h.sum(-1)

// ---------------- W_h row-sum ----------------
__global__ void rowsum_kernel(const float* __restrict__ Wh) {
    int i = blockIdx.x * blockDim.x + threadIdx.x;   // over H*DK
    if (i < HH*DK) {
        const float* p = Wh + (size_t)i * DK;
        float s = 0.f;
        #pragma unroll
        for (int k = 0; k < DK; k++) s += p[k];
        g_wrow[i] = s;
    }
}

// ---------------- SGEMM: C[M,N] = A[M,K] @ W[N,K]^T + bias[N] ----------------
// 64x64 tile, K-tile 16, 256 threads, 4x4 per thread.
#define TM 64
#define TN 64
#define TK 16

__global__ __launch_bounds__(256) void sgemm_bias(
    const float* __restrict__ A, const float* __restrict__ W,
    const float* __restrict__ bias, float* __restrict__ C,
    int M, int N, int K)
{
    __shared__ float As[TK][TM + 4];
    __shared__ float Ws[TK][TN + 4];

    const int tid = threadIdx.x;
    const int tx = tid & 15, ty = tid >> 4;
    const int bm = blockIdx.y * TM, bn = blockIdx.x * TN;

    const int lr = tid >> 2;         // 0..63  (row within tile)
    const int lc = (tid & 3) * 4;    // 0,4,8,12 (k offset)

    float acc[4][4] = {};

    for (int k0 = 0; k0 < K; k0 += TK) {
        float4 a4 = *reinterpret_cast<const float4*>(A + (size_t)(bm + lr) * K + k0 + lc);
        float4 w4 = *reinterpret_cast<const float4*>(W + (size_t)(bn + lr) * K + k0 + lc);
        As[lc+0][lr] = a4.x; As[lc+1][lr] = a4.y; As[lc+2][lr] = a4.z; As[lc+3][lr] = a4.w;
        Ws[lc+0][lr] = w4.x; Ws[lc+1][lr] = w4.y; Ws[lc+2][lr] = w4.z; Ws[lc+3][lr] = w4.w;
        __syncthreads();

        #pragma unroll
        for (int kk = 0; kk < TK; kk++) {
            float4 rm = *reinterpret_cast<const float4*>(&As[kk][ty * 4]);
            float4 rn = *reinterpret_cast<const float4*>(&Ws[kk][tx * 4]);
            float rmv[4] = {rm.x, rm.y, rm.z, rm.w};
            float rnv[4] = {rn.x, rn.y, rn.z, rn.w};
            #pragma unroll
            for (int i = 0; i < 4; i++)
                #pragma unroll
                for (int j = 0; j < 4; j++)
                    acc[i][j] += rmv[i] * rnv[j];
        }
        __syncthreads();
    }

    #pragma unroll
    for (int i = 0; i < 4; i++) {
        int row = bm + ty * 4 + i;
        #pragma unroll
        for (int j = 0; j < 4; j++) {
            int col = bn + tx * 4 + j;
            C[(size_t)row * N + col] = acc[i][j] + bias[col];
        }
    }
}

// ---------------- recurrence: h_t = tanh(h_{t-1} * w + r_t) ----------------
// grid = B*H blocks, 64 threads (one per dk). Inherently serial over SK.
__global__ void recurrence_kernel() {
    int bh = blockIdx.x;
    int b = bh / HH, h = bh % HH;
    int d = threadIdx.x;
    float w = g_wrow[h * DK + d];
    float st = 0.f;
    const float* Rp = g_Rp + ((size_t)b * SK) * DD + h * DK + d;
    float*       Ho = g_Hs + ((size_t)b * SK) * DD + h * DK + d;
    for (int t = 0; t < SK; t++) {
        st = tanhf(st * w + Rp[(size_t)t * DD]);
        Ho[(size_t)t * DD] = st;
    }
}

// ---------------- flash-style attention, fp32 ----------------
// Per block: one (b,h), one 64-row q-tile. 256 threads.
// Strided 4x4 register tiling: thread (tx,ty) owns rows ty+16i, cols tx+16j.
#define QT 64
#define KT 64
#define SMPAD 68
#define ATT_SMEM (4 * 64 * SMPAD * 4)   // Qs,Ks,Vs,Ps = 69632 B

__global__ __launch_bounds__(256) void attention_kernel() {
    const int bh = blockIdx.y;
    const int b = bh / HH, h = bh % HH;
    const int q0 = blockIdx.x * QT;
    const int tid = threadIdx.x;
    const int tx = tid & 15, ty = tid >> 4;
    const float scale = 0.125f;   // 1/sqrt(64)

    extern __shared__ float sm[];
    float (*Qs)[SMPAD] = (float (*)[SMPAD])(sm);
    float (*Ks)[SMPAD] = (float (*)[SMPAD])(sm + 64 * SMPAD);
    float (*Vs)[SMPAD] = (float (*)[SMPAD])(sm + 2 * 64 * SMPAD);
    float (*Ps)[SMPAD] = (float (*)[SMPAD])(sm + 3 * 64 * SMPAD);

    const float* Qg = g_Qp + ((size_t)(b * SQ + q0)) * DD + h * DK;
    const float* Hg = g_Hs + ((size_t)(b * SK)) * DD + h * DK;
    const float* Vg = g_Vp + ((size_t)(b * SK)) * DD + h * DK;

    // load Q tile once
    #pragma unroll
    for (int e = tid * 4; e < 64 * 64; e += 256 * 4) {
        int r = e >> 6, c = e & 63;
        float4 v = *reinterpret_cast<const float4*>(Qg + (size_t)r * DD + c);
        *reinterpret_cast<float4*>(&Qs[r][c]) = v;
    }

    float m_i[4], l_i[4], acc[4][4];
    #pragma unroll
    for (int i = 0; i < 4; i++) {
        m_i[i] = -1e30f; l_i[i] = 0.f;
        #pragma unroll
        for (int j = 0; j < 4; j++) acc[i][j] = 0.f;
    }

    for (int k0 = 0; k0 < SK; k0 += KT) {
        __syncthreads();   // prev PV done + (first iter) Q visible
        #pragma unroll
        for (int e = tid * 4; e < 64 * 64; e += 256 * 4) {
            int r = e >> 6, c = e & 63;
            float4 kv = *reinterpret_cast<const float4*>(Hg + (size_t)(k0 + r) * DD + c);
            float4 vv = *reinterpret_cast<const float4*>(Vg + (size_t)(k0 + r) * DD + c);
            *reinterpret_cast<float4*>(&Ks[r][c]) = kv;
            *reinterpret_cast<float4*>(&Vs[r][c]) = vv;
        }
        __syncthreads();

        // S = Q @ K^T (this thread: rows ty+16i, cols tx+16j)
        float s[4][4] = {};
        #pragma unroll
        for (int d0 = 0; d0 < DK; d0 += 4) {
            float4 qv[4], kv[4];
            #pragma unroll
            for (int i = 0; i < 4; i++)
                qv[i] = *reinterpret_cast<const float4*>(&Qs[ty + 16 * i][d0]);
            #pragma unroll
            for (int j = 0; j < 4; j++)
                kv[j] = *reinterpret_cast<const float4*>(&Ks[tx + 16 * j][d0]);
            #pragma unroll
            for (int i = 0; i < 4; i++)
                #pragma unroll
                for (int j = 0; j < 4; j++) {
                    s[i][j] += qv[i].x * kv[j].x;
                    s[i][j] += qv[i].y * kv[j].y;
                    s[i][j] += qv[i].z * kv[j].z;
                    s[i][j] += qv[i].w * kv[j].w;
                }
        }

        // online softmax (rows reduced over tx via shfl; row-mates share warp)
        #pragma unroll
        for (int i = 0; i < 4; i++) {
            float rmax = -1e30f;
            #pragma unroll
            for (int j = 0; j < 4; j++) { s[i][j] *= scale; rmax = fmaxf(rmax, s[i][j]); }
            #pragma unroll
            for (int o = 1; o < 16; o <<= 1)
                rmax = fmaxf(rmax, __shfl_xor_sync(0xffffffffu, rmax, o));
            float mnew = fmaxf(m_i[i], rmax);
            float corr = __expf(m_i[i] - mnew);
            m_i[i] = mnew;
            l_i[i] *= corr;
            #pragma unroll
            for (int j = 0; j < 4; j++) {
                float p = __expf(s[i][j] - mnew);
                l_i[i] += p;
                Ps[ty + 16 * i][tx + 16 * j] = p;
            }
            #pragma unroll
            for (int j = 0; j < 4; j++) acc[i][j] *= corr;
        }
        __syncthreads();

        // acc += P @ V
        #pragma unroll 4
        for (int kk = 0; kk < KT; kk++) {
            float pv[4], vv[4];
            #pragma unroll
            for (int i = 0; i < 4; i++) pv[i] = Ps[ty + 16 * i][kk];
            #pragma unroll
            for (int j = 0; j < 4; j++) vv[j] = Vs[kk][tx + 16 * j];
            #pragma unroll
            for (int i = 0; i < 4; i++)
                #pragma unroll
                for (int j = 0; j < 4; j++)
                    acc[i][j] += pv[i] * vv[j];
        }
    }

    // finalize: divide by total row sum, store
    float* Og = g_O + ((size_t)(b * SQ + q0)) * DD + h * DK;
    #pragma unroll
    for (int i = 0; i < 4; i++) {
        float lt = l_i[i];
        #pragma unroll
        for (int o = 1; o < 16; o <<= 1)
            lt += __shfl_xor_sync(0xffffffffu, lt, o);
        float inv = 1.f / lt;
        int r = ty + 16 * i;
        #pragma unroll
        for (int j = 0; j < 4; j++)
            Og[(size_t)r * DD + tx + 16 * j] = acc[i][j] * inv;
    }
}

// ---------------- launch ----------------
extern "C" void kernel_launch(void* const* d_in, const int* in_sizes, int n_in,
                              void* d_out, int out_size) {
    const float* query = (const float*)d_in[0];
    // d_in[1] = key : unused by the reference computation
    const float* value = (const float*)d_in[2];
    const float* Rin   = (const float*)d_in[3];
    const float* Wq    = (const float*)d_in[4];
    const float* bq    = (const float*)d_in[5];
    const float* Wv    = (const float*)d_in[6];
    const float* bv    = (const float*)d_in[7];
    const float* Wr    = (const float*)d_in[8];
    const float* br    = (const float*)d_in[9];
    const float* Wh    = (const float*)d_in[10];
    const float* Wo    = (const float*)d_in[11];
    const float* bo    = (const float*)d_in[12];
    float* out = (float*)d_out;

    float *Qp, *Vp, *Rp, *Op;
    cudaGetSymbolAddress((void**)&Qp, g_Qp);
    cudaGetSymbolAddress((void**)&Vp, g_Vp);
    cudaGetSymbolAddress((void**)&Rp, g_Rp);
    cudaGetSymbolAddress((void**)&Op, g_O);

    cudaFuncSetAttribute(attention_kernel,
                         cudaFuncAttributeMaxDynamicSharedMemorySize, ATT_SMEM);

    rowsum_kernel<<<(HH * DK + 127) / 128, 128>>>(Wh);

    dim3 gproj(DD / TN, MROWS / TM);   // (16, 64)
    sgemm_bias<<<gproj, 256>>>(query, Wq, bq, Qp, MROWS, DD, DD);
    sgemm_bias<<<gproj, 256>>>(value, Wv, bv, Vp, MROWS, DD, DD);
    sgemm_bias<<<gproj, 256>>>(Rin,   Wr, br, Rp, MROWS, DD, DD);

    recurrence_kernel<<<BB * HH, DK>>>();

    attention_kernel<<<dim3(SQ / QT, BB * HH), 256, ATT_SMEM>>>();

    sgemm_bias<<<gproj, 256>>>(Op, Wo, bo, out, MROWS, DD, DD);
}

// round 9
// speedup vs baseline: 2.5369x; 2.5369x over previous
#include <cuda_runtime.h>
#include <cuda_bf16.h>
#include <math.h>
#include <stdint.h>

#define BB 2
#define SQ 2048
#define SK 2048
#define DD 1024
#define HH 16
#define DK 64
#define MROWS (BB*SQ)   // 4096

// fold softmax scale (1/8) * log2(e) into Q projection output
#define QK_SCALE (0.125f * 1.4426950408889634f)

// ---------------- scratch (device globals; no allocation allowed) ----------------
__device__ float g_Rp[BB*SK*DD];      // R projection f32 (recurrence input)
__device__ float g_O [BB*SQ*DD];      // attention output f32 (pre-Wo)
__device__ float g_wrow[HH*DK];
__device__ __nv_bfloat16 g_Ah[MROWS*DD];   // GEMM A staging (hi)
__device__ __nv_bfloat16 g_Al[MROWS*DD];   // GEMM A staging (lo)
__device__ __nv_bfloat16 g_Wh[DD*DD];
__device__ __nv_bfloat16 g_Wl[DD*DD];
__device__ __nv_bfloat16 g_Qh[MROWS*DD];   // scaled Q proj
__device__ __nv_bfloat16 g_Ql[MROWS*DD];
__device__ __nv_bfloat16 g_Vh[MROWS*DD];   // V proj
__device__ __nv_bfloat16 g_Vl[MROWS*DD];
__device__ __nv_bfloat16 g_Hh[MROWS*DD];   // recurrent states
__device__ __nv_bfloat16 g_Hl[MROWS*DD];

// ---------------- helpers ----------------
__device__ __forceinline__ uint32_t smem_to_u32(const void* p) {
    uint32_t a;
    asm("{ .reg .u64 t; cvta.to.shared.u64 t, %1; cvt.u32.u64 %0, t; }" : "=r"(a) : "l"(p));
    return a;
}
__device__ __forceinline__ uint32_t lds32(uint32_t addr) {
    uint32_t v; asm volatile("ld.shared.b32 %0, [%1];" : "=r"(v) : "r"(addr)); return v;
}
__device__ __forceinline__ float ex2f(float x) {
    float r; asm("ex2.approx.f32 %0, %1;" : "=f"(r) : "f"(x)); return r;
}
#define CP_ASYNC16(dst, src) \
    asm volatile("cp.async.cg.shared.global [%0], [%1], 16;" :: "r"(dst), "l"(src) : "memory")
#define CP_COMMIT() asm volatile("cp.async.commit_group;" ::: "memory")
#define CP_WAIT1() asm volatile("cp.async.wait_group 1;" ::: "memory")
#define CP_WAIT0() asm volatile("cp.async.wait_group 0;" ::: "memory")

// mma.sync m16n8k16 bf16 -> f32 accumulate (sm_80+, works in compute_103 PTX)
__device__ __forceinline__ void mma16816(float* d, const uint32_t* a, uint32_t b0, uint32_t b1) {
    asm volatile("mma.sync.aligned.m16n8k16.row.col.f32.bf16.bf16.f32 "
        "{%0,%1,%2,%3}, {%4,%5,%6,%7}, {%8,%9}, {%0,%1,%2,%3};"
        : "+f"(d[0]), "+f"(d[1]), "+f"(d[2]), "+f"(d[3])
        : "r"(a[0]), "r"(a[1]), "r"(a[2]), "r"(a[3]), "r"(b0), "r"(b1));
}

// pack two floats into (hi-pair, lo-pair) bf16x2: low half = x, high half = y
__device__ __forceinline__ void split2(float x, float y, uint32_t& hi, uint32_t& lo) {
    __nv_bfloat16 xh = __float2bfloat16_rn(x), yh = __float2bfloat16_rn(y);
    float xr = x - __bfloat162float(xh), yr = y - __bfloat162float(yh);
    __nv_bfloat16 xl = __float2bfloat16_rn(xr), yl = __float2bfloat16_rn(yr);
    hi = ((uint32_t)__bfloat16_as_ushort(yh) << 16) | __bfloat16_as_ushort(xh);
    lo = ((uint32_t)__bfloat16_as_ushort(yl) << 16) | __bfloat16_as_ushort(xl);
}

// ---------------- f32 -> (bf16 hi, bf16 lo) split ----------------
__global__ void conv_split_kernel(const float* __restrict__ in,
                                  __nv_bfloat16* __restrict__ hi,
                                  __nv_bfloat16* __restrict__ lo, int n4) {
    int i = blockIdx.x * blockDim.x + threadIdx.x;
    if (i >= n4) return;
    float4 v = reinterpret_cast<const float4*>(in)[i];
    uint32_t h0, l0, h1, l1;
    split2(v.x, v.y, h0, l0);
    split2(v.z, v.w, h1, l1);
    reinterpret_cast<uint2*>(hi)[i] = make_uint2(h0, h1);
    reinterpret_cast<uint2*>(lo)[i] = make_uint2(l0, l1);
}

// ---------------- mma.sync GEMM: C[4096,1024] = A @ W^T + bias ----------------
// CTA tile 128x128, K-tile 32, 8 warps (4x2), warp tile 32x64, bf16 3-pass split.
#define GSTR 80          // smem row stride in bytes (32 bf16 + 8 pad)
#define GARR 10240       // 128 * 80 bytes per operand array
#define GSTG 40960       // 4 arrays per stage
#define GEMM_SMEM (2*GSTG)   // 81920

__global__ __launch_bounds__(256) void gemm_mma(
    const __nv_bfloat16* __restrict__ Ah, const __nv_bfloat16* __restrict__ Al,
    const __nv_bfloat16* __restrict__ Wh, const __nv_bfloat16* __restrict__ Wl,
    const float* __restrict__ bias,
    float* __restrict__ Cf,                 // f32 output (or null)
    __nv_bfloat16* __restrict__ Chi,        // bf16 split output (or null)
    __nv_bfloat16* __restrict__ Clo,
    float cscale)
{
    extern __shared__ __align__(16) char sm[];
    const uint32_t sb = smem_to_u32(sm);
    const int tid = threadIdx.x;
    const int warp = tid >> 5, lane = tid & 31;
    const int g = lane >> 2, tg = lane & 3;
    const int wm = warp >> 1, wn = warp & 1;      // 4 x 2 warp grid
    const int bm = blockIdx.y * 128, bn = blockIdx.x * 128;

    auto load_stage = [&](int kt) {
        const uint32_t base = sb + (kt & 1) * GSTG;
        const int kofs = kt * 32;
        for (int t = tid; t < 512; t += 256) {
            int r = t >> 2, c = t & 3;
            uint32_t d0 = base + r * GSTR + c * 16;
            size_t ga = (size_t)(bm + r) * DD + kofs + c * 8;
            size_t gw = (size_t)(bn + r) * DD + kofs + c * 8;
            CP_ASYNC16(d0,            Ah + ga);
            CP_ASYNC16(d0 + GARR,     Al + ga);
            CP_ASYNC16(d0 + 2*GARR,   Wh + gw);
            CP_ASYNC16(d0 + 3*GARR,   Wl + gw);
        }
    };

    float acc[2][8][4];
    #pragma unroll
    for (int mi = 0; mi < 2; mi++)
        #pragma unroll
        for (int ni = 0; ni < 8; ni++)
            #pragma unroll
            for (int q = 0; q < 4; q++) acc[mi][ni][q] = 0.f;

    load_stage(0); CP_COMMIT();
    load_stage(1); CP_COMMIT();

    const int NT = 32;
    for (int kt = 0; kt < NT; kt++) {
        if (kt == NT - 1) { CP_WAIT0(); } else { CP_WAIT1(); }
        __syncthreads();
        const uint32_t base = sb + (kt & 1) * GSTG;

        #pragma unroll
        for (int kc = 0; kc < 2; kc++) {
            uint32_t ah[2][4], al[2][4];
            #pragma unroll
            for (int mi = 0; mi < 2; mi++) {
                uint32_t ar = base + (wm*32 + mi*16 + g) * GSTR + kc*32 + tg*4;
                ah[mi][0] = lds32(ar);            ah[mi][1] = lds32(ar + 8*GSTR);
                ah[mi][2] = lds32(ar + 16);       ah[mi][3] = lds32(ar + 8*GSTR + 16);
                uint32_t arl = ar + GARR;
                al[mi][0] = lds32(arl);           al[mi][1] = lds32(arl + 8*GSTR);
                al[mi][2] = lds32(arl + 16);      al[mi][3] = lds32(arl + 8*GSTR + 16);
            }
            #pragma unroll
            for (int ni = 0; ni < 8; ni++) {
                uint32_t br = base + 2*GARR + (wn*64 + ni*8 + g) * GSTR + kc*32 + tg*4;
                uint32_t bh0 = lds32(br), bh1 = lds32(br + 16);
                uint32_t bl0 = lds32(br + GARR), bl1 = lds32(br + GARR + 16);
                #pragma unroll
                for (int mi = 0; mi < 2; mi++) {
                    mma16816(acc[mi][ni], ah[mi], bh0, bh1);
                    mma16816(acc[mi][ni], ah[mi], bl0, bl1);
                    mma16816(acc[mi][ni], al[mi], bh0, bh1);
                }
            }
        }
        __syncthreads();
        if (kt + 2 < NT) { load_stage(kt + 2); CP_COMMIT(); }
    }

    // epilogue
    #pragma unroll
    for (int mi = 0; mi < 2; mi++) {
        int row = bm + wm*32 + mi*16 + g;
        #pragma unroll
        for (int ni = 0; ni < 8; ni++) {
            int col = bn + wn*64 + ni*8 + tg*2;
            float b0 = bias[col], b1 = bias[col + 1];
            float v0 = acc[mi][ni][0] + b0, v1 = acc[mi][ni][1] + b1;
            float v2 = acc[mi][ni][2] + b0, v3 = acc[mi][ni][3] + b1;
            if (Cf) {
                *reinterpret_cast<float2*>(&Cf[(size_t)row * DD + col])     = make_float2(v0, v1);
                *reinterpret_cast<float2*>(&Cf[(size_t)(row+8) * DD + col]) = make_float2(v2, v3);
            } else {
                uint32_t h01, l01, h23, l23;
                split2(v0 * cscale, v1 * cscale, h01, l01);
                split2(v2 * cscale, v3 * cscale, h23, l23);
                *reinterpret_cast<uint32_t*>(&Chi[(size_t)row * DD + col])     = h01;
                *reinterpret_cast<uint32_t*>(&Clo[(size_t)row * DD + col])     = l01;
                *reinterpret_cast<uint32_t*>(&Chi[(size_t)(row+8) * DD + col]) = h23;
                *reinterpret_cast<uint32_t*>(&Clo[(size_t)(row+8) * DD + col]) = l23;
            }
        }
    }
}

// ---------------- W_h row-sum ----------------
__global__ void rowsum_kernel(const float* __restrict__ Wh) {
    int i = blockIdx.x * blockDim.x + threadIdx.x;
    if (i < HH*DK) {
        const float* p = Wh + (size_t)i * DK;
        float s = 0.f;
        #pragma unroll
        for (int k = 0; k < DK; k++) s += p[k];
        g_wrow[i] = s;
    }
}

// ---------------- recurrence: h_t = tanh(h_{t-1}*w + r_t) -> bf16 hi/lo ----------------
__global__ void recurrence_kernel() {
    int bh = blockIdx.x;
    int b = bh / HH, h = bh % HH;
    int d = threadIdx.x;
    float w = g_wrow[h * DK + d];
    float st = 0.f;
    const float* Rp = g_Rp + ((size_t)b * SK) * DD + h * DK + d;
    size_t ho = ((size_t)b * SK) * DD + h * DK + d;
    #pragma unroll 1
    for (int t = 0; t < SK; t += 8) {
        float r[8];
        #pragma unroll
        for (int i = 0; i < 8; i++) r[i] = Rp[(size_t)(t + i) * DD];
        #pragma unroll
        for (int i = 0; i < 8; i++) {
            st = tanhf(st * w + r[i]);
            __nv_bfloat16 hh = __float2bfloat16_rn(st);
            __nv_bfloat16 hl = __float2bfloat16_rn(st - __bfloat162float(hh));
            g_Hh[ho + (size_t)(t + i) * DD] = hh;
            g_Hl[ho + (size_t)(t + i) * DD] = hl;
        }
    }
}

// ---------------- flash attention with mma.sync bf16 split ----------------
// CTA: one (b,h), 64 q-rows, 128 threads (4 warps x 16 rows). KT=64 keys/iter.
// smem (bytes): rows stride 144 (72 bf16); arrays of 64*144 = 9216 each
#define AQH 0
#define AQL 9216
#define AHH 18432
#define AHL 27648
#define AVH 36864
#define AVL 46080
#define ATT_SMEM 55296

__global__ __launch_bounds__(128) void attn_mma() {
    const int bh = blockIdx.y;
    const int b = bh >> 4, h = bh & 15;
    const int q0 = blockIdx.x * 64;
    const int tid = threadIdx.x;
    const int warp = tid >> 5, lane = tid & 31;
    const int g = lane >> 2, tg = lane & 3;

    extern __shared__ __align__(16) char sm[];
    const uint32_t sb = smem_to_u32(sm);
    uint32_t* sVh32 = (uint32_t*)(sm + AVH);
    uint32_t* sVl32 = (uint32_t*)(sm + AVL);

    const size_t qbase = (size_t)(b * SQ + q0);
    const size_t kbase = (size_t)(b * SK);
    const int hofs = h * DK;

    // Q tile (hi+lo) via cp.async, loaded once
    for (int t = tid; t < 512; t += 128) {
        int r = t >> 3, c = t & 7;
        uint32_t dst = sb + AQH + r * 144 + c * 16;
        size_t src = (qbase + r) * DD + hofs + c * 8;
        CP_ASYNC16(dst,              g_Qh + src);
        CP_ASYNC16(dst + (AQL-AQH),  g_Ql + src);
    }
    CP_COMMIT();

    float acc[8][4];
    #pragma unroll
    for (int n = 0; n < 8; n++)
        #pragma unroll
        for (int q = 0; q < 4; q++) acc[n][q] = 0.f;
    float mrow0 = -1e30f, mrow1 = -1e30f, lrow0 = 0.f, lrow1 = 0.f;

    for (int kt = 0; kt < SK / 64; kt++) {
        const int k0 = kt * 64;
        __syncthreads();    // previous iter done reading H/V smem

        // H tile (hi+lo) via cp.async
        for (int t = tid; t < 512; t += 128) {
            int r = t >> 3, c = t & 7;
            uint32_t dst = sb + AHH + r * 144 + c * 16;
            size_t src = (kbase + k0 + r) * DD + hofs + c * 8;
            CP_ASYNC16(dst,             g_Hh + src);
            CP_ASYNC16(dst + 9216,      g_Hl + src);
        }
        CP_COMMIT();

        // V tile transposed into key-pair u32 words: sVt[dim][keypair], stride 36 words
        for (int t = tid; t < 256; t += 128) {
            int rp = t & 31, c = t >> 5;     // second pass: c 4..7
            size_t src = (kbase + k0 + 2 * rp) * DD + hofs + c * 8;
            uint4 h0 = *reinterpret_cast<const uint4*>(g_Vh + src);
            uint4 h1 = *reinterpret_cast<const uint4*>(g_Vh + src + DD);
            uint4 l0 = *reinterpret_cast<const uint4*>(g_Vl + src);
            uint4 l1 = *reinterpret_cast<const uint4*>(g_Vl + src + DD);
            const ushort* ph0 = (const ushort*)&h0; const ushort* ph1 = (const ushort*)&h1;
            const ushort* pl0 = (const ushort*)&l0; const ushort* pl1 = (const ushort*)&l1;
            #pragma unroll
            for (int i = 0; i < 8; i++) {
                sVh32[(c*8 + i)*36 + rp] = ((uint32_t)ph1[i] << 16) | ph0[i];
                sVl32[(c*8 + i)*36 + rp] = ((uint32_t)pl1[i] << 16) | pl0[i];
            }
        }
        CP_WAIT0();
        __syncthreads();

        // ---- S = Qs . Hs^T  (scale*log2e already folded into Q) ----
        float s[8][4];
        #pragma unroll
        for (int n = 0; n < 8; n++)
            #pragma unroll
            for (int q = 0; q < 4; q++) s[n][q] = 0.f;

        #pragma unroll
        for (int kc = 0; kc < 4; kc++) {
            uint32_t qh[4], ql[4];
            uint32_t ar = sb + AQH + (warp*16 + g) * 144 + kc*32 + tg*4;
            qh[0] = lds32(ar);       qh[1] = lds32(ar + 8*144);
            qh[2] = lds32(ar + 16);  qh[3] = lds32(ar + 8*144 + 16);
            uint32_t arl = ar + (AQL - AQH);
            ql[0] = lds32(arl);      ql[1] = lds32(arl + 8*144);
            ql[2] = lds32(arl + 16); ql[3] = lds32(arl + 8*144 + 16);
            #pragma unroll
            for (int ni = 0; ni < 8; ni++) {
                uint32_t br = sb + AHH + (ni*8 + g) * 144 + kc*32 + tg*4;
                uint32_t bh0 = lds32(br),        bh1 = lds32(br + 16);
                uint32_t bl0 = lds32(br + 9216), bl1 = lds32(br + 9216 + 16);
                mma16816(s[ni], qh, bh0, bh1);
                mma16816(s[ni], qh, bl0, bl1);
                mma16816(s[ni], ql, bh0, bh1);
            }
        }

        // ---- online softmax (base-2) ----
        float tm0 = mrow0, tm1 = mrow1;
        #pragma unroll
        for (int n = 0; n < 8; n++) {
            tm0 = fmaxf(tm0, fmaxf(s[n][0], s[n][1]));
            tm1 = fmaxf(tm1, fmaxf(s[n][2], s[n][3]));
        }
        tm0 = fmaxf(tm0, __shfl_xor_sync(0xffffffffu, tm0, 1));
        tm0 = fmaxf(tm0, __shfl_xor_sync(0xffffffffu, tm0, 2));
        tm1 = fmaxf(tm1, __shfl_xor_sync(0xffffffffu, tm1, 1));
        tm1 = fmaxf(tm1, __shfl_xor_sync(0xffffffffu, tm1, 2));
        float corr0 = ex2f(mrow0 - tm0), corr1 = ex2f(mrow1 - tm1);
        mrow0 = tm0; mrow1 = tm1;
        lrow0 *= corr0; lrow1 *= corr1;

        uint32_t pah[4][4], pal[4][4];
        #pragma unroll
        for (int n = 0; n < 8; n++) {
            float p0 = ex2f(s[n][0] - tm0), p1 = ex2f(s[n][1] - tm0);
            float p2 = ex2f(s[n][2] - tm1), p3 = ex2f(s[n][3] - tm1);
            lrow0 += p0 + p1; lrow1 += p2 + p3;
            int kc = n >> 1, hf = (n & 1) * 2;
            split2(p0, p1, pah[kc][hf],     pal[kc][hf]);
            split2(p2, p3, pah[kc][hf + 1], pal[kc][hf + 1]);
        }
        #pragma unroll
        for (int n = 0; n < 8; n++) {
            acc[n][0] *= corr0; acc[n][1] *= corr0;
            acc[n][2] *= corr1; acc[n][3] *= corr1;
        }

        // ---- acc += P . V ----
        #pragma unroll
        for (int kc = 0; kc < 4; kc++) {
            #pragma unroll
            for (int nd = 0; nd < 8; nd++) {
                uint32_t br = sb + AVH + ((nd*8 + g)*36 + kc*8 + tg) * 4;
                uint32_t bh0 = lds32(br),                 bh1 = lds32(br + 16);
                uint32_t bl0 = lds32(br + (AVL - AVH)),   bl1 = lds32(br + (AVL - AVH) + 16);
                mma16816(acc[nd], pah[kc], bh0, bh1);
                mma16816(acc[nd], pah[kc], bl0, bl1);
                mma16816(acc[nd], pal[kc], bh0, bh1);
            }
        }
    }

    // epilogue: normalize and write g_O (f32)
    lrow0 += __shfl_xor_sync(0xffffffffu, lrow0, 1);
    lrow0 += __shfl_xor_sync(0xffffffffu, lrow0, 2);
    lrow1 += __shfl_xor_sync(0xffffffffu, lrow1, 1);
    lrow1 += __shfl_xor_sync(0xffffffffu, lrow1, 2);
    float inv0 = 1.f / lrow0, inv1 = 1.f / lrow1;
    #pragma unroll
    for (int nd = 0; nd < 8; nd++) {
        size_t row = qbase + warp*16 + g;
        int col = hofs + nd*8 + tg*2;
        *reinterpret_cast<float2*>(&g_O[row * DD + col]) =
            make_float2(acc[nd][0] * inv0, acc[nd][1] * inv0);
        *reinterpret_cast<float2*>(&g_O[(row + 8) * DD + col]) =
            make_float2(acc[nd][2] * inv1, acc[nd][3] * inv1);
    }
}

// ---------------- launch ----------------
extern "C" void kernel_launch(void* const* d_in, const int* in_sizes, int n_in,
                              void* d_out, int out_size) {
    const float* query = (const float*)d_in[0];
    // d_in[1] = key : unused by the reference computation
    const float* value = (const float*)d_in[2];
    const float* Rin   = (const float*)d_in[3];
    const float* Wq    = (const float*)d_in[4];
    const float* bq    = (const float*)d_in[5];
    const float* Wv    = (const float*)d_in[6];
    const float* bv    = (const float*)d_in[7];
    const float* Wr    = (const float*)d_in[8];
    const float* br    = (const float*)d_in[9];
    const float* Wh    = (const float*)d_in[10];
    const float* Wo    = (const float*)d_in[11];
    const float* bo    = (const float*)d_in[12];
    float* out = (float*)d_out;

    float *Rp, *Op;
    __nv_bfloat16 *Ah, *Al, *Wbh, *Wbl, *Qh, *Ql, *Vh, *Vl;
    cudaGetSymbolAddress((void**)&Rp, g_Rp);
    cudaGetSymbolAddress((void**)&Op, g_O);
    cudaGetSymbolAddress((void**)&Ah, g_Ah);
    cudaGetSymbolAddress((void**)&Al, g_Al);
    cudaGetSymbolAddress((void**)&Wbh, g_Wh);
    cudaGetSymbolAddress((void**)&Wbl, g_Wl);
    cudaGetSymbolAddress((void**)&Qh, g_Qh);
    cudaGetSymbolAddress((void**)&Ql, g_Ql);
    cudaGetSymbolAddress((void**)&Vh, g_Vh);
    cudaGetSymbolAddress((void**)&Vl, g_Vl);

    cudaFuncSetAttribute(gemm_mma,
                         cudaFuncAttributeMaxDynamicSharedMemorySize, GEMM_SMEM);
    cudaFuncSetAttribute(attn_mma,
                         cudaFuncAttributeMaxDynamicSharedMemorySize, ATT_SMEM);

    const int nA4 = MROWS * DD / 4;
    const int nW4 = DD * DD / 4;
    dim3 ggemm(DD / 128, MROWS / 128);      // (8, 32)

    rowsum_kernel<<<(HH * DK + 127) / 128, 128>>>(Wh);

    // Q projection -> scaled bf16 split
    conv_split_kernel<<<nA4 / 256, 256>>>(query, Ah, Al, nA4);
    conv_split_kernel<<<nW4 / 256, 256>>>(Wq, Wbh, Wbl, nW4);
    gemm_mma<<<ggemm, 256, GEMM_SMEM>>>(Ah, Al, Wbh, Wbl, bq, nullptr, Qh, Ql, QK_SCALE);

    // V projection -> bf16 split
    conv_split_kernel<<<nA4 / 256, 256>>>(value, Ah, Al, nA4);
    conv_split_kernel<<<nW4 / 256, 256>>>(Wv, Wbh, Wbl, nW4);
    gemm_mma<<<ggemm, 256, GEMM_SMEM>>>(Ah, Al, Wbh, Wbl, bv, nullptr, Vh, Vl, 1.0f);

    // R projection -> f32
    conv_split_kernel<<<nA4 / 256, 256>>>(Rin, Ah, Al, nA4);
    conv_split_kernel<<<nW4 / 256, 256>>>(Wr, Wbh, Wbl, nW4);
    gemm_mma<<<ggemm, 256, GEMM_SMEM>>>(Ah, Al, Wbh, Wbl, br, Rp, nullptr, nullptr, 1.0f);

    recurrence_kernel<<<BB * HH, DK>>>();

    attn_mma<<<dim3(SQ / 64, BB * HH), 128, ATT_SMEM>>>();

    // output projection -> f32 out
    conv_split_kernel<<<nA4 / 256, 256>>>(Op, Ah, Al, nA4);
    conv_split_kernel<<<nW4 / 256, 256>>>(Wo, Wbh, Wbl, nW4);
    gemm_mma<<<ggemm, 256, GEMM_SMEM>>>(Ah, Al, Wbh, Wbl, bo, out, nullptr, nullptr, 1.0f);
}

// round 10
// speedup vs baseline: 2.7758x; 1.0941x over previous
#include <cuda_runtime.h>
#include <cuda_bf16.h>
#include <math.h>
#include <stdint.h>

#define BB 2
#define SQ 2048
#define SK 2048
#define DD 1024
#define HH 16
#define DK 64
#define MROWS (BB*SQ)   // 4096

// fold softmax scale (1/8) * log2(e) into Q projection output
#define QK_SCALE (0.125f * 1.4426950408889634f)

// ---------------- scratch (device globals; no allocation allowed) ----------------
__device__ float g_Rp[BB*SK*DD];           // R projection f32 (recurrence input)
__device__ float g_wrow[HH*DK];
__device__ __nv_bfloat16 g_Ah[MROWS*DD];   // GEMM A staging (hi) / attn output hi
__device__ __nv_bfloat16 g_Al[MROWS*DD];   // GEMM A staging (lo) / attn output lo
__device__ __nv_bfloat16 g_Wh[DD*DD];
__device__ __nv_bfloat16 g_Wl[DD*DD];
__device__ __nv_bfloat16 g_Qh[MROWS*DD];   // scaled Q proj
__device__ __nv_bfloat16 g_Ql[MROWS*DD];
__device__ __nv_bfloat16 g_Vh[MROWS*DD];   // V proj
__device__ __nv_bfloat16 g_Vl[MROWS*DD];
__device__ __nv_bfloat16 g_Hh[MROWS*DD];   // recurrent states
__device__ __nv_bfloat16 g_Hl[MROWS*DD];

// ---------------- helpers ----------------
__device__ __forceinline__ uint32_t smem_to_u32(const void* p) {
    uint32_t a;
    asm("{ .reg .u64 t; cvta.to.shared.u64 t, %1; cvt.u32.u64 %0, t; }" : "=r"(a) : "l"(p));
    return a;
}
__device__ __forceinline__ float ex2f(float x) {
    float r; asm("ex2.approx.f32 %0, %1;" : "=f"(r) : "f"(x)); return r;
}
__device__ __forceinline__ void ldsm4(uint32_t& r0, uint32_t& r1, uint32_t& r2, uint32_t& r3,
                                      uint32_t addr) {
    asm volatile("ldmatrix.sync.aligned.m8n8.x4.shared.b16 {%0,%1,%2,%3}, [%4];"
        : "=r"(r0), "=r"(r1), "=r"(r2), "=r"(r3) : "r"(addr));
}
__device__ __forceinline__ void ldsm4t(uint32_t& r0, uint32_t& r1, uint32_t& r2, uint32_t& r3,
                                       uint32_t addr) {
    asm volatile("ldmatrix.sync.aligned.m8n8.x4.trans.shared.b16 {%0,%1,%2,%3}, [%4];"
        : "=r"(r0), "=r"(r1), "=r"(r2), "=r"(r3) : "r"(addr));
}
#define CP_ASYNC16(dst, src) \
    asm volatile("cp.async.cg.shared.global [%0], [%1], 16;" :: "r"(dst), "l"(src) : "memory")
#define CP_COMMIT() asm volatile("cp.async.commit_group;" ::: "memory")
#define CP_WAIT2() asm volatile("cp.async.wait_group 2;" ::: "memory")
#define CP_WAIT1() asm volatile("cp.async.wait_group 1;" ::: "memory")
#define CP_WAIT0() asm volatile("cp.async.wait_group 0;" ::: "memory")

// mma.sync m16n8k16 bf16 -> f32 accumulate
__device__ __forceinline__ void mma16816(float* d, const uint32_t* a, uint32_t b0, uint32_t b1) {
    asm volatile("mma.sync.aligned.m16n8k16.row.col.f32.bf16.bf16.f32 "
        "{%0,%1,%2,%3}, {%4,%5,%6,%7}, {%8,%9}, {%0,%1,%2,%3};"
        : "+f"(d[0]), "+f"(d[1]), "+f"(d[2]), "+f"(d[3])
        : "r"(a[0]), "r"(a[1]), "r"(a[2]), "r"(a[3]), "r"(b0), "r"(b1));
}

// pack two floats into (hi-pair, lo-pair) bf16x2
__device__ __forceinline__ void split2(float x, float y, uint32_t& hi, uint32_t& lo) {
    __nv_bfloat16 xh = __float2bfloat16_rn(x), yh = __float2bfloat16_rn(y);
    float xr = x - __bfloat162float(xh), yr = y - __bfloat162float(yh);
    __nv_bfloat16 xl = __float2bfloat16_rn(xr), yl = __float2bfloat16_rn(yr);
    hi = ((uint32_t)__bfloat16_as_ushort(yh) << 16) | __bfloat16_as_ushort(xh);
    lo = ((uint32_t)__bfloat16_as_ushort(yl) << 16) | __bfloat16_as_ushort(xl);
}

// ---------------- f32 -> (bf16 hi, bf16 lo) split ----------------
__global__ void conv_split_kernel(const float* __restrict__ in,
                                  __nv_bfloat16* __restrict__ hi,
                                  __nv_bfloat16* __restrict__ lo, int n4) {
    int i = blockIdx.x * blockDim.x + threadIdx.x;
    if (i >= n4) return;
    float4 v = reinterpret_cast<const float4*>(in)[i];
    uint32_t h0, l0, h1, l1;
    split2(v.x, v.y, h0, l0);
    split2(v.z, v.w, h1, l1);
    reinterpret_cast<uint2*>(hi)[i] = make_uint2(h0, h1);
    reinterpret_cast<uint2*>(lo)[i] = make_uint2(l0, l1);
}

// ---------------- mma.sync GEMM: C[4096,1024] = A @ W^T + bias ----------------
// CTA tile 128x64, K-tile 32, 8 warps (4x2), warp tile 32x32, 3-stage cp.async,
// ldmatrix fragment loads, bf16 3-pass split.
#define GSTR 80          // smem row stride bytes (32 bf16 + 16 pad)
#define G_A_L 10240      // Al offset within stage (128*80)
#define G_W_H 20480      // Wh offset
#define G_W_L 25600      // Wl offset (+64*80)
#define GSTG 30720       // stage size
#define GEMM_SMEM (3*GSTG)   // 92160

__global__ void __launch_bounds__(256, 2) gemm_mma(
    const __nv_bfloat16* __restrict__ Ah, const __nv_bfloat16* __restrict__ Al,
    const __nv_bfloat16* __restrict__ Wh, const __nv_bfloat16* __restrict__ Wl,
    const float* __restrict__ bias,
    float* __restrict__ Cf,                 // f32 output (or null)
    __nv_bfloat16* __restrict__ Chi,        // bf16 split output (or null)
    __nv_bfloat16* __restrict__ Clo,
    float cscale)
{
    extern __shared__ __align__(1024) char sm[];
    const uint32_t sb = smem_to_u32(sm);
    const int tid = threadIdx.x;
    const int warp = tid >> 5, lane = tid & 31;
    const int g = lane >> 2, tg = lane & 3;
    const int wm = warp >> 1, wn = warp & 1;      // 4 x 2 warp grid, 32x32 warp tiles
    const int bm = blockIdx.y * 128, bn = blockIdx.x * 64;
    const int lt = lane >> 3, lr = lane & 7;      // ldmatrix tile id / row

    auto load_stage = [&](int kt) {
        const uint32_t base = sb + (kt % 3) * GSTG;
        const int kofs = kt * 32;
        #pragma unroll
        for (int t = tid; t < 512; t += 256) {    // A: 128 rows x 4 chunks
            int r = t >> 2, c = t & 3;
            uint32_t dst = base + r * GSTR + c * 16;
            size_t src = (size_t)(bm + r) * DD + kofs + c * 8;
            CP_ASYNC16(dst,         Ah + src);
            CP_ASYNC16(dst + G_A_L, Al + src);
        }
        {                                          // W: 64 rows x 4 chunks
            int t = tid;
            if (t < 256) {
                int r = t >> 2, c = t & 3;
                uint32_t dst = sb + (kt % 3) * GSTG + G_W_H + r * GSTR + c * 16;
                size_t src = (size_t)(bn + r) * DD + kofs + c * 8;
                CP_ASYNC16(dst,                 Wh + src);
                CP_ASYNC16(dst + (G_W_L-G_W_H), Wl + src);
            }
        }
    };

    float acc[2][4][4];
    #pragma unroll
    for (int mi = 0; mi < 2; mi++)
        #pragma unroll
        for (int ni = 0; ni < 4; ni++)
            #pragma unroll
            for (int q = 0; q < 4; q++) acc[mi][ni][q] = 0.f;

    load_stage(0); CP_COMMIT();
    load_stage(1); CP_COMMIT();
    load_stage(2); CP_COMMIT();

    const int NT = 32;
    for (int kt = 0; kt < NT; kt++) {
        if (kt < NT - 2) { CP_WAIT2(); }
        else if (kt == NT - 2) { CP_WAIT1(); }
        else { CP_WAIT0(); }
        __syncthreads();
        const uint32_t base = sb + (kt % 3) * GSTG;

        #pragma unroll
        for (int kc = 0; kc < 2; kc++) {
            // A frags: region rows wm*32+mi*16 (16) x k 16
            uint32_t ah[2][4], al[2][4];
            #pragma unroll
            for (int mi = 0; mi < 2; mi++) {
                uint32_t ar = base + (wm*32 + mi*16 + (lt&1)*8 + lr) * GSTR
                            + kc*32 + (lt>>1)*16;
                ldsm4(ah[mi][0], ah[mi][1], ah[mi][2], ah[mi][3], ar);
                ldsm4(al[mi][0], al[mi][1], al[mi][2], al[mi][3], ar + G_A_L);
            }
            // B frags: region n wn*32+ngp*16 (16) x k 16 -> 2 n-groups per ldsm
            #pragma unroll
            for (int ngp = 0; ngp < 2; ngp++) {
                uint32_t br = base + G_W_H + (wn*32 + ngp*16 + (lt>>1)*8 + lr) * GSTR
                            + kc*32 + (lt&1)*16;
                uint32_t bh0, bh1, bh2, bh3, bl0, bl1, bl2, bl3;
                ldsm4(bh0, bh1, bh2, bh3, br);
                ldsm4(bl0, bl1, bl2, bl3, br + (G_W_L - G_W_H));
                int n0 = ngp*2, n1 = ngp*2 + 1;
                #pragma unroll
                for (int mi = 0; mi < 2; mi++) {
                    mma16816(acc[mi][n0], ah[mi], bh0, bh1);
                    mma16816(acc[mi][n1], ah[mi], bh2, bh3);
                    mma16816(acc[mi][n0], ah[mi], bl0, bl1);
                    mma16816(acc[mi][n1], ah[mi], bl2, bl3);
                    mma16816(acc[mi][n0], al[mi], bh0, bh1);
                    mma16816(acc[mi][n1], al[mi], bh2, bh3);
                }
            }
        }
        __syncthreads();
        if (kt + 3 < NT) { load_stage(kt + 3); CP_COMMIT(); }
    }

    // epilogue
    #pragma unroll
    for (int mi = 0; mi < 2; mi++) {
        int row = bm + wm*32 + mi*16 + g;
        #pragma unroll
        for (int ni = 0; ni < 4; ni++) {
            int col = bn + wn*32 + ni*8 + tg*2;
            float b0 = bias[col], b1 = bias[col + 1];
            float v0 = acc[mi][ni][0] + b0, v1 = acc[mi][ni][1] + b1;
            float v2 = acc[mi][ni][2] + b0, v3 = acc[mi][ni][3] + b1;
            if (Cf) {
                *reinterpret_cast<float2*>(&Cf[(size_t)row * DD + col])     = make_float2(v0, v1);
                *reinterpret_cast<float2*>(&Cf[(size_t)(row+8) * DD + col]) = make_float2(v2, v3);
            } else {
                uint32_t h01, l01, h23, l23;
                split2(v0 * cscale, v1 * cscale, h01, l01);
                split2(v2 * cscale, v3 * cscale, h23, l23);
                *reinterpret_cast<uint32_t*>(&Chi[(size_t)row * DD + col])     = h01;
                *reinterpret_cast<uint32_t*>(&Clo[(size_t)row * DD + col])     = l01;
                *reinterpret_cast<uint32_t*>(&Chi[(size_t)(row+8) * DD + col]) = h23;
                *reinterpret_cast<uint32_t*>(&Clo[(size_t)(row+8) * DD + col]) = l23;
            }
        }
    }
}

// ---------------- W_h row-sum ----------------
__global__ void rowsum_kernel(const float* __restrict__ Wh) {
    int i = blockIdx.x * blockDim.x + threadIdx.x;
    if (i < HH*DK) {
        const float* p = Wh + (size_t)i * DK;
        float s = 0.f;
        #pragma unroll
        for (int k = 0; k < DK; k++) s += p[k];
        g_wrow[i] = s;
    }
}

// ---------------- recurrence: h_t = tanh(h_{t-1}*w + r_t) -> bf16 hi/lo ----------------
__global__ void recurrence_kernel() {
    int bh = blockIdx.x;
    int b = bh / HH, h = bh % HH;
    int d = threadIdx.x;
    float w = g_wrow[h * DK + d];
    float st = 0.f;
    const float* Rp = g_Rp + ((size_t)b * SK) * DD + h * DK + d;
    size_t ho = ((size_t)b * SK) * DD + h * DK + d;
    #pragma unroll 1
    for (int t = 0; t < SK; t += 8) {
        float r[8];
        #pragma unroll
        for (int i = 0; i < 8; i++) r[i] = Rp[(size_t)(t + i) * DD];
        #pragma unroll
        for (int i = 0; i < 8; i++) {
            st = tanhf(st * w + r[i]);
            __nv_bfloat16 hh = __float2bfloat16_rn(st);
            __nv_bfloat16 hl = __float2bfloat16_rn(st - __bfloat162float(hh));
            g_Hh[ho + (size_t)(t + i) * DD] = hh;
            g_Hl[ho + (size_t)(t + i) * DD] = hl;
        }
    }
}

// ---------------- flash attention, double-buffered + ldmatrix ----------------
// CTA: one (b,h), 64 q-rows, 128 threads (4 warps x 16 q-rows).
// smem stage: Hh/Hl/Vh/Vl, each 64 rows x 144 B (64 dims + pad).
#define ASTR 144
#define A_HL 9216
#define A_VH 18432
#define A_VL 27648
#define ASTG 36864
#define ATT_SMEM (2*ASTG)    // 73728

__global__ void __launch_bounds__(128, 3) attn_mma() {
    const int bh = blockIdx.y;
    const int b = bh >> 4, h = bh & 15;
    const int q0 = blockIdx.x * 64;
    const int tid = threadIdx.x;
    const int warp = tid >> 5, lane = tid & 31;
    const int g = lane >> 2, tg = lane & 3;
    const int lt = lane >> 3, lr = lane & 7;   // ldmatrix tile / row

    extern __shared__ __align__(1024) char sm[];
    const uint32_t sb = smem_to_u32(sm);

    const size_t qbase = (size_t)(b * SQ + q0);
    const size_t kbase = (size_t)(b * SK);
    const int hofs = h * DK;

    // Q fragments: preload from gmem into registers (live whole kernel)
    uint32_t qh[4][4], ql[4][4];
    {
        size_t r0 = (qbase + warp*16 + g) * DD + hofs;
        size_t r1 = r0 + 8 * DD;
        #pragma unroll
        for (int kc = 0; kc < 4; kc++) {
            int c0 = kc*16 + tg*2;
            qh[kc][0] = *reinterpret_cast<const uint32_t*>(g_Qh + r0 + c0);
            qh[kc][1] = *reinterpret_cast<const uint32_t*>(g_Qh + r1 + c0);
            qh[kc][2] = *reinterpret_cast<const uint32_t*>(g_Qh + r0 + c0 + 8);
            qh[kc][3] = *reinterpret_cast<const uint32_t*>(g_Qh + r1 + c0 + 8);
            ql[kc][0] = *reinterpret_cast<const uint32_t*>(g_Ql + r0 + c0);
            ql[kc][1] = *reinterpret_cast<const uint32_t*>(g_Ql + r1 + c0);
            ql[kc][2] = *reinterpret_cast<const uint32_t*>(g_Ql + r0 + c0 + 8);
            ql[kc][3] = *reinterpret_cast<const uint32_t*>(g_Ql + r1 + c0 + 8);
        }
    }

    auto load_stage = [&](int kt) {
        const uint32_t base = sb + (kt & 1) * ASTG;
        const int k0 = kt * 64;
        #pragma unroll
        for (int t = tid; t < 512; t += 128) {     // 64 rows x 8 chunks of 16B
            int r = t >> 3, c = t & 7;
            uint32_t dst = base + r * ASTR + c * 16;
            size_t src = (kbase + k0 + r) * DD + hofs + c * 8;
            CP_ASYNC16(dst,        g_Hh + src);
            CP_ASYNC16(dst + A_HL, g_Hl + src);
            CP_ASYNC16(dst + A_VH, g_Vh + src);
            CP_ASYNC16(dst + A_VL, g_Vl + src);
        }
    };

    load_stage(0); CP_COMMIT();
    load_stage(1); CP_COMMIT();

    float acc[8][4];
    #pragma unroll
    for (int n = 0; n < 8; n++)
        #pragma unroll
        for (int q = 0; q < 4; q++) acc[n][q] = 0.f;
    float mrow0 = -1e30f, mrow1 = -1e30f, lrow0 = 0.f, lrow1 = 0.f;

    const int NT = SK / 64;   // 32
    for (int kt = 0; kt < NT; kt++) {
        if (kt < NT - 1) { CP_WAIT1(); } else { CP_WAIT0(); }
        __syncthreads();
        const uint32_t base = sb + (kt & 1) * ASTG;

        // ---- S = Q . H^T (3-pass split; scale*log2e folded into Q) ----
        float s[8][4];
        #pragma unroll
        for (int n = 0; n < 8; n++)
            #pragma unroll
            for (int q = 0; q < 4; q++) s[n][q] = 0.f;

        #pragma unroll
        for (int kc = 0; kc < 4; kc++) {
            #pragma unroll
            for (int ngp = 0; ngp < 4; ngp++) {
                uint32_t br = base + (ngp*16 + (lt>>1)*8 + lr) * ASTR
                            + kc*32 + (lt&1)*16;
                uint32_t bh0, bh1, bh2, bh3, bl0, bl1, bl2, bl3;
                ldsm4(bh0, bh1, bh2, bh3, br);
                ldsm4(bl0, bl1, bl2, bl3, br + A_HL);
                int n0 = ngp*2, n1 = ngp*2 + 1;
                mma16816(s[n0], qh[kc], bh0, bh1);
                mma16816(s[n1], qh[kc], bh2, bh3);
                mma16816(s[n0], qh[kc], bl0, bl1);
                mma16816(s[n1], qh[kc], bl2, bl3);
                mma16816(s[n0], ql[kc], bh0, bh1);
                mma16816(s[n1], ql[kc], bh2, bh3);
            }
        }

        // ---- online softmax (base-2) ----
        float tm0 = mrow0, tm1 = mrow1;
        #pragma unroll
        for (int n = 0; n < 8; n++) {
            tm0 = fmaxf(tm0, fmaxf(s[n][0], s[n][1]));
            tm1 = fmaxf(tm1, fmaxf(s[n][2], s[n][3]));
        }
        tm0 = fmaxf(tm0, __shfl_xor_sync(0xffffffffu, tm0, 1));
        tm0 = fmaxf(tm0, __shfl_xor_sync(0xffffffffu, tm0, 2));
        tm1 = fmaxf(tm1, __shfl_xor_sync(0xffffffffu, tm1, 1));
        tm1 = fmaxf(tm1, __shfl_xor_sync(0xffffffffu, tm1, 2));
        float corr0 = ex2f(mrow0 - tm0), corr1 = ex2f(mrow1 - tm1);
        mrow0 = tm0; mrow1 = tm1;
        lrow0 *= corr0; lrow1 *= corr1;

        uint32_t pah[4][4], pal[4][4];
        #pragma unroll
        for (int n = 0; n < 8; n++) {
            float p0 = ex2f(s[n][0] - tm0), p1 = ex2f(s[n][1] - tm0);
            float p2 = ex2f(s[n][2] - tm1), p3 = ex2f(s[n][3] - tm1);
            lrow0 += p0 + p1; lrow1 += p2 + p3;
            int kc = n >> 1, hf = (n & 1) * 2;
            split2(p0, p1, pah[kc][hf],     pal[kc][hf]);
            split2(p2, p3, pah[kc][hf + 1], pal[kc][hf + 1]);
        }
        #pragma unroll
        for (int n = 0; n < 8; n++) {
            acc[n][0] *= corr0; acc[n][1] *= corr0;
            acc[n][2] *= corr1; acc[n][3] *= corr1;
        }

        // ---- acc += P . V (V via ldmatrix.trans) ----
        #pragma unroll
        for (int kc = 0; kc < 4; kc++) {
            #pragma unroll
            for (int ndgp = 0; ndgp < 4; ndgp++) {
                uint32_t vr = base + A_VH + (kc*16 + (lt&1)*8 + lr) * ASTR
                            + (ndgp*16 + (lt>>1)*8) * 2;
                uint32_t bh0, bh1, bh2, bh3, bl0, bl1, bl2, bl3;
                ldsm4t(bh0, bh1, bh2, bh3, vr);
                ldsm4t(bl0, bl1, bl2, bl3, vr + (A_VL - A_VH));
                int n0 = ndgp*2, n1 = ndgp*2 + 1;
                mma16816(acc[n0], pah[kc], bh0, bh1);
                mma16816(acc[n1], pah[kc], bh2, bh3);
                mma16816(acc[n0], pah[kc], bl0, bl1);
                mma16816(acc[n1], pah[kc], bl2, bl3);
                mma16816(acc[n0], pal[kc], bh0, bh1);
                mma16816(acc[n1], pal[kc], bh2, bh3);
            }
        }

        __syncthreads();
        if (kt + 2 < NT) { load_stage(kt + 2); CP_COMMIT(); }
    }

    // epilogue: normalize, split to bf16 hi/lo for the Wo GEMM
    lrow0 += __shfl_xor_sync(0xffffffffu, lrow0, 1);
    lrow0 += __shfl_xor_sync(0xffffffffu, lrow0, 2);
    lrow1 += __shfl_xor_sync(0xffffffffu, lrow1, 1);
    lrow1 += __shfl_xor_sync(0xffffffffu, lrow1, 2);
    float inv0 = 1.f / lrow0, inv1 = 1.f / lrow1;
    size_t row = qbase + warp*16 + g;
    #pragma unroll
    for (int nd = 0; nd < 8; nd++) {
        int col = hofs + nd*8 + tg*2;
        uint32_t h01, l01, h23, l23;
        split2(acc[nd][0] * inv0, acc[nd][1] * inv0, h01, l01);
        split2(acc[nd][2] * inv1, acc[nd][3] * inv1, h23, l23);
        *reinterpret_cast<uint32_t*>(&g_Ah[row * DD + col])       = h01;
        *reinterpret_cast<uint32_t*>(&g_Al[row * DD + col])       = l01;
        *reinterpret_cast<uint32_t*>(&g_Ah[(row + 8) * DD + col]) = h23;
        *reinterpret_cast<uint32_t*>(&g_Al[(row + 8) * DD + col]) = l23;
    }
}

// ---------------- launch ----------------
extern "C" void kernel_launch(void* const* d_in, const int* in_sizes, int n_in,
                              void* d_out, int out_size) {
    const float* query = (const float*)d_in[0];
    // d_in[1] = key : unused by the reference computation
    const float* value = (const float*)d_in[2];
    const float* Rin   = (const float*)d_in[3];
    const float* Wq    = (const float*)d_in[4];
    const float* bq    = (const float*)d_in[5];
    const float* Wv    = (const float*)d_in[6];
    const float* bv    = (const float*)d_in[7];
    const float* Wr    = (const float*)d_in[8];
    const float* br    = (const float*)d_in[9];
    const float* Wh    = (const float*)d_in[10];
    const float* Wo    = (const float*)d_in[11];
    const float* bo    = (const float*)d_in[12];
    float* out = (float*)d_out;

    float *Rp;
    __nv_bfloat16 *Ah, *Al, *Wbh, *Wbl, *Qh, *Ql, *Vh, *Vl;
    cudaGetSymbolAddress((void**)&Rp, g_Rp);
    cudaGetSymbolAddress((void**)&Ah, g_Ah);
    cudaGetSymbolAddress((void**)&Al, g_Al);
    cudaGetSymbolAddress((void**)&Wbh, g_Wh);
    cudaGetSymbolAddress((void**)&Wbl, g_Wl);
    cudaGetSymbolAddress((void**)&Qh, g_Qh);
    cudaGetSymbolAddress((void**)&Ql, g_Ql);
    cudaGetSymbolAddress((void**)&Vh, g_Vh);
    cudaGetSymbolAddress((void**)&Vl, g_Vl);

    cudaFuncSetAttribute(gemm_mma,
                         cudaFuncAttributeMaxDynamicSharedMemorySize, GEMM_SMEM);
    cudaFuncSetAttribute(attn_mma,
                         cudaFuncAttributeMaxDynamicSharedMemorySize, ATT_SMEM);

    const int nA4 = MROWS * DD / 4;
    const int nW4 = DD * DD / 4;
    dim3 ggemm(DD / 64, MROWS / 128);       // (16, 32) = 512 CTAs

    rowsum_kernel<<<(HH * DK + 127) / 128, 128>>>(Wh);

    // Q projection -> scaled bf16 split
    conv_split_kernel<<<nA4 / 256, 256>>>(query, Ah, Al, nA4);
    conv_split_kernel<<<nW4 / 256, 256>>>(Wq, Wbh, Wbl, nW4);
    gemm_mma<<<ggemm, 256, GEMM_SMEM>>>(Ah, Al, Wbh, Wbl, bq, nullptr, Qh, Ql, QK_SCALE);

    // V projection -> bf16 split
    conv_split_kernel<<<nA4 / 256, 256>>>(value, Ah, Al, nA4);
    conv_split_kernel<<<nW4 / 256, 256>>>(Wv, Wbh, Wbl, nW4);
    gemm_mma<<<ggemm, 256, GEMM_SMEM>>>(Ah, Al, Wbh, Wbl, bv, nullptr, Vh, Vl, 1.0f);

    // R projection -> f32
    conv_split_kernel<<<nA4 / 256, 256>>>(Rin, Ah, Al, nA4);
    conv_split_kernel<<<nW4 / 256, 256>>>(Wr, Wbh, Wbl, nW4);
    gemm_mma<<<ggemm, 256, GEMM_SMEM>>>(Ah, Al, Wbh, Wbl, br, Rp, nullptr, nullptr, 1.0f);

    recurrence_kernel<<<BB * HH, DK>>>();

    // attention writes bf16 split directly into Ah/Al
    attn_mma<<<dim3(SQ / 64, BB * HH), 128, ATT_SMEM>>>();

    // output projection -> f32 out
    conv_split_kernel<<<nW4 / 256, 256>>>(Wo, Wbh, Wbl, nW4);
    gemm_mma<<<ggemm, 256, GEMM_SMEM>>>(Ah, Al, Wbh, Wbl, bo, out, nullptr, nullptr, 1.0f);
}

// round 13
// speedup vs baseline: 2.9818x; 1.0742x over previous
#include <cuda_runtime.h>
#include <cuda_bf16.h>
#include <math.h>
#include <stdint.h>

#define BB 2
#define SQ 2048
#define SK 2048
#define DD 1024
#define HH 16
#define DK 64
#define MROWS (BB*SQ)   // 4096

#define QK_SCALE (0.125f * 1.4426950408889634f)

// ---------------- scratch (device globals; no allocation allowed) ----------------
__device__ float g_Rp[BB*SK*DD];
__device__ float g_wrow[HH*DK];
// A-operand splits for the 3 projection GEMMs (and attn-out reuses slot 0)
__device__ __nv_bfloat16 g_Aqh[MROWS*DD], g_Aql[MROWS*DD];   // query split / attn out
__device__ __nv_bfloat16 g_Avh[MROWS*DD], g_Avl[MROWS*DD];   // value split
__device__ __nv_bfloat16 g_Arh[MROWS*DD], g_Arl[MROWS*DD];   // R split
// weight splits
__device__ __nv_bfloat16 g_Wqh[DD*DD], g_Wql[DD*DD];
__device__ __nv_bfloat16 g_Wvh[DD*DD], g_Wvl[DD*DD];
__device__ __nv_bfloat16 g_Wrh[DD*DD], g_Wrl[DD*DD];
__device__ __nv_bfloat16 g_Woh[DD*DD], g_Wol[DD*DD];
// projection outputs
__device__ __nv_bfloat16 g_Qh[MROWS*DD], g_Ql[MROWS*DD];
__device__ __nv_bfloat16 g_Vh[MROWS*DD], g_Vl[MROWS*DD];
__device__ __nv_bfloat16 g_Hh[MROWS*DD], g_Hl[MROWS*DD];

// ---------------- helpers ----------------
__device__ __forceinline__ uint32_t smem_to_u32(const void* p) {
    uint32_t a;
    asm("{ .reg .u64 t; cvta.to.shared.u64 t, %1; cvt.u32.u64 %0, t; }" : "=r"(a) : "l"(p));
    return a;
}
__device__ __forceinline__ float ex2f(float x) {
    float r; asm("ex2.approx.f32 %0, %1;" : "=f"(r) : "f"(x)); return r;
}
__device__ __forceinline__ void ldsm4(uint32_t& r0, uint32_t& r1, uint32_t& r2, uint32_t& r3,
                                      uint32_t addr) {
    asm volatile("ldmatrix.sync.aligned.m8n8.x4.shared.b16 {%0,%1,%2,%3}, [%4];"
        : "=r"(r0), "=r"(r1), "=r"(r2), "=r"(r3) : "r"(addr));
}
__device__ __forceinline__ void ldsm4t(uint32_t& r0, uint32_t& r1, uint32_t& r2, uint32_t& r3,
                                       uint32_t addr) {
    asm volatile("ldmatrix.sync.aligned.m8n8.x4.trans.shared.b16 {%0,%1,%2,%3}, [%4];"
        : "=r"(r0), "=r"(r1), "=r"(r2), "=r"(r3) : "r"(addr));
}
#define CP_ASYNC16(dst, src) \
    asm volatile("cp.async.cg.shared.global [%0], [%1], 16;" :: "r"(dst), "l"(src) : "memory")
#define CP_COMMIT() asm volatile("cp.async.commit_group;" ::: "memory")
#define CP_WAIT1() asm volatile("cp.async.wait_group 1;" ::: "memory")
#define CP_WAIT0() asm volatile("cp.async.wait_group 0;" ::: "memory")

__device__ __forceinline__ void mma16816(float* d, const uint32_t* a, uint32_t b0, uint32_t b1) {
    asm volatile("mma.sync.aligned.m16n8k16.row.col.f32.bf16.bf16.f32 "
        "{%0,%1,%2,%3}, {%4,%5,%6,%7}, {%8,%9}, {%0,%1,%2,%3};"
        : "+f"(d[0]), "+f"(d[1]), "+f"(d[2]), "+f"(d[3])
        : "r"(a[0]), "r"(a[1]), "r"(a[2]), "r"(a[3]), "r"(b0), "r"(b1));
}

__device__ __forceinline__ void split2(float x, float y, uint32_t& hi, uint32_t& lo) {
    __nv_bfloat16 xh = __float2bfloat16_rn(x), yh = __float2bfloat16_rn(y);
    float xr = x - __bfloat162float(xh), yr = y - __bfloat162float(yh);
    __nv_bfloat16 xl = __float2bfloat16_rn(xr), yl = __float2bfloat16_rn(yr);
    hi = ((uint32_t)__bfloat16_as_ushort(yh) << 16) | __bfloat16_as_ushort(xh);
    lo = ((uint32_t)__bfloat16_as_ushort(yl) << 16) | __bfloat16_as_ushort(xl);
}

// ---------------- batched f32 -> bf16 hi/lo split (up to 4 tensors via blockIdx.y) ----------------
__global__ void conv_split4(const float* i0, const float* i1, const float* i2, const float* i3,
                            __nv_bfloat16* h0, __nv_bfloat16* l0,
                            __nv_bfloat16* h1, __nv_bfloat16* l1,
                            __nv_bfloat16* h2, __nv_bfloat16* l2,
                            __nv_bfloat16* h3, __nv_bfloat16* l3, int n4) {
    int i = blockIdx.x * blockDim.x + threadIdx.x;
    if (i >= n4) return;
    const float* in; __nv_bfloat16 *hi, *lo;
    switch (blockIdx.y) {
        case 0: in = i0; hi = h0; lo = l0; break;
        case 1: in = i1; hi = h1; lo = l1; break;
        case 2: in = i2; hi = h2; lo = l2; break;
        default: in = i3; hi = h3; lo = l3; break;
    }
    float4 v = reinterpret_cast<const float4*>(in)[i];
    uint32_t a0, b0, a1, b1;
    split2(v.x, v.y, a0, b0);
    split2(v.z, v.w, a1, b1);
    reinterpret_cast<uint2*>(hi)[i] = make_uint2(a0, a1);
    reinterpret_cast<uint2*>(lo)[i] = make_uint2(b0, b1);
}

// ---------------- mma.sync GEMM, batched over grid.z ----------------
// CTA tile 128x128, K-tile 32, 2-stage cp.async, 8 warps (4x2), warp tile 32x64.
struct GemmJob {
    const __nv_bfloat16 *Ah, *Al, *Wh, *Wl;
    const float* bias;
    float* Cf;                 // f32 out (or null)
    __nv_bfloat16 *Chi, *Clo;  // bf16 split out (used when Cf==null)
    float scale;
};

#define GSTR 80
#define G_A_L 10240
#define G_W_H 20480
#define G_W_L 30720
#define GSTG 40960
#define GEMM_SMEM (2*GSTG)   // 81920

__global__ void __launch_bounds__(256, 2) gemm_mma(GemmJob j0, GemmJob j1, GemmJob j2)
{
    const GemmJob j = (blockIdx.z == 0) ? j0 : (blockIdx.z == 1) ? j1 : j2;
    extern __shared__ __align__(1024) char sm[];
    const uint32_t sb = smem_to_u32(sm);
    const int tid = threadIdx.x;
    const int warp = tid >> 5, lane = tid & 31;
    const int g = lane >> 2, tg = lane & 3;
    const int wm = warp >> 1, wn = warp & 1;      // 4x2 grid, warp tile 32x64
    const int bm = blockIdx.y * 128, bn = blockIdx.x * 128;
    const int lt = lane >> 3, lr = lane & 7;

    auto load_stage = [&](int kt) {
        const uint32_t base = sb + (kt & 1) * GSTG;
        const int kofs = kt * 32;
        #pragma unroll
        for (int t = tid; t < 512; t += 256) {
            int r = t >> 2, c = t & 3;
            uint32_t da = base + r * GSTR + c * 16;
            size_t ga = (size_t)(bm + r) * DD + kofs + c * 8;
            size_t gw = (size_t)(bn + r) * DD + kofs + c * 8;
            CP_ASYNC16(da,         j.Ah + ga);
            CP_ASYNC16(da + G_A_L, j.Al + ga);
            uint32_t dw = base + G_W_H + r * GSTR + c * 16;
            CP_ASYNC16(dw,                 j.Wh + gw);
            CP_ASYNC16(dw + (G_W_L-G_W_H), j.Wl + gw);
        }
    };

    float acc[2][8][4];
    #pragma unroll
    for (int mi = 0; mi < 2; mi++)
        #pragma unroll
        for (int ni = 0; ni < 8; ni++)
            #pragma unroll
            for (int q = 0; q < 4; q++) acc[mi][ni][q] = 0.f;

    load_stage(0); CP_COMMIT();
    load_stage(1); CP_COMMIT();

    const int NT = 32;
    for (int kt = 0; kt < NT; kt++) {
        if (kt == NT - 1) { CP_WAIT0(); } else { CP_WAIT1(); }
        __syncthreads();
        const uint32_t base = sb + (kt & 1) * GSTG;

        #pragma unroll
        for (int kc = 0; kc < 2; kc++) {
            uint32_t ah[2][4], al[2][4], bh[4][4], bl[4][4];
            #pragma unroll
            for (int mi = 0; mi < 2; mi++) {
                uint32_t ar = base + (wm*32 + mi*16 + (lt&1)*8 + lr) * GSTR
                            + kc*32 + (lt>>1)*16;
                ldsm4(ah[mi][0], ah[mi][1], ah[mi][2], ah[mi][3], ar);
                ldsm4(al[mi][0], al[mi][1], al[mi][2], al[mi][3], ar + G_A_L);
            }
            #pragma unroll
            for (int ngp = 0; ngp < 4; ngp++) {
                uint32_t br = base + G_W_H + (wn*64 + ngp*16 + (lt>>1)*8 + lr) * GSTR
                            + kc*32 + (lt&1)*16;
                ldsm4(bh[ngp][0], bh[ngp][1], bh[ngp][2], bh[ngp][3], br);
                ldsm4(bl[ngp][0], bl[ngp][1], bl[ngp][2], bl[ngp][3], br + (G_W_L-G_W_H));
            }
            // pass 1: Ah x Wh   (same-acc reuse distance = 16)
            #pragma unroll
            for (int mi = 0; mi < 2; mi++)
                #pragma unroll
                for (int ngp = 0; ngp < 4; ngp++) {
                    mma16816(acc[mi][2*ngp],   ah[mi], bh[ngp][0], bh[ngp][1]);
                    mma16816(acc[mi][2*ngp+1], ah[mi], bh[ngp][2], bh[ngp][3]);
                }
            // pass 2: Ah x Wl
            #pragma unroll
            for (int mi = 0; mi < 2; mi++)
                #pragma unroll
                for (int ngp = 0; ngp < 4; ngp++) {
                    mma16816(acc[mi][2*ngp],   ah[mi], bl[ngp][0], bl[ngp][1]);
                    mma16816(acc[mi][2*ngp+1], ah[mi], bl[ngp][2], bl[ngp][3]);
                }
            // pass 3: Al x Wh
            #pragma unroll
            for (int mi = 0; mi < 2; mi++)
                #pragma unroll
                for (int ngp = 0; ngp < 4; ngp++) {
                    mma16816(acc[mi][2*ngp],   al[mi], bh[ngp][0], bh[ngp][1]);
                    mma16816(acc[mi][2*ngp+1], al[mi], bh[ngp][2], bh[ngp][3]);
                }
        }
        __syncthreads();
        if (kt + 2 < NT) { load_stage(kt + 2); CP_COMMIT(); }
    }

    #pragma unroll
    for (int mi = 0; mi < 2; mi++) {
        int row = bm + wm*32 + mi*16 + g;
        #pragma unroll
        for (int ni = 0; ni < 8; ni++) {
            int col = bn + wn*64 + ni*8 + tg*2;
            float b0 = j.bias[col], b1 = j.bias[col + 1];
            float v0 = acc[mi][ni][0] + b0, v1 = acc[mi][ni][1] + b1;
            float v2 = acc[mi][ni][2] + b0, v3 = acc[mi][ni][3] + b1;
            if (j.Cf) {
                *reinterpret_cast<float2*>(&j.Cf[(size_t)row * DD + col])     = make_float2(v0, v1);
                *reinterpret_cast<float2*>(&j.Cf[(size_t)(row+8) * DD + col]) = make_float2(v2, v3);
            } else {
                uint32_t h01, l01, h23, l23;
                split2(v0 * j.scale, v1 * j.scale, h01, l01);
                split2(v2 * j.scale, v3 * j.scale, h23, l23);
                *reinterpret_cast<uint32_t*>(&j.Chi[(size_t)row * DD + col])     = h01;
                *reinterpret_cast<uint32_t*>(&j.Clo[(size_t)row * DD + col])     = l01;
                *reinterpret_cast<uint32_t*>(&j.Chi[(size_t)(row+8) * DD + col]) = h23;
                *reinterpret_cast<uint32_t*>(&j.Clo[(size_t)(row+8) * DD + col]) = l23;
            }
        }
    }
}

// ---------------- W_h row-sum ----------------
__global__ void rowsum_kernel(const float* __restrict__ Wh) {
    int i = blockIdx.x * blockDim.x + threadIdx.x;
    if (i < HH*DK) {
        const float* p = Wh + (size_t)i * DK;
        float s = 0.f;
        #pragma unroll
        for (int k = 0; k < DK; k++) s += p[k];
        g_wrow[i] = s;
    }
}

// ---------------- recurrence ----------------
__global__ void recurrence_kernel() {
    int bh = blockIdx.x;
    int b = bh / HH, h = bh % HH;
    int d = threadIdx.x;
    float w = g_wrow[h * DK + d];
    float st = 0.f;
    const float* Rp = g_Rp + ((size_t)b * SK) * DD + h * DK + d;
    size_t ho = ((size_t)b * SK) * DD + h * DK + d;
    #pragma unroll 1
    for (int t = 0; t < SK; t += 8) {
        float r[8];
        #pragma unroll
        for (int i = 0; i < 8; i++) r[i] = Rp[(size_t)(t + i) * DD];
        #pragma unroll
        for (int i = 0; i < 8; i++) {
            st = tanhf(st * w + r[i]);
            __nv_bfloat16 hh = __float2bfloat16_rn(st);
            __nv_bfloat16 hl = __float2bfloat16_rn(st - __bfloat162float(hh));
            g_Hh[ho + (size_t)(t + i) * DD] = hh;
            g_Hl[ho + (size_t)(t + i) * DD] = hl;
        }
    }
}

// ---------------- flash attention, double-buffered + ldmatrix, pass-major mma ----------------
#define ASTR 144
#define A_HL 9216
#define A_VH 18432
#define A_VL 27648
#define ASTG 36864
#define ATT_SMEM (2*ASTG)    // 73728

__global__ void __launch_bounds__(128, 3) attn_mma() {
    const int bh = blockIdx.y;
    const int b = bh >> 4, h = bh & 15;
    const int q0 = blockIdx.x * 64;
    const int tid = threadIdx.x;
    const int warp = tid >> 5, lane = tid & 31;
    const int g = lane >> 2, tg = lane & 3;
    const int lt = lane >> 3, lr = lane & 7;

    extern __shared__ __align__(1024) char sm[];
    const uint32_t sb = smem_to_u32(sm);

    const size_t qbase = (size_t)(b * SQ + q0);
    const size_t kbase = (size_t)(b * SK);
    const int hofs = h * DK;

    // Q fragments preloaded into registers
    uint32_t qh[4][4], ql[4][4];
    {
        size_t r0 = (qbase + warp*16 + g) * DD + hofs;
        size_t r1 = r0 + 8 * DD;
        #pragma unroll
        for (int kc = 0; kc < 4; kc++) {
            int c0 = kc*16 + tg*2;
            qh[kc][0] = *reinterpret_cast<const uint32_t*>(g_Qh + r0 + c0);
            qh[kc][1] = *reinterpret_cast<const uint32_t*>(g_Qh + r1 + c0);
            qh[kc][2] = *reinterpret_cast<const uint32_t*>(g_Qh + r0 + c0 + 8);
            qh[kc][3] = *reinterpret_cast<const uint32_t*>(g_Qh + r1 + c0 + 8);
            ql[kc][0] = *reinterpret_cast<const uint32_t*>(g_Ql + r0 + c0);
            ql[kc][1] = *reinterpret_cast<const uint32_t*>(g_Ql + r1 + c0);
            ql[kc][2] = *reinterpret_cast<const uint32_t*>(g_Ql + r0 + c0 + 8);
            ql[kc][3] = *reinterpret_cast<const uint32_t*>(g_Ql + r1 + c0 + 8);
        }
    }

    auto load_stage = [&](int kt) {
        const uint32_t base = sb + (kt & 1) * ASTG;
        const int k0 = kt * 64;
        #pragma unroll
        for (int t = tid; t < 512; t += 128) {
            int r = t >> 3, c = t & 7;
            uint32_t dst = base + r * ASTR + c * 16;
            size_t src = (kbase + k0 + r) * DD + hofs + c * 8;
            CP_ASYNC16(dst,        g_Hh + src);
            CP_ASYNC16(dst + A_HL, g_Hl + src);
            CP_ASYNC16(dst + A_VH, g_Vh + src);
            CP_ASYNC16(dst + A_VL, g_Vl + src);
        }
    };

    load_stage(0); CP_COMMIT();
    load_stage(1); CP_COMMIT();

    float acc[8][4];
    #pragma unroll
    for (int n = 0; n < 8; n++)
        #pragma unroll
        for (int q = 0; q < 4; q++) acc[n][q] = 0.f;
    float mrow0 = -1e30f, mrow1 = -1e30f, lrow0 = 0.f, lrow1 = 0.f;

    const int NT = SK / 64;   // 32
    for (int kt = 0; kt < NT; kt++) {
        if (kt < NT - 1) { CP_WAIT1(); } else { CP_WAIT0(); }
        __syncthreads();
        const uint32_t base = sb + (kt & 1) * ASTG;

        // ---- S = Q . H^T ----
        float s[8][4];
        #pragma unroll
        for (int n = 0; n < 8; n++)
            #pragma unroll
            for (int q = 0; q < 4; q++) s[n][q] = 0.f;

        #pragma unroll
        for (int kc = 0; kc < 4; kc++) {
            uint32_t hb[4][4], lb[4][4];
            #pragma unroll
            for (int ngp = 0; ngp < 4; ngp++) {
                uint32_t br = base + (ngp*16 + (lt>>1)*8 + lr) * ASTR + kc*32 + (lt&1)*16;
                ldsm4(hb[ngp][0], hb[ngp][1], hb[ngp][2], hb[ngp][3], br);
                ldsm4(lb[ngp][0], lb[ngp][1], lb[ngp][2], lb[ngp][3], br + A_HL);
            }
            #pragma unroll
            for (int ngp = 0; ngp < 4; ngp++) {
                mma16816(s[2*ngp],   qh[kc], hb[ngp][0], hb[ngp][1]);
                mma16816(s[2*ngp+1], qh[kc], hb[ngp][2], hb[ngp][3]);
            }
            #pragma unroll
            for (int ngp = 0; ngp < 4; ngp++) {
                mma16816(s[2*ngp],   qh[kc], lb[ngp][0], lb[ngp][1]);
                mma16816(s[2*ngp+1], qh[kc], lb[ngp][2], lb[ngp][3]);
            }
            #pragma unroll
            for (int ngp = 0; ngp < 4; ngp++) {
                mma16816(s[2*ngp],   ql[kc], hb[ngp][0], hb[ngp][1]);
                mma16816(s[2*ngp+1], ql[kc], hb[ngp][2], hb[ngp][3]);
            }
        }

        // ---- online softmax (base-2) ----
        float tm0 = mrow0, tm1 = mrow1;
        #pragma unroll
        for (int n = 0; n < 8; n++) {
            tm0 = fmaxf(tm0, fmaxf(s[n][0], s[n][1]));
            tm1 = fmaxf(tm1, fmaxf(s[n][2], s[n][3]));
        }
        tm0 = fmaxf(tm0, __shfl_xor_sync(0xffffffffu, tm0, 1));
        tm0 = fmaxf(tm0, __shfl_xor_sync(0xffffffffu, tm0, 2));
        tm1 = fmaxf(tm1, __shfl_xor_sync(0xffffffffu, tm1, 1));
        tm1 = fmaxf(tm1, __shfl_xor_sync(0xffffffffu, tm1, 2));
        float corr0 = ex2f(mrow0 - tm0), corr1 = ex2f(mrow1 - tm1);
        mrow0 = tm0; mrow1 = tm1;
        lrow0 *= corr0; lrow1 *= corr1;

        uint32_t pah[4][4], pal[4][4];
        #pragma unroll
        for (int n = 0; n < 8; n++) {
            float p0 = ex2f(s[n][0] - tm0), p1 = ex2f(s[n][1] - tm0);
            float p2 = ex2f(s[n][2] - tm1), p3 = ex2f(s[n][3] - tm1);
            lrow0 += p0 + p1; lrow1 += p2 + p3;
            int kc = n >> 1, hf = (n & 1) * 2;
            split2(p0, p1, pah[kc][hf],     pal[kc][hf]);
            split2(p2, p3, pah[kc][hf + 1], pal[kc][hf + 1]);
        }
        #pragma unroll
        for (int n = 0; n < 8; n++) {
            acc[n][0] *= corr0; acc[n][1] *= corr0;
            acc[n][2] *= corr1; acc[n][3] *= corr1;
        }

        // ---- acc += P . V (V via ldmatrix.trans), pass-major ----
        #pragma unroll
        for (int kc = 0; kc < 4; kc++) {
            uint32_t vh[4][4], vl[4][4];
            #pragma unroll
            for (int ndgp = 0; ndgp < 4; ndgp++) {
                uint32_t vr = base + A_VH + (kc*16 + (lt&1)*8 + lr) * ASTR
                            + (ndgp*16 + (lt>>1)*8) * 2;
                ldsm4t(vh[ndgp][0], vh[ndgp][1], vh[ndgp][2], vh[ndgp][3], vr);
                ldsm4t(vl[ndgp][0], vl[ndgp][1], vl[ndgp][2], vl[ndgp][3], vr + (A_VL - A_VH));
            }
            #pragma unroll
            for (int ndgp = 0; ndgp < 4; ndgp++) {
                mma16816(acc[2*ndgp],   pah[kc], vh[ndgp][0], vh[ndgp][1]);
                mma16816(acc[2*ndgp+1], pah[kc], vh[ndgp][2], vh[ndgp][3]);
            }
            #pragma unroll
            for (int ndgp = 0; ndgp < 4; ndgp++) {
                mma16816(acc[2*ndgp],   pah[kc], vl[ndgp][0], vl[ndgp][1]);
                mma16816(acc[2*ndgp+1], pah[kc], vl[ndgp][2], vl[ndgp][3]);
            }
            #pragma unroll
            for (int ndgp = 0; ndgp < 4; ndgp++) {
                mma16816(acc[2*ndgp],   pal[kc], vh[ndgp][0], vh[ndgp][1]);
                mma16816(acc[2*ndgp+1], pal[kc], vh[ndgp][2], vh[ndgp][3]);
            }
        }

        __syncthreads();
        if (kt + 2 < NT) { load_stage(kt + 2); CP_COMMIT(); }
    }

    // epilogue: normalize, split to bf16 hi/lo for the Wo GEMM (slot 0 staging)
    lrow0 += __shfl_xor_sync(0xffffffffu, lrow0, 1);
    lrow0 += __shfl_xor_sync(0xffffffffu, lrow0, 2);
    lrow1 += __shfl_xor_sync(0xffffffffu, lrow1, 1);
    lrow1 += __shfl_xor_sync(0xffffffffu, lrow1, 2);
    float inv0 = 1.f / lrow0, inv1 = 1.f / lrow1;
    size_t row = qbase + warp*16 + g;
    #pragma unroll
    for (int nd = 0; nd < 8; nd++) {
        int col = hofs + nd*8 + tg*2;
        uint32_t h01, l01, h23, l23;
        split2(acc[nd][0] * inv0, acc[nd][1] * inv0, h01, l01);
        split2(acc[nd][2] * inv1, acc[nd][3] * inv1, h23, l23);
        *reinterpret_cast<uint32_t*>(&g_Aqh[row * DD + col])       = h01;
        *reinterpret_cast<uint32_t*>(&g_Aql[row * DD + col])       = l01;
        *reinterpret_cast<uint32_t*>(&g_Aqh[(row + 8) * DD + col]) = h23;
        *reinterpret_cast<uint32_t*>(&g_Aql[(row + 8) * DD + col]) = l23;
    }
}

// ---------------- launch ----------------
extern "C" void kernel_launch(void* const* d_in, const int* in_sizes, int n_in,
                              void* d_out, int out_size) {
    const float* query = (const float*)d_in[0];
    // d_in[1] = key : unused by the reference computation
    const float* value = (const float*)d_in[2];
    const float* Rin   = (const float*)d_in[3];
    const float* Wq    = (const float*)d_in[4];
    const float* bq    = (const float*)d_in[5];
    const float* Wv    = (const float*)d_in[6];
    const float* bv    = (const float*)d_in[7];
    const float* Wr    = (const float*)d_in[8];
    const float* br    = (const float*)d_in[9];
    const float* Wh    = (const float*)d_in[10];
    const float* Wo    = (const float*)d_in[11];
    const float* bo    = (const float*)d_in[12];
    float* out = (float*)d_out;

    float* Rp;
    __nv_bfloat16 *Aqh, *Aql, *Avh, *Avl, *Arh, *Arl;
    __nv_bfloat16 *Wqh, *Wql, *Wvh, *Wvl, *Wrh, *Wrl, *Woh, *Wol;
    __nv_bfloat16 *Qh, *Ql, *Vh, *Vl;
    cudaGetSymbolAddress((void**)&Rp, g_Rp);
    cudaGetSymbolAddress((void**)&Aqh, g_Aqh); cudaGetSymbolAddress((void**)&Aql, g_Aql);
    cudaGetSymbolAddress((void**)&Avh, g_Avh); cudaGetSymbolAddress((void**)&Avl, g_Avl);
    cudaGetSymbolAddress((void**)&Arh, g_Arh); cudaGetSymbolAddress((void**)&Arl, g_Arl);
    cudaGetSymbolAddress((void**)&Wqh, g_Wqh); cudaGetSymbolAddress((void**)&Wql, g_Wql);
    cudaGetSymbolAddress((void**)&Wvh, g_Wvh); cudaGetSymbolAddress((void**)&Wvl, g_Wvl);
    cudaGetSymbolAddress((void**)&Wrh, g_Wrh); cudaGetSymbolAddress((void**)&Wrl, g_Wrl);
    cudaGetSymbolAddress((void**)&Woh, g_Woh); cudaGetSymbolAddress((void**)&Wol, g_Wol);
    cudaGetSymbolAddress((void**)&Qh, g_Qh);   cudaGetSymbolAddress((void**)&Ql, g_Ql);
    cudaGetSymbolAddress((void**)&Vh, g_Vh);   cudaGetSymbolAddress((void**)&Vl, g_Vl);

    cudaFuncSetAttribute(gemm_mma,
                         cudaFuncAttributeMaxDynamicSharedMemorySize, GEMM_SMEM);
    cudaFuncSetAttribute(attn_mma,
                         cudaFuncAttributeMaxDynamicSharedMemorySize, ATT_SMEM);

    const int nA4 = MROWS * DD / 4;   // 1048576
    const int nW4 = DD * DD / 4;      // 262144

    rowsum_kernel<<<(HH * DK + 127) / 128, 128>>>(Wh);

    // batched splits: 3 activations, 4 weights
    conv_split4<<<dim3(nA4 / 256, 3), 256>>>(query, value, Rin, query,
                                             Aqh, Aql, Avh, Avl, Arh, Arl, Aqh, Aql, nA4);
    conv_split4<<<dim3(nW4 / 256, 4), 256>>>(Wq, Wv, Wr, Wo,
                                             Wqh, Wql, Wvh, Wvl, Wrh, Wrl, Woh, Wol, nW4);

    // batched projection GEMMs (Q scaled-split, V split, R f32)
    GemmJob jq = { Aqh, Aql, Wqh, Wql, bq, nullptr, Qh, Ql, QK_SCALE };
    GemmJob jv = { Avh, Avl, Wvh, Wvl, bv, nullptr, Vh, Vl, 1.0f };
    GemmJob jr = { Arh, Arl, Wrh, Wrl, br, Rp, nullptr, nullptr, 1.0f };
    gemm_mma<<<dim3(DD/128, MROWS/128, 3), 256, GEMM_SMEM>>>(jq, jv, jr);

    recurrence_kernel<<<BB * HH, DK>>>();

    // attention writes bf16 split directly into Aqh/Aql
    attn_mma<<<dim3(SQ / 64, BB * HH), 128, ATT_SMEM>>>();

    // output projection -> f32 out
    GemmJob jo = { Aqh, Aql, Woh, Wol, bo, out, nullptr, nullptr, 1.0f };
    gemm_mma<<<dim3(DD/128, MROWS/128, 1), 256, GEMM_SMEM>>>(jo, jo, jo);
}

// round 14
// speedup vs baseline: 3.0123x; 1.0102x over previous
#include <cuda_runtime.h>
#include <cuda_bf16.h>
#include <math.h>
#include <stdint.h>

#define BB 2
#define SQ 2048
#define SK 2048
#define DD 1024
#define HH 16
#define DK 64
#define MROWS (BB*SQ)   // 4096

#define QK_SCALE (0.125f * 1.4426950408889634f)

// ---------------- scratch (device globals; no allocation allowed) ----------------
__device__ float g_Rp[BB*SK*DD];
__device__ int   g_prog[BB*HH];                              // recurrence progress (chunks of 64)
__device__ __nv_bfloat16 g_Aqh[MROWS*DD], g_Aql[MROWS*DD];   // query split / attn out
__device__ __nv_bfloat16 g_Avh[MROWS*DD], g_Avl[MROWS*DD];   // value split
__device__ __nv_bfloat16 g_Arh[MROWS*DD], g_Arl[MROWS*DD];   // R split
__device__ __nv_bfloat16 g_Wqh[DD*DD], g_Wql[DD*DD];
__device__ __nv_bfloat16 g_Wvh[DD*DD], g_Wvl[DD*DD];
__device__ __nv_bfloat16 g_Wrh[DD*DD], g_Wrl[DD*DD];
__device__ __nv_bfloat16 g_Woh[DD*DD], g_Wol[DD*DD];
__device__ __nv_bfloat16 g_Qh[MROWS*DD], g_Ql[MROWS*DD];
__device__ __nv_bfloat16 g_Vh[MROWS*DD], g_Vl[MROWS*DD];
__device__ __nv_bfloat16 g_Hh[MROWS*DD], g_Hl[MROWS*DD];

// ---------------- helpers ----------------
__device__ __forceinline__ uint32_t smem_to_u32(const void* p) {
    uint32_t a;
    asm("{ .reg .u64 t; cvta.to.shared.u64 t, %1; cvt.u32.u64 %0, t; }" : "=r"(a) : "l"(p));
    return a;
}
__device__ __forceinline__ float ex2f(float x) {
    float r; asm("ex2.approx.f32 %0, %1;" : "=f"(r) : "f"(x)); return r;
}
__device__ __forceinline__ void ldsm4(uint32_t& r0, uint32_t& r1, uint32_t& r2, uint32_t& r3,
                                      uint32_t addr) {
    asm volatile("ldmatrix.sync.aligned.m8n8.x4.shared.b16 {%0,%1,%2,%3}, [%4];"
        : "=r"(r0), "=r"(r1), "=r"(r2), "=r"(r3) : "r"(addr));
}
__device__ __forceinline__ void ldsm4t(uint32_t& r0, uint32_t& r1, uint32_t& r2, uint32_t& r3,
                                       uint32_t addr) {
    asm volatile("ldmatrix.sync.aligned.m8n8.x4.trans.shared.b16 {%0,%1,%2,%3}, [%4];"
        : "=r"(r0), "=r"(r1), "=r"(r2), "=r"(r3) : "r"(addr));
}
#define CP_ASYNC16(dst, src) \
    asm volatile("cp.async.cg.shared.global [%0], [%1], 16;" :: "r"(dst), "l"(src) : "memory")
#define CP_COMMIT() asm volatile("cp.async.commit_group;" ::: "memory")
#define CP_WAIT1() asm volatile("cp.async.wait_group 1;" ::: "memory")
#define CP_WAIT0() asm volatile("cp.async.wait_group 0;" ::: "memory")

__device__ __forceinline__ void mma16816(float* d, const uint32_t* a, uint32_t b0, uint32_t b1) {
    asm volatile("mma.sync.aligned.m16n8k16.row.col.f32.bf16.bf16.f32 "
        "{%0,%1,%2,%3}, {%4,%5,%6,%7}, {%8,%9}, {%0,%1,%2,%3};"
        : "+f"(d[0]), "+f"(d[1]), "+f"(d[2]), "+f"(d[3])
        : "r"(a[0]), "r"(a[1]), "r"(a[2]), "r"(a[3]), "r"(b0), "r"(b1));
}

__device__ __forceinline__ void split2(float x, float y, uint32_t& hi, uint32_t& lo) {
    __nv_bfloat16 xh = __float2bfloat16_rn(x), yh = __float2bfloat16_rn(y);
    float xr = x - __bfloat162float(xh), yr = y - __bfloat162float(yh);
    __nv_bfloat16 xl = __float2bfloat16_rn(xr), yl = __float2bfloat16_rn(yr);
    hi = ((uint32_t)__bfloat16_as_ushort(yh) << 16) | __bfloat16_as_ushort(xh);
    lo = ((uint32_t)__bfloat16_as_ushort(yl) << 16) | __bfloat16_as_ushort(xl);
}

// ---------------- batched f32 -> bf16 hi/lo split (also resets g_prog) ----------------
__global__ void conv_split4(const float* i0, const float* i1, const float* i2, const float* i3,
                            __nv_bfloat16* h0, __nv_bfloat16* l0,
                            __nv_bfloat16* h1, __nv_bfloat16* l1,
                            __nv_bfloat16* h2, __nv_bfloat16* l2,
                            __nv_bfloat16* h3, __nv_bfloat16* l3, int n4) {
    if (blockIdx.x == 0 && blockIdx.y == 0 && threadIdx.x < BB*HH)
        g_prog[threadIdx.x] = 0;
    int i = blockIdx.x * blockDim.x + threadIdx.x;
    if (i >= n4) return;
    const float* in; __nv_bfloat16 *hi, *lo;
    switch (blockIdx.y) {
        case 0: in = i0; hi = h0; lo = l0; break;
        case 1: in = i1; hi = h1; lo = l1; break;
        case 2: in = i2; hi = h2; lo = l2; break;
        default: in = i3; hi = h3; lo = l3; break;
    }
    float4 v = reinterpret_cast<const float4*>(in)[i];
    uint32_t a0, b0, a1, b1;
    split2(v.x, v.y, a0, b0);
    split2(v.z, v.w, a1, b1);
    reinterpret_cast<uint2*>(hi)[i] = make_uint2(a0, a1);
    reinterpret_cast<uint2*>(lo)[i] = make_uint2(b0, b1);
}

// ---------------- mma.sync GEMM, batched over grid.z ----------------
struct GemmJob {
    const __nv_bfloat16 *Ah, *Al, *Wh, *Wl;
    const float* bias;
    float* Cf;
    __nv_bfloat16 *Chi, *Clo;
    float scale;
};

#define GSTR 80
#define G_A_L 10240
#define G_W_H 20480
#define G_W_L 30720
#define GSTG 40960
#define GEMM_SMEM (2*GSTG)   // 81920

__global__ void __launch_bounds__(256, 2) gemm_mma(GemmJob j0, GemmJob j1, GemmJob j2)
{
    const GemmJob j = (blockIdx.z == 0) ? j0 : (blockIdx.z == 1) ? j1 : j2;
    extern __shared__ __align__(1024) char sm[];
    const uint32_t sb = smem_to_u32(sm);
    const int tid = threadIdx.x;
    const int warp = tid >> 5, lane = tid & 31;
    const int g = lane >> 2, tg = lane & 3;
    const int wm = warp >> 1, wn = warp & 1;
    const int bm = blockIdx.y * 128, bn = blockIdx.x * 128;
    const int lt = lane >> 3, lr = lane & 7;

    auto load_stage = [&](int kt) {
        const uint32_t base = sb + (kt & 1) * GSTG;
        const int kofs = kt * 32;
        #pragma unroll
        for (int t = tid; t < 512; t += 256) {
            int r = t >> 2, c = t & 3;
            uint32_t da = base + r * GSTR + c * 16;
            size_t ga = (size_t)(bm + r) * DD + kofs + c * 8;
            size_t gw = (size_t)(bn + r) * DD + kofs + c * 8;
            CP_ASYNC16(da,         j.Ah + ga);
            CP_ASYNC16(da + G_A_L, j.Al + ga);
            uint32_t dw = base + G_W_H + r * GSTR + c * 16;
            CP_ASYNC16(dw,                 j.Wh + gw);
            CP_ASYNC16(dw + (G_W_L-G_W_H), j.Wl + gw);
        }
    };

    float acc[2][8][4];
    #pragma unroll
    for (int mi = 0; mi < 2; mi++)
        #pragma unroll
        for (int ni = 0; ni < 8; ni++)
            #pragma unroll
            for (int q = 0; q < 4; q++) acc[mi][ni][q] = 0.f;

    load_stage(0); CP_COMMIT();
    load_stage(1); CP_COMMIT();

    const int NT = 32;
    for (int kt = 0; kt < NT; kt++) {
        if (kt == NT - 1) { CP_WAIT0(); } else { CP_WAIT1(); }
        __syncthreads();
        const uint32_t base = sb + (kt & 1) * GSTG;

        #pragma unroll
        for (int kc = 0; kc < 2; kc++) {
            uint32_t ah[2][4], al[2][4], bh[4][4], bl[4][4];
            #pragma unroll
            for (int mi = 0; mi < 2; mi++) {
                uint32_t ar = base + (wm*32 + mi*16 + (lt&1)*8 + lr) * GSTR
                            + kc*32 + (lt>>1)*16;
                ldsm4(ah[mi][0], ah[mi][1], ah[mi][2], ah[mi][3], ar);
                ldsm4(al[mi][0], al[mi][1], al[mi][2], al[mi][3], ar + G_A_L);
            }
            #pragma unroll
            for (int ngp = 0; ngp < 4; ngp++) {
                uint32_t br = base + G_W_H + (wn*64 + ngp*16 + (lt>>1)*8 + lr) * GSTR
                            + kc*32 + (lt&1)*16;
                ldsm4(bh[ngp][0], bh[ngp][1], bh[ngp][2], bh[ngp][3], br);
                ldsm4(bl[ngp][0], bl[ngp][1], bl[ngp][2], bl[ngp][3], br + (G_W_L-G_W_H));
            }
            #pragma unroll
            for (int mi = 0; mi < 2; mi++)
                #pragma unroll
                for (int ngp = 0; ngp < 4; ngp++) {
                    mma16816(acc[mi][2*ngp],   ah[mi], bh[ngp][0], bh[ngp][1]);
                    mma16816(acc[mi][2*ngp+1], ah[mi], bh[ngp][2], bh[ngp][3]);
                }
            #pragma unroll
            for (int mi = 0; mi < 2; mi++)
                #pragma unroll
                for (int ngp = 0; ngp < 4; ngp++) {
                    mma16816(acc[mi][2*ngp],   ah[mi], bl[ngp][0], bl[ngp][1]);
                    mma16816(acc[mi][2*ngp+1], ah[mi], bl[ngp][2], bl[ngp][3]);
                }
            #pragma unroll
            for (int mi = 0; mi < 2; mi++)
                #pragma unroll
                for (int ngp = 0; ngp < 4; ngp++) {
                    mma16816(acc[mi][2*ngp],   al[mi], bh[ngp][0], bh[ngp][1]);
                    mma16816(acc[mi][2*ngp+1], al[mi], bh[ngp][2], bh[ngp][3]);
                }
        }
        __syncthreads();
        if (kt + 2 < NT) { load_stage(kt + 2); CP_COMMIT(); }
    }

    #pragma unroll
    for (int mi = 0; mi < 2; mi++) {
        int row = bm + wm*32 + mi*16 + g;
        #pragma unroll
        for (int ni = 0; ni < 8; ni++) {
            int col = bn + wn*64 + ni*8 + tg*2;
            float b0 = j.bias[col], b1 = j.bias[col + 1];
            float v0 = acc[mi][ni][0] + b0, v1 = acc[mi][ni][1] + b1;
            float v2 = acc[mi][ni][2] + b0, v3 = acc[mi][ni][3] + b1;
            if (j.Cf) {
                *reinterpret_cast<float2*>(&j.Cf[(size_t)row * DD + col])     = make_float2(v0, v1);
                *reinterpret_cast<float2*>(&j.Cf[(size_t)(row+8) * DD + col]) = make_float2(v2, v3);
            } else {
                uint32_t h01, l01, h23, l23;
                split2(v0 * j.scale, v1 * j.scale, h01, l01);
                split2(v2 * j.scale, v3 * j.scale, h23, l23);
                *reinterpret_cast<uint32_t*>(&j.Chi[(size_t)row * DD + col])     = h01;
                *reinterpret_cast<uint32_t*>(&j.Clo[(size_t)row * DD + col])     = l01;
                *reinterpret_cast<uint32_t*>(&j.Chi[(size_t)(row+8) * DD + col]) = h23;
                *reinterpret_cast<uint32_t*>(&j.Clo[(size_t)(row+8) * DD + col]) = l23;
            }
        }
    }
}

// ---------------- fused attention + recurrence ----------------
// Flat grid: blocks [0,32) = recurrence producers (one per (b,h));
//            blocks [32, 32+1024) = attention consumers (bh = i>>5, q0 = (i&31)*64).
// Producers publish H in 64-row chunks via g_prog; consumers gate cp.async stages on it.
#define ASTR 144
#define A_HL 9216
#define A_VH 18432
#define A_VL 27648
#define ASTG 36864
#define ATT_SMEM (2*ASTG)    // 73728

__device__ __forceinline__ void wait_chunk(int bh, int need) {
    if (threadIdx.x == 0) {
        volatile int* p = &g_prog[bh];
        while (*p < need) __nanosleep(64);
        __threadfence();
    }
    __syncthreads();
}

__global__ void __launch_bounds__(128, 3) attn_mma(const float* __restrict__ WhIn) {
    const int tid = threadIdx.x;

    // ======== producer blocks: recurrence ========
    if (blockIdx.x < BB*HH) {
        const int bh = blockIdx.x;
        const int b = bh >> 4, h = bh & 15;
        const int d = tid;
        float w = 0.f, st = 0.f;
        const float* Rp = g_Rp + ((size_t)b * SK) * DD + h * DK + d;
        size_t ho = ((size_t)b * SK) * DD + h * DK + d;
        if (d < DK) {
            const float* wp = WhIn + (size_t)h * DK * DK + (size_t)d * DK;
            #pragma unroll
            for (int k = 0; k < DK; k++) w += wp[k];
        }
        for (int c = 0; c < SK/64; c++) {
            if (d < DK) {
                #pragma unroll 1
                for (int tt = 0; tt < 64; tt += 8) {
                    int t = c*64 + tt;
                    float r[8];
                    #pragma unroll
                    for (int i = 0; i < 8; i++) r[i] = Rp[(size_t)(t + i) * DD];
                    #pragma unroll
                    for (int i = 0; i < 8; i++) {
                        st = tanhf(st * w + r[i]);
                        __nv_bfloat16 hh = __float2bfloat16_rn(st);
                        __nv_bfloat16 hl = __float2bfloat16_rn(st - __bfloat162float(hh));
                        g_Hh[ho + (size_t)(t + i) * DD] = hh;
                        g_Hl[ho + (size_t)(t + i) * DD] = hl;
                    }
                }
            }
            __syncthreads();
            if (tid == 0) { __threadfence(); atomicExch(&g_prog[bh], c + 1); }
        }
        return;
    }

    // ======== consumer blocks: flash attention ========
    const int flat = blockIdx.x - BB*HH;
    const int bh = flat >> 5;
    const int b = bh >> 4, h = bh & 15;
    const int q0 = (flat & 31) * 64;
    const int warp = tid >> 5, lane = tid & 31;
    const int g = lane >> 2, tg = lane & 3;
    const int lt = lane >> 3, lr = lane & 7;

    extern __shared__ __align__(1024) char sm[];
    const uint32_t sb = smem_to_u32(sm);

    const size_t qbase = (size_t)(b * SQ + q0);
    const size_t kbase = (size_t)(b * SK);
    const int hofs = h * DK;

    // Q fragments preloaded into registers
    uint32_t qh[4][4], ql[4][4];
    {
        size_t r0 = (qbase + warp*16 + g) * DD + hofs;
        size_t r1 = r0 + 8 * DD;
        #pragma unroll
        for (int kc = 0; kc < 4; kc++) {
            int c0 = kc*16 + tg*2;
            qh[kc][0] = *reinterpret_cast<const uint32_t*>(g_Qh + r0 + c0);
            qh[kc][1] = *reinterpret_cast<const uint32_t*>(g_Qh + r1 + c0);
            qh[kc][2] = *reinterpret_cast<const uint32_t*>(g_Qh + r0 + c0 + 8);
            qh[kc][3] = *reinterpret_cast<const uint32_t*>(g_Qh + r1 + c0 + 8);
            ql[kc][0] = *reinterpret_cast<const uint32_t*>(g_Ql + r0 + c0);
            ql[kc][1] = *reinterpret_cast<const uint32_t*>(g_Ql + r1 + c0);
            ql[kc][2] = *reinterpret_cast<const uint32_t*>(g_Ql + r0 + c0 + 8);
            ql[kc][3] = *reinterpret_cast<const uint32_t*>(g_Ql + r1 + c0 + 8);
        }
    }

    auto load_stage = [&](int kt) {
        const uint32_t base = sb + (kt & 1) * ASTG;
        const int k0 = kt * 64;
        #pragma unroll
        for (int t = tid; t < 512; t += 128) {
            int r = t >> 3, c = t & 7;
            uint32_t dst = base + r * ASTR + c * 16;
            size_t src = (kbase + k0 + r) * DD + hofs + c * 8;
            CP_ASYNC16(dst,        g_Hh + src);
            CP_ASYNC16(dst + A_HL, g_Hl + src);
            CP_ASYNC16(dst + A_VH, g_Vh + src);
            CP_ASYNC16(dst + A_VL, g_Vl + src);
        }
    };

    wait_chunk(bh, 1);
    load_stage(0); CP_COMMIT();
    wait_chunk(bh, 2);
    load_stage(1); CP_COMMIT();

    float acc[8][4];
    #pragma unroll
    for (int n = 0; n < 8; n++)
        #pragma unroll
        for (int q = 0; q < 4; q++) acc[n][q] = 0.f;
    float mrow0 = -1e30f, mrow1 = -1e30f, lrow0 = 0.f, lrow1 = 0.f;

    const int NT = SK / 64;   // 32
    for (int kt = 0; kt < NT; kt++) {
        if (kt < NT - 1) { CP_WAIT1(); } else { CP_WAIT0(); }
        __syncthreads();
        const uint32_t base = sb + (kt & 1) * ASTG;

        // ---- S = Q . H^T ----
        float s[8][4];
        #pragma unroll
        for (int n = 0; n < 8; n++)
            #pragma unroll
            for (int q = 0; q < 4; q++) s[n][q] = 0.f;

        #pragma unroll
        for (int kc = 0; kc < 4; kc++) {
            uint32_t hb[4][4], lb[4][4];
            #pragma unroll
            for (int ngp = 0; ngp < 4; ngp++) {
                uint32_t br = base + (ngp*16 + (lt>>1)*8 + lr) * ASTR + kc*32 + (lt&1)*16;
                ldsm4(hb[ngp][0], hb[ngp][1], hb[ngp][2], hb[ngp][3], br);
                ldsm4(lb[ngp][0], lb[ngp][1], lb[ngp][2], lb[ngp][3], br + A_HL);
            }
            #pragma unroll
            for (int ngp = 0; ngp < 4; ngp++) {
                mma16816(s[2*ngp],   qh[kc], hb[ngp][0], hb[ngp][1]);
                mma16816(s[2*ngp+1], qh[kc], hb[ngp][2], hb[ngp][3]);
            }
            #pragma unroll
            for (int ngp = 0; ngp < 4; ngp++) {
                mma16816(s[2*ngp],   qh[kc], lb[ngp][0], lb[ngp][1]);
                mma16816(s[2*ngp+1], qh[kc], lb[ngp][2], lb[ngp][3]);
            }
            #pragma unroll
            for (int ngp = 0; ngp < 4; ngp++) {
                mma16816(s[2*ngp],   ql[kc], hb[ngp][0], hb[ngp][1]);
                mma16816(s[2*ngp+1], ql[kc], hb[ngp][2], hb[ngp][3]);
            }
        }

        // ---- online softmax (base-2) ----
        float tm0 = mrow0, tm1 = mrow1;
        #pragma unroll
        for (int n = 0; n < 8; n++) {
            tm0 = fmaxf(tm0, fmaxf(s[n][0], s[n][1]));
            tm1 = fmaxf(tm1, fmaxf(s[n][2], s[n][3]));
        }
        tm0 = fmaxf(tm0, __shfl_xor_sync(0xffffffffu, tm0, 1));
        tm0 = fmaxf(tm0, __shfl_xor_sync(0xffffffffu, tm0, 2));
        tm1 = fmaxf(tm1, __shfl_xor_sync(0xffffffffu, tm1, 1));
        tm1 = fmaxf(tm1, __shfl_xor_sync(0xffffffffu, tm1, 2));
        float corr0 = ex2f(mrow0 - tm0), corr1 = ex2f(mrow1 - tm1);
        mrow0 = tm0; mrow1 = tm1;
        lrow0 *= corr0; lrow1 *= corr1;

        uint32_t pah[4][4], pal[4][4];
        #pragma unroll
        for (int n = 0; n < 8; n++) {
            float p0 = ex2f(s[n][0] - tm0), p1 = ex2f(s[n][1] - tm0);
            float p2 = ex2f(s[n][2] - tm1), p3 = ex2f(s[n][3] - tm1);
            lrow0 += p0 + p1; lrow1 += p2 + p3;
            int kc = n >> 1, hf = (n & 1) * 2;
            split2(p0, p1, pah[kc][hf],     pal[kc][hf]);
            split2(p2, p3, pah[kc][hf + 1], pal[kc][hf + 1]);
        }
        #pragma unroll
        for (int n = 0; n < 8; n++) {
            acc[n][0] *= corr0; acc[n][1] *= corr0;
            acc[n][2] *= corr1; acc[n][3] *= corr1;
        }

        // ---- acc += P . V (V via ldmatrix.trans), pass-major ----
        #pragma unroll
        for (int kc = 0; kc < 4; kc++) {
            uint32_t vh[4][4], vl[4][4];
            #pragma unroll
            for (int ndgp = 0; ndgp < 4; ndgp++) {
                uint32_t vr = base + A_VH + (kc*16 + (lt&1)*8 + lr) * ASTR
                            + (ndgp*16 + (lt>>1)*8) * 2;
                ldsm4t(vh[ndgp][0], vh[ndgp][1], vh[ndgp][2], vh[ndgp][3], vr);
                ldsm4t(vl[ndgp][0], vl[ndgp][1], vl[ndgp][2], vl[ndgp][3], vr + (A_VL - A_VH));
            }
            #pragma unroll
            for (int ndgp = 0; ndgp < 4; ndgp++) {
                mma16816(acc[2*ndgp],   pah[kc], vh[ndgp][0], vh[ndgp][1]);
                mma16816(acc[2*ndgp+1], pah[kc], vh[ndgp][2], vh[ndgp][3]);
            }
            #pragma unroll
            for (int ndgp = 0; ndgp < 4; ndgp++) {
                mma16816(acc[2*ndgp],   pah[kc], vl[ndgp][0], vl[ndgp][1]);
                mma16816(acc[2*ndgp+1], pah[kc], vl[ndgp][2], vl[ndgp][3]);
            }
            #pragma unroll
            for (int ndgp = 0; ndgp < 4; ndgp++) {
                mma16816(acc[2*ndgp],   pal[kc], vh[ndgp][0], vh[ndgp][1]);
                mma16816(acc[2*ndgp+1], pal[kc], vh[ndgp][2], vh[ndgp][3]);
            }
        }

        __syncthreads();
        if (kt + 2 < NT) {
            wait_chunk(bh, kt + 3);
            load_stage(kt + 2); CP_COMMIT();
        }
    }

    // epilogue: normalize, split to bf16 hi/lo for the Wo GEMM
    lrow0 += __shfl_xor_sync(0xffffffffu, lrow0, 1);
    lrow0 += __shfl_xor_sync(0xffffffffu, lrow0, 2);
    lrow1 += __shfl_xor_sync(0xffffffffu, lrow1, 1);
    lrow1 += __shfl_xor_sync(0xffffffffu, lrow1, 2);
    float inv0 = 1.f / lrow0, inv1 = 1.f / lrow1;
    size_t row = qbase + warp*16 + g;
    #pragma unroll
    for (int nd = 0; nd < 8; nd++) {
        int col = hofs + nd*8 + tg*2;
        uint32_t h01, l01, h23, l23;
        split2(acc[nd][0] * inv0, acc[nd][1] * inv0, h01, l01);
        split2(acc[nd][2] * inv1, acc[nd][3] * inv1, h23, l23);
        *reinterpret_cast<uint32_t*>(&g_Aqh[row * DD + col])       = h01;
        *reinterpret_cast<uint32_t*>(&g_Aql[row * DD + col])       = l01;
        *reinterpret_cast<uint32_t*>(&g_Aqh[(row + 8) * DD + col]) = h23;
        *reinterpret_cast<uint32_t*>(&g_Aql[(row + 8) * DD + col]) = l23;
    }
}

// ---------------- launch ----------------
extern "C" void kernel_launch(void* const* d_in, const int* in_sizes, int n_in,
                              void* d_out, int out_size) {
    const float* query = (const float*)d_in[0];
    // d_in[1] = key : unused by the reference computation
    const float* value = (const float*)d_in[2];
    const float* Rin   = (const float*)d_in[3];
    const float* Wq    = (const float*)d_in[4];
    const float* bq    = (const float*)d_in[5];
    const float* Wv    = (const float*)d_in[6];
    const float* bv    = (const float*)d_in[7];
    const float* Wr    = (const float*)d_in[8];
    const float* br    = (const float*)d_in[9];
    const float* Wh    = (const float*)d_in[10];
    const float* Wo    = (const float*)d_in[11];
    const float* bo    = (const float*)d_in[12];
    float* out = (float*)d_out;

    float* Rp;
    __nv_bfloat16 *Aqh, *Aql, *Avh, *Avl, *Arh, *Arl;
    __nv_bfloat16 *Wqh, *Wql, *Wvh, *Wvl, *Wrh, *Wrl, *Woh, *Wol;
    __nv_bfloat16 *Qh, *Ql, *Vh, *Vl;
    cudaGetSymbolAddress((void**)&Rp, g_Rp);
    cudaGetSymbolAddress((void**)&Aqh, g_Aqh); cudaGetSymbolAddress((void**)&Aql, g_Aql);
    cudaGetSymbolAddress((void**)&Avh, g_Avh); cudaGetSymbolAddress((void**)&Avl, g_Avl);
    cudaGetSymbolAddress((void**)&Arh, g_Arh); cudaGetSymbolAddress((void**)&Arl, g_Arl);
    cudaGetSymbolAddress((void**)&Wqh, g_Wqh); cudaGetSymbolAddress((void**)&Wql, g_Wql);
    cudaGetSymbolAddress((void**)&Wvh, g_Wvh); cudaGetSymbolAddress((void**)&Wvl, g_Wvl);
    cudaGetSymbolAddress((void**)&Wrh, g_Wrh); cudaGetSymbolAddress((void**)&Wrl, g_Wrl);
    cudaGetSymbolAddress((void**)&Woh, g_Woh); cudaGetSymbolAddress((void**)&Wol, g_Wol);
    cudaGetSymbolAddress((void**)&Qh, g_Qh);   cudaGetSymbolAddress((void**)&Ql, g_Ql);
    cudaGetSymbolAddress((void**)&Vh, g_Vh);   cudaGetSymbolAddress((void**)&Vl, g_Vl);

    cudaFuncSetAttribute(gemm_mma,
                         cudaFuncAttributeMaxDynamicSharedMemorySize, GEMM_SMEM);
    cudaFuncSetAttribute(attn_mma,
                         cudaFuncAttributeMaxDynamicSharedMemorySize, ATT_SMEM);

    const int nA4 = MROWS * DD / 4;
    const int nW4 = DD * DD / 4;

    // batched splits (conv also resets g_prog for the fused attn)
    conv_split4<<<dim3(nA4 / 256, 3), 256>>>(query, value, Rin, query,
                                             Aqh, Aql, Avh, Avl, Arh, Arl, Aqh, Aql, nA4);
    conv_split4<<<dim3(nW4 / 256, 4), 256>>>(Wq, Wv, Wr, Wo,
                                             Wqh, Wql, Wvh, Wvl, Wrh, Wrl, Woh, Wol, nW4);

    // batched projection GEMMs (Q scaled-split, V split, R f32)
    GemmJob jq = { Aqh, Aql, Wqh, Wql, bq, nullptr, Qh, Ql, QK_SCALE };
    GemmJob jv = { Avh, Avl, Wvh, Wvl, bv, nullptr, Vh, Vl, 1.0f };
    GemmJob jr = { Arh, Arl, Wrh, Wrl, br, Rp, nullptr, nullptr, 1.0f };
    gemm_mma<<<dim3(DD/128, MROWS/128, 3), 256, GEMM_SMEM>>>(jq, jv, jr);

    // fused recurrence (32 producer blocks) + attention (1024 consumer blocks)
    attn_mma<<<BB*HH + BB*HH*(SQ/64), 128, ATT_SMEM>>>(Wh);

    // output projection -> f32 out
    GemmJob jo = { Aqh, Aql, Woh, Wol, bo, out, nullptr, nullptr, 1.0f };
    gemm_mma<<<dim3(DD/128, MROWS/128, 1), 256, GEMM_SMEM>>>(jo, jo, jo);
}

// round 15
// speedup vs baseline: 3.1820x; 1.0563x over previous
#include <cuda_runtime.h>
#include <cuda_bf16.h>
#include <cuda_fp16.h>
#include <math.h>
#include <stdint.h>

#define BB 2
#define SQ 2048
#define SK 2048
#define DD 1024
#define HH 16
#define DK 64
#define MROWS (BB*SQ)   // 4096

#define QK_SCALE (0.125f * 1.4426950408889634f)

// ---------------- scratch (device globals; no allocation allowed) ----------------
__device__ float g_Rp[BB*SK*DD];
__device__ int   g_prog[BB*HH];
__device__ __nv_bfloat16 g_Aqh[MROWS*DD], g_Aql[MROWS*DD];   // bf16 A splits / attn out
__device__ __nv_bfloat16 g_Avh[MROWS*DD], g_Avl[MROWS*DD];
__device__ __nv_bfloat16 g_Arh[MROWS*DD], g_Arl[MROWS*DD];
__device__ __nv_bfloat16 g_Wqh[DD*DD], g_Wql[DD*DD];
__device__ __nv_bfloat16 g_Wvh[DD*DD], g_Wvl[DD*DD];
__device__ __nv_bfloat16 g_Wrh[DD*DD], g_Wrl[DD*DD];
__device__ __nv_bfloat16 g_Woh[DD*DD], g_Wol[DD*DD];
// fp16 splits for the attention datapath
__device__ __half g_Qh[MROWS*DD], g_Ql[MROWS*DD];
__device__ __half g_Vh[MROWS*DD], g_Vl[MROWS*DD];
__device__ __half g_Hh[MROWS*DD], g_Hl[MROWS*DD];

// ---------------- helpers ----------------
__device__ __forceinline__ uint32_t smem_to_u32(const void* p) {
    uint32_t a;
    asm("{ .reg .u64 t; cvta.to.shared.u64 t, %1; cvt.u32.u64 %0, t; }" : "=r"(a) : "l"(p));
    return a;
}
__device__ __forceinline__ float ex2f(float x) {
    float r; asm("ex2.approx.f32 %0, %1;" : "=f"(r) : "f"(x)); return r;
}
__device__ __forceinline__ void ldsm4(uint32_t& r0, uint32_t& r1, uint32_t& r2, uint32_t& r3,
                                      uint32_t addr) {
    asm volatile("ldmatrix.sync.aligned.m8n8.x4.shared.b16 {%0,%1,%2,%3}, [%4];"
        : "=r"(r0), "=r"(r1), "=r"(r2), "=r"(r3) : "r"(addr));
}
__device__ __forceinline__ void ldsm4t(uint32_t& r0, uint32_t& r1, uint32_t& r2, uint32_t& r3,
                                       uint32_t addr) {
    asm volatile("ldmatrix.sync.aligned.m8n8.x4.trans.shared.b16 {%0,%1,%2,%3}, [%4];"
        : "=r"(r0), "=r"(r1), "=r"(r2), "=r"(r3) : "r"(addr));
}
#define CP_ASYNC16(dst, src) \
    asm volatile("cp.async.cg.shared.global [%0], [%1], 16;" :: "r"(dst), "l"(src) : "memory")
#define CP_COMMIT() asm volatile("cp.async.commit_group;" ::: "memory")
#define CP_WAIT1() asm volatile("cp.async.wait_group 1;" ::: "memory")
#define CP_WAIT0() asm volatile("cp.async.wait_group 0;" ::: "memory")

// bf16 mma (GEMMs)
__device__ __forceinline__ void mma16816(float* d, const uint32_t* a, uint32_t b0, uint32_t b1) {
    asm volatile("mma.sync.aligned.m16n8k16.row.col.f32.bf16.bf16.f32 "
        "{%0,%1,%2,%3}, {%4,%5,%6,%7}, {%8,%9}, {%0,%1,%2,%3};"
        : "+f"(d[0]), "+f"(d[1]), "+f"(d[2]), "+f"(d[3])
        : "r"(a[0]), "r"(a[1]), "r"(a[2]), "r"(a[3]), "r"(b0), "r"(b1));
}
// fp16 mma (attention)
__device__ __forceinline__ void mma16816h(float* d, const uint32_t* a, uint32_t b0, uint32_t b1) {
    asm volatile("mma.sync.aligned.m16n8k16.row.col.f32.f16.f16.f32 "
        "{%0,%1,%2,%3}, {%4,%5,%6,%7}, {%8,%9}, {%0,%1,%2,%3};"
        : "+f"(d[0]), "+f"(d[1]), "+f"(d[2]), "+f"(d[3])
        : "r"(a[0]), "r"(a[1]), "r"(a[2]), "r"(a[3]), "r"(b0), "r"(b1));
}

__device__ __forceinline__ void split2(float x, float y, uint32_t& hi, uint32_t& lo) {
    __nv_bfloat16 xh = __float2bfloat16_rn(x), yh = __float2bfloat16_rn(y);
    float xr = x - __bfloat162float(xh), yr = y - __bfloat162float(yh);
    __nv_bfloat16 xl = __float2bfloat16_rn(xr), yl = __float2bfloat16_rn(yr);
    hi = ((uint32_t)__bfloat16_as_ushort(yh) << 16) | __bfloat16_as_ushort(xh);
    lo = ((uint32_t)__bfloat16_as_ushort(yl) << 16) | __bfloat16_as_ushort(xl);
}
// fp16 hi/lo split (x -> low half, y -> high half)
__device__ __forceinline__ void split2h(float x, float y, uint32_t& hi, uint32_t& lo) {
    __half xh = __float2half_rn(x), yh = __float2half_rn(y);
    float xr = x - __half2float(xh), yr = y - __half2float(yh);
    __half xl = __float2half_rn(xr), yl = __float2half_rn(yr);
    hi = ((uint32_t)__half_as_ushort(yh) << 16) | __half_as_ushort(xh);
    lo = ((uint32_t)__half_as_ushort(yl) << 16) | __half_as_ushort(xl);
}
// pack two f32 -> f16x2 (x -> low, y -> high)
__device__ __forceinline__ uint32_t packh2(float x, float y) {
    uint32_t r; asm("cvt.rn.f16x2.f32 %0, %1, %2;" : "=r"(r) : "f"(y), "f"(x)); return r;
}

// ---------------- batched f32 -> bf16 hi/lo split (also resets g_prog) ----------------
__global__ void conv_split4(const float* i0, const float* i1, const float* i2, const float* i3,
                            __nv_bfloat16* h0, __nv_bfloat16* l0,
                            __nv_bfloat16* h1, __nv_bfloat16* l1,
                            __nv_bfloat16* h2, __nv_bfloat16* l2,
                            __nv_bfloat16* h3, __nv_bfloat16* l3, int n4) {
    if (blockIdx.x == 0 && blockIdx.y == 0 && threadIdx.x < BB*HH)
        g_prog[threadIdx.x] = 0;
    int i = blockIdx.x * blockDim.x + threadIdx.x;
    if (i >= n4) return;
    const float* in; __nv_bfloat16 *hi, *lo;
    switch (blockIdx.y) {
        case 0: in = i0; hi = h0; lo = l0; break;
        case 1: in = i1; hi = h1; lo = l1; break;
        case 2: in = i2; hi = h2; lo = l2; break;
        default: in = i3; hi = h3; lo = l3; break;
    }
    float4 v = reinterpret_cast<const float4*>(in)[i];
    uint32_t a0, b0, a1, b1;
    split2(v.x, v.y, a0, b0);
    split2(v.z, v.w, a1, b1);
    reinterpret_cast<uint2*>(hi)[i] = make_uint2(a0, a1);
    reinterpret_cast<uint2*>(lo)[i] = make_uint2(b0, b1);
}

// ---------------- mma.sync GEMM, batched over grid.z ----------------
struct GemmJob {
    const __nv_bfloat16 *Ah, *Al, *Wh, *Wl;
    const float* bias;
    float* Cf;                 // f32 out (or null)
    __half *Chi, *Clo;         // fp16 split out (used when Cf==null)
    float scale;
};

#define GSTR 80
#define G_A_L 10240
#define G_W_H 20480
#define G_W_L 30720
#define GSTG 40960
#define GEMM_SMEM (2*GSTG)   // 81920

__global__ void __launch_bounds__(256, 2) gemm_mma(GemmJob j0, GemmJob j1, GemmJob j2)
{
    const GemmJob j = (blockIdx.z == 0) ? j0 : (blockIdx.z == 1) ? j1 : j2;
    extern __shared__ __align__(1024) char sm[];
    const uint32_t sb = smem_to_u32(sm);
    const int tid = threadIdx.x;
    const int warp = tid >> 5, lane = tid & 31;
    const int g = lane >> 2, tg = lane & 3;
    const int wm = warp >> 1, wn = warp & 1;
    const int bm = blockIdx.y * 128, bn = blockIdx.x * 128;
    const int lt = lane >> 3, lr = lane & 7;

    auto load_stage = [&](int kt) {
        const uint32_t base = sb + (kt & 1) * GSTG;
        const int kofs = kt * 32;
        #pragma unroll
        for (int t = tid; t < 512; t += 256) {
            int r = t >> 2, c = t & 3;
            uint32_t da = base + r * GSTR + c * 16;
            size_t ga = (size_t)(bm + r) * DD + kofs + c * 8;
            size_t gw = (size_t)(bn + r) * DD + kofs + c * 8;
            CP_ASYNC16(da,         j.Ah + ga);
            CP_ASYNC16(da + G_A_L, j.Al + ga);
            uint32_t dw = base + G_W_H + r * GSTR + c * 16;
            CP_ASYNC16(dw,                 j.Wh + gw);
            CP_ASYNC16(dw + (G_W_L-G_W_H), j.Wl + gw);
        }
    };

    float acc[2][8][4];
    #pragma unroll
    for (int mi = 0; mi < 2; mi++)
        #pragma unroll
        for (int ni = 0; ni < 8; ni++)
            #pragma unroll
            for (int q = 0; q < 4; q++) acc[mi][ni][q] = 0.f;

    load_stage(0); CP_COMMIT();
    load_stage(1); CP_COMMIT();

    const int NT = 32;
    for (int kt = 0; kt < NT; kt++) {
        if (kt == NT - 1) { CP_WAIT0(); } else { CP_WAIT1(); }
        __syncthreads();
        const uint32_t base = sb + (kt & 1) * GSTG;

        #pragma unroll
        for (int kc = 0; kc < 2; kc++) {
            uint32_t ah[2][4], al[2][4], bh[4][4], bl[4][4];
            #pragma unroll
            for (int mi = 0; mi < 2; mi++) {
                uint32_t ar = base + (wm*32 + mi*16 + (lt&1)*8 + lr) * GSTR
                            + kc*32 + (lt>>1)*16;
                ldsm4(ah[mi][0], ah[mi][1], ah[mi][2], ah[mi][3], ar);
                ldsm4(al[mi][0], al[mi][1], al[mi][2], al[mi][3], ar + G_A_L);
            }
            #pragma unroll
            for (int ngp = 0; ngp < 4; ngp++) {
                uint32_t br = base + G_W_H + (wn*64 + ngp*16 + (lt>>1)*8 + lr) * GSTR
                            + kc*32 + (lt&1)*16;
                ldsm4(bh[ngp][0], bh[ngp][1], bh[ngp][2], bh[ngp][3], br);
                ldsm4(bl[ngp][0], bl[ngp][1], bl[ngp][2], bl[ngp][3], br + (G_W_L-G_W_H));
            }
            #pragma unroll
            for (int mi = 0; mi < 2; mi++)
                #pragma unroll
                for (int ngp = 0; ngp < 4; ngp++) {
                    mma16816(acc[mi][2*ngp],   ah[mi], bh[ngp][0], bh[ngp][1]);
                    mma16816(acc[mi][2*ngp+1], ah[mi], bh[ngp][2], bh[ngp][3]);
                }
            #pragma unroll
            for (int mi = 0; mi < 2; mi++)
                #pragma unroll
                for (int ngp = 0; ngp < 4; ngp++) {
                    mma16816(acc[mi][2*ngp],   ah[mi], bl[ngp][0], bl[ngp][1]);
                    mma16816(acc[mi][2*ngp+1], ah[mi], bl[ngp][2], bl[ngp][3]);
                }
            #pragma unroll
            for (int mi = 0; mi < 2; mi++)
                #pragma unroll
                for (int ngp = 0; ngp < 4; ngp++) {
                    mma16816(acc[mi][2*ngp],   al[mi], bh[ngp][0], bh[ngp][1]);
                    mma16816(acc[mi][2*ngp+1], al[mi], bh[ngp][2], bh[ngp][3]);
                }
        }
        __syncthreads();
        if (kt + 2 < NT) { load_stage(kt + 2); CP_COMMIT(); }
    }

    #pragma unroll
    for (int mi = 0; mi < 2; mi++) {
        int row = bm + wm*32 + mi*16 + g;
        #pragma unroll
        for (int ni = 0; ni < 8; ni++) {
            int col = bn + wn*64 + ni*8 + tg*2;
            float b0 = j.bias[col], b1 = j.bias[col + 1];
            float v0 = acc[mi][ni][0] + b0, v1 = acc[mi][ni][1] + b1;
            float v2 = acc[mi][ni][2] + b0, v3 = acc[mi][ni][3] + b1;
            if (j.Cf) {
                *reinterpret_cast<float2*>(&j.Cf[(size_t)row * DD + col])     = make_float2(v0, v1);
                *reinterpret_cast<float2*>(&j.Cf[(size_t)(row+8) * DD + col]) = make_float2(v2, v3);
            } else {
                uint32_t h01, l01, h23, l23;
                split2h(v0 * j.scale, v1 * j.scale, h01, l01);
                split2h(v2 * j.scale, v3 * j.scale, h23, l23);
                *reinterpret_cast<uint32_t*>(&j.Chi[(size_t)row * DD + col])     = h01;
                *reinterpret_cast<uint32_t*>(&j.Clo[(size_t)row * DD + col])     = l01;
                *reinterpret_cast<uint32_t*>(&j.Chi[(size_t)(row+8) * DD + col]) = h23;
                *reinterpret_cast<uint32_t*>(&j.Clo[(size_t)(row+8) * DD + col]) = l23;
            }
        }
    }
}

// ---------------- fused attention + recurrence ----------------
#define ASTR 144
#define A_HL 9216
#define A_VH 18432
#define A_VL 27648
#define ASTG 36864
#define ATT_SMEM (2*ASTG)    // 73728

__device__ __forceinline__ void wait_chunk(int bh, int need) {
    if (threadIdx.x == 0) {
        volatile int* p = &g_prog[bh];
        while (*p < need) __nanosleep(64);
        __threadfence();
    }
    __syncthreads();
}

__global__ void __launch_bounds__(128, 3) attn_mma(const float* __restrict__ WhIn) {
    const int tid = threadIdx.x;

    // ======== producer blocks: recurrence -> fp16 hi/lo H ========
    if (blockIdx.x < BB*HH) {
        const int bh = blockIdx.x;
        const int b = bh >> 4, h = bh & 15;
        const int d = tid;
        float w = 0.f, st = 0.f;
        const float* Rp = g_Rp + ((size_t)b * SK) * DD + h * DK + d;
        size_t ho = ((size_t)b * SK) * DD + h * DK + d;
        if (d < DK) {
            const float* wp = WhIn + (size_t)h * DK * DK + (size_t)d * DK;
            #pragma unroll
            for (int k = 0; k < DK; k++) w += wp[k];
        }
        for (int c = 0; c < SK/64; c++) {
            if (d < DK) {
                #pragma unroll 1
                for (int tt = 0; tt < 64; tt += 8) {
                    int t = c*64 + tt;
                    float r[8];
                    #pragma unroll
                    for (int i = 0; i < 8; i++) r[i] = Rp[(size_t)(t + i) * DD];
                    #pragma unroll
                    for (int i = 0; i < 8; i++) {
                        st = tanhf(st * w + r[i]);
                        __half hh = __float2half_rn(st);
                        __half hl = __float2half_rn(st - __half2float(hh));
                        g_Hh[ho + (size_t)(t + i) * DD] = hh;
                        g_Hl[ho + (size_t)(t + i) * DD] = hl;
                    }
                }
            }
            __syncthreads();
            if (tid == 0) { __threadfence(); atomicExch(&g_prog[bh], c + 1); }
        }
        return;
    }

    // ======== consumer blocks: flash attention (fp16 datapath) ========
    const int flat = blockIdx.x - BB*HH;
    const int bh = flat >> 5;
    const int b = bh >> 4, h = bh & 15;
    const int q0 = (flat & 31) * 64;
    const int warp = tid >> 5, lane = tid & 31;
    const int g = lane >> 2, tg = lane & 3;
    const int lt = lane >> 3, lr = lane & 7;

    extern __shared__ __align__(1024) char sm[];
    const uint32_t sb = smem_to_u32(sm);

    const size_t qbase = (size_t)(b * SQ + q0);
    const size_t kbase = (size_t)(b * SK);
    const int hofs = h * DK;

    uint32_t qh[4][4], ql[4][4];
    {
        size_t r0 = (qbase + warp*16 + g) * DD + hofs;
        size_t r1 = r0 + 8 * DD;
        #pragma unroll
        for (int kc = 0; kc < 4; kc++) {
            int c0 = kc*16 + tg*2;
            qh[kc][0] = *reinterpret_cast<const uint32_t*>(g_Qh + r0 + c0);
            qh[kc][1] = *reinterpret_cast<const uint32_t*>(g_Qh + r1 + c0);
            qh[kc][2] = *reinterpret_cast<const uint32_t*>(g_Qh + r0 + c0 + 8);
            qh[kc][3] = *reinterpret_cast<const uint32_t*>(g_Qh + r1 + c0 + 8);
            ql[kc][0] = *reinterpret_cast<const uint32_t*>(g_Ql + r0 + c0);
            ql[kc][1] = *reinterpret_cast<const uint32_t*>(g_Ql + r1 + c0);
            ql[kc][2] = *reinterpret_cast<const uint32_t*>(g_Ql + r0 + c0 + 8);
            ql[kc][3] = *reinterpret_cast<const uint32_t*>(g_Ql + r1 + c0 + 8);
        }
    }

    auto load_stage = [&](int kt) {
        const uint32_t base = sb + (kt & 1) * ASTG;
        const int k0 = kt * 64;
        #pragma unroll
        for (int t = tid; t < 512; t += 128) {
            int r = t >> 3, c = t & 7;
            uint32_t dst = base + r * ASTR + c * 16;
            size_t src = (kbase + k0 + r) * DD + hofs + c * 8;
            CP_ASYNC16(dst,        g_Hh + src);
            CP_ASYNC16(dst + A_HL, g_Hl + src);
            CP_ASYNC16(dst + A_VH, g_Vh + src);
            CP_ASYNC16(dst + A_VL, g_Vl + src);
        }
    };

    wait_chunk(bh, 1);
    load_stage(0); CP_COMMIT();
    wait_chunk(bh, 2);
    load_stage(1); CP_COMMIT();

    float acc[8][4];
    #pragma unroll
    for (int n = 0; n < 8; n++)
        #pragma unroll
        for (int q = 0; q < 4; q++) acc[n][q] = 0.f;
    float mrow0 = -1e30f, mrow1 = -1e30f, lrow0 = 0.f, lrow1 = 0.f;

    const int NT = SK / 64;   // 32
    for (int kt = 0; kt < NT; kt++) {
        if (kt < NT - 1) { CP_WAIT1(); } else { CP_WAIT0(); }
        __syncthreads();
        const uint32_t base = sb + (kt & 1) * ASTG;

        // ---- S = Q . H^T  (fp16 3-pass) ----
        float s[8][4];
        #pragma unroll
        for (int n = 0; n < 8; n++)
            #pragma unroll
            for (int q = 0; q < 4; q++) s[n][q] = 0.f;

        #pragma unroll
        for (int kc = 0; kc < 4; kc++) {
            uint32_t hb[4][4], lb[4][4];
            #pragma unroll
            for (int ngp = 0; ngp < 4; ngp++) {
                uint32_t br = base + (ngp*16 + (lt>>1)*8 + lr) * ASTR + kc*32 + (lt&1)*16;
                ldsm4(hb[ngp][0], hb[ngp][1], hb[ngp][2], hb[ngp][3], br);
                ldsm4(lb[ngp][0], lb[ngp][1], lb[ngp][2], lb[ngp][3], br + A_HL);
            }
            #pragma unroll
            for (int ngp = 0; ngp < 4; ngp++) {
                mma16816h(s[2*ngp],   qh[kc], hb[ngp][0], hb[ngp][1]);
                mma16816h(s[2*ngp+1], qh[kc], hb[ngp][2], hb[ngp][3]);
            }
            #pragma unroll
            for (int ngp = 0; ngp < 4; ngp++) {
                mma16816h(s[2*ngp],   qh[kc], lb[ngp][0], lb[ngp][1]);
                mma16816h(s[2*ngp+1], qh[kc], lb[ngp][2], lb[ngp][3]);
            }
            #pragma unroll
            for (int ngp = 0; ngp < 4; ngp++) {
                mma16816h(s[2*ngp],   ql[kc], hb[ngp][0], hb[ngp][1]);
                mma16816h(s[2*ngp+1], ql[kc], hb[ngp][2], hb[ngp][3]);
            }
        }

        // ---- online softmax (base-2); P -> single fp16 ----
        float tm0 = mrow0, tm1 = mrow1;
        #pragma unroll
        for (int n = 0; n < 8; n++) {
            tm0 = fmaxf(tm0, fmaxf(s[n][0], s[n][1]));
            tm1 = fmaxf(tm1, fmaxf(s[n][2], s[n][3]));
        }
        tm0 = fmaxf(tm0, __shfl_xor_sync(0xffffffffu, tm0, 1));
        tm0 = fmaxf(tm0, __shfl_xor_sync(0xffffffffu, tm0, 2));
        tm1 = fmaxf(tm1, __shfl_xor_sync(0xffffffffu, tm1, 1));
        tm1 = fmaxf(tm1, __shfl_xor_sync(0xffffffffu, tm1, 2));
        float corr0 = ex2f(mrow0 - tm0), corr1 = ex2f(mrow1 - tm1);
        mrow0 = tm0; mrow1 = tm1;
        lrow0 *= corr0; lrow1 *= corr1;

        uint32_t pa[4][4];
        #pragma unroll
        for (int n = 0; n < 8; n++) {
            float p0 = ex2f(s[n][0] - tm0), p1 = ex2f(s[n][1] - tm0);
            float p2 = ex2f(s[n][2] - tm1), p3 = ex2f(s[n][3] - tm1);
            lrow0 += p0 + p1; lrow1 += p2 + p3;
            int kc = n >> 1, hf = (n & 1) * 2;
            pa[kc][hf]     = packh2(p0, p1);
            pa[kc][hf + 1] = packh2(p2, p3);
        }
        #pragma unroll
        for (int n = 0; n < 8; n++) {
            acc[n][0] *= corr0; acc[n][1] *= corr0;
            acc[n][2] *= corr1; acc[n][3] *= corr1;
        }

        // ---- acc += P . V  (fp16 2-pass: P x Vh, P x Vl) ----
        #pragma unroll
        for (int kc = 0; kc < 4; kc++) {
            uint32_t vh[4][4], vl[4][4];
            #pragma unroll
            for (int ndgp = 0; ndgp < 4; ndgp++) {
                uint32_t vr = base + A_VH + (kc*16 + (lt&1)*8 + lr) * ASTR
                            + (ndgp*16 + (lt>>1)*8) * 2;
                ldsm4t(vh[ndgp][0], vh[ndgp][1], vh[ndgp][2], vh[ndgp][3], vr);
                ldsm4t(vl[ndgp][0], vl[ndgp][1], vl[ndgp][2], vl[ndgp][3], vr + (A_VL - A_VH));
            }
            #pragma unroll
            for (int ndgp = 0; ndgp < 4; ndgp++) {
                mma16816h(acc[2*ndgp],   pa[kc], vh[ndgp][0], vh[ndgp][1]);
                mma16816h(acc[2*ndgp+1], pa[kc], vh[ndgp][2], vh[ndgp][3]);
            }
            #pragma unroll
            for (int ndgp = 0; ndgp < 4; ndgp++) {
                mma16816h(acc[2*ndgp],   pa[kc], vl[ndgp][0], vl[ndgp][1]);
                mma16816h(acc[2*ndgp+1], pa[kc], vl[ndgp][2], vl[ndgp][3]);
            }
        }

        __syncthreads();
        if (kt + 2 < NT) {
            wait_chunk(bh, kt + 3);
            load_stage(kt + 2); CP_COMMIT();
        }
    }

    // epilogue: normalize, split to bf16 hi/lo for the Wo GEMM
    lrow0 += __shfl_xor_sync(0xffffffffu, lrow0, 1);
    lrow0 += __shfl_xor_sync(0xffffffffu, lrow0, 2);
    lrow1 += __shfl_xor_sync(0xffffffffu, lrow1, 1);
    lrow1 += __shfl_xor_sync(0xffffffffu, lrow1, 2);
    float inv0 = 1.f / lrow0, inv1 = 1.f / lrow1;
    size_t row = qbase + warp*16 + g;
    #pragma unroll
    for (int nd = 0; nd < 8; nd++) {
        int col = hofs + nd*8 + tg*2;
        uint32_t h01, l01, h23, l23;
        split2(acc[nd][0] * inv0, acc[nd][1] * inv0, h01, l01);
        split2(acc[nd][2] * inv1, acc[nd][3] * inv1, h23, l23);
        *reinterpret_cast<uint32_t*>(&g_Aqh[row * DD + col])       = h01;
        *reinterpret_cast<uint32_t*>(&g_Aql[row * DD + col])       = l01;
        *reinterpret_cast<uint32_t*>(&g_Aqh[(row + 8) * DD + col]) = h23;
        *reinterpret_cast<uint32_t*>(&g_Aql[(row + 8) * DD + col]) = l23;
    }
}

// ---------------- launch ----------------
extern "C" void kernel_launch(void* const* d_in, const int* in_sizes, int n_in,
                              void* d_out, int out_size) {
    const float* query = (const float*)d_in[0];
    // d_in[1] = key : unused by the reference computation
    const float* value = (const float*)d_in[2];
    const float* Rin   = (const float*)d_in[3];
    const float* Wq    = (const float*)d_in[4];
    const float* bq    = (const float*)d_in[5];
    const float* Wv    = (const float*)d_in[6];
    const float* bv    = (const float*)d_in[7];
    const float* Wr    = (const float*)d_in[8];
    const float* br    = (const float*)d_in[9];
    const float* Wh    = (const float*)d_in[10];
    const float* Wo    = (const float*)d_in[11];
    const float* bo    = (const float*)d_in[12];
    float* out = (float*)d_out;

    float* Rp;
    __nv_bfloat16 *Aqh, *Aql, *Avh, *Avl, *Arh, *Arl;
    __nv_bfloat16 *Wqh, *Wql, *Wvh, *Wvl, *Wrh, *Wrl, *Woh, *Wol;
    __half *Qh, *Ql, *Vh, *Vl;
    cudaGetSymbolAddress((void**)&Rp, g_Rp);
    cudaGetSymbolAddress((void**)&Aqh, g_Aqh); cudaGetSymbolAddress((void**)&Aql, g_Aql);
    cudaGetSymbolAddress((void**)&Avh, g_Avh); cudaGetSymbolAddress((void**)&Avl, g_Avl);
    cudaGetSymbolAddress((void**)&Arh, g_Arh); cudaGetSymbolAddress((void**)&Arl, g_Arl);
    cudaGetSymbolAddress((void**)&Wqh, g_Wqh); cudaGetSymbolAddress((void**)&Wql, g_Wql);
    cudaGetSymbolAddress((void**)&Wvh, g_Wvh); cudaGetSymbolAddress((void**)&Wvl, g_Wvl);
    cudaGetSymbolAddress((void**)&Wrh, g_Wrh); cudaGetSymbolAddress((void**)&Wrl, g_Wrl);
    cudaGetSymbolAddress((void**)&Woh, g_Woh); cudaGetSymbolAddress((void**)&Wol, g_Wol);
    cudaGetSymbolAddress((void**)&Qh, g_Qh);   cudaGetSymbolAddress((void**)&Ql, g_Ql);
    cudaGetSymbolAddress((void**)&Vh, g_Vh);   cudaGetSymbolAddress((void**)&Vl, g_Vl);

    cudaFuncSetAttribute(gemm_mma,
                         cudaFuncAttributeMaxDynamicSharedMemorySize, GEMM_SMEM);
    cudaFuncSetAttribute(attn_mma,
                         cudaFuncAttributeMaxDynamicSharedMemorySize, ATT_SMEM);

    const int nA4 = MROWS * DD / 4;
    const int nW4 = DD * DD / 4;

    conv_split4<<<dim3(nA4 / 256, 3), 256>>>(query, value, Rin, query,
                                             Aqh, Aql, Avh, Avl, Arh, Arl, Aqh, Aql, nA4);
    conv_split4<<<dim3(nW4 / 256, 4), 256>>>(Wq, Wv, Wr, Wo,
                                             Wqh, Wql, Wvh, Wvl, Wrh, Wrl, Woh, Wol, nW4);

    GemmJob jq = { Aqh, Aql, Wqh, Wql, bq, nullptr, Qh, Ql, QK_SCALE };
    GemmJob jv = { Avh, Avl, Wvh, Wvl, bv, nullptr, Vh, Vl, 1.0f };
    GemmJob jr = { Arh, Arl, Wrh, Wrl, br, Rp, nullptr, nullptr, 1.0f };
    gemm_mma<<<dim3(DD/128, MROWS/128, 3), 256, GEMM_SMEM>>>(jq, jv, jr);

    attn_mma<<<BB*HH + BB*HH*(SQ/64), 128, ATT_SMEM>>>(Wh);

    GemmJob jo = { Aqh, Aql, Woh, Wol, bo, out, nullptr, nullptr, 1.0f };
    gemm_mma<<<dim3(DD/128, MROWS/128, 1), 256, GEMM_SMEM>>>(jo, jo, jo);
}

// round 16
// speedup vs baseline: 3.2403x; 1.0183x over previous
#include <cuda_runtime.h>
#include <cuda_bf16.h>
#include <cuda_fp16.h>
#include <math.h>
#include <stdint.h>

#define BB 2
#define SQ 2048
#define SK 2048
#define DD 1024
#define HH 16
#define DK 64
#define MROWS (BB*SQ)   // 4096

#define QK_SCALE (0.125f * 1.4426950408889634f)

// ---------------- scratch (device globals; no allocation allowed) ----------------
__device__ float g_Rp[BB*SK*DD];
__device__ int   g_prog[BB*HH];
__device__ __nv_bfloat16 g_Aqh[MROWS*DD], g_Aql[MROWS*DD];   // bf16 A splits / attn out
__device__ __nv_bfloat16 g_Avh[MROWS*DD], g_Avl[MROWS*DD];
__device__ __nv_bfloat16 g_Arh[MROWS*DD], g_Arl[MROWS*DD];
__device__ __nv_bfloat16 g_Wqh[DD*DD], g_Wql[DD*DD];
__device__ __nv_bfloat16 g_Wvh[DD*DD], g_Wvl[DD*DD];
__device__ __nv_bfloat16 g_Wrh[DD*DD], g_Wrl[DD*DD];
__device__ __nv_bfloat16 g_Woh[DD*DD], g_Wol[DD*DD];
// fp16 splits for the attention datapath (V used as single fp16: hi only)
__device__ __half g_Qh[MROWS*DD], g_Ql[MROWS*DD];
__device__ __half g_Vh[MROWS*DD], g_Vl[MROWS*DD];
__device__ __half g_Hh[MROWS*DD], g_Hl[MROWS*DD];

// ---------------- helpers ----------------
__device__ __forceinline__ uint32_t smem_to_u32(const void* p) {
    uint32_t a;
    asm("{ .reg .u64 t; cvta.to.shared.u64 t, %1; cvt.u32.u64 %0, t; }" : "=r"(a) : "l"(p));
    return a;
}
__device__ __forceinline__ float ex2f(float x) {
    float r; asm("ex2.approx.f32 %0, %1;" : "=f"(r) : "f"(x)); return r;
}
__device__ __forceinline__ void ldsm4(uint32_t& r0, uint32_t& r1, uint32_t& r2, uint32_t& r3,
                                      uint32_t addr) {
    asm volatile("ldmatrix.sync.aligned.m8n8.x4.shared.b16 {%0,%1,%2,%3}, [%4];"
        : "=r"(r0), "=r"(r1), "=r"(r2), "=r"(r3) : "r"(addr));
}
__device__ __forceinline__ void ldsm4t(uint32_t& r0, uint32_t& r1, uint32_t& r2, uint32_t& r3,
                                       uint32_t addr) {
    asm volatile("ldmatrix.sync.aligned.m8n8.x4.trans.shared.b16 {%0,%1,%2,%3}, [%4];"
        : "=r"(r0), "=r"(r1), "=r"(r2), "=r"(r3) : "r"(addr));
}
#define CP_ASYNC16(dst, src) \
    asm volatile("cp.async.cg.shared.global [%0], [%1], 16;" :: "r"(dst), "l"(src) : "memory")
#define CP_COMMIT() asm volatile("cp.async.commit_group;" ::: "memory")
#define CP_WAIT1() asm volatile("cp.async.wait_group 1;" ::: "memory")
#define CP_WAIT0() asm volatile("cp.async.wait_group 0;" ::: "memory")

// bf16 mma (GEMMs)
__device__ __forceinline__ void mma16816(float* d, const uint32_t* a, uint32_t b0, uint32_t b1) {
    asm volatile("mma.sync.aligned.m16n8k16.row.col.f32.bf16.bf16.f32 "
        "{%0,%1,%2,%3}, {%4,%5,%6,%7}, {%8,%9}, {%0,%1,%2,%3};"
        : "+f"(d[0]), "+f"(d[1]), "+f"(d[2]), "+f"(d[3])
        : "r"(a[0]), "r"(a[1]), "r"(a[2]), "r"(a[3]), "r"(b0), "r"(b1));
}
// fp16 mma (attention)
__device__ __forceinline__ void mma16816h(float* d, const uint32_t* a, uint32_t b0, uint32_t b1) {
    asm volatile("mma.sync.aligned.m16n8k16.row.col.f32.f16.f16.f32 "
        "{%0,%1,%2,%3}, {%4,%5,%6,%7}, {%8,%9}, {%0,%1,%2,%3};"
        : "+f"(d[0]), "+f"(d[1]), "+f"(d[2]), "+f"(d[3])
        : "r"(a[0]), "r"(a[1]), "r"(a[2]), "r"(a[3]), "r"(b0), "r"(b1));
}

__device__ __forceinline__ void split2(float x, float y, uint32_t& hi, uint32_t& lo) {
    __nv_bfloat16 xh = __float2bfloat16_rn(x), yh = __float2bfloat16_rn(y);
    float xr = x - __bfloat162float(xh), yr = y - __bfloat162float(yh);
    __nv_bfloat16 xl = __float2bfloat16_rn(xr), yl = __float2bfloat16_rn(yr);
    hi = ((uint32_t)__bfloat16_as_ushort(yh) << 16) | __bfloat16_as_ushort(xh);
    lo = ((uint32_t)__bfloat16_as_ushort(yl) << 16) | __bfloat16_as_ushort(xl);
}
__device__ __forceinline__ void split2h(float x, float y, uint32_t& hi, uint32_t& lo) {
    __half xh = __float2half_rn(x), yh = __float2half_rn(y);
    float xr = x - __half2float(xh), yr = y - __half2float(yh);
    __half xl = __float2half_rn(xr), yl = __float2half_rn(yr);
    hi = ((uint32_t)__half_as_ushort(yh) << 16) | __half_as_ushort(xh);
    lo = ((uint32_t)__half_as_ushort(yl) << 16) | __half_as_ushort(xl);
}
__device__ __forceinline__ uint32_t packh2(float x, float y) {
    uint32_t r; asm("cvt.rn.f16x2.f32 %0, %1, %2;" : "=r"(r) : "f"(y), "f"(x)); return r;
}

// ---------------- batched f32 -> bf16 hi/lo split (also resets g_prog) ----------------
__global__ void conv_split4(const float* i0, const float* i1, const float* i2, const float* i3,
                            __nv_bfloat16* h0, __nv_bfloat16* l0,
                            __nv_bfloat16* h1, __nv_bfloat16* l1,
                            __nv_bfloat16* h2, __nv_bfloat16* l2,
                            __nv_bfloat16* h3, __nv_bfloat16* l3, int n4) {
    if (blockIdx.x == 0 && blockIdx.y == 0 && threadIdx.x < BB*HH)
        g_prog[threadIdx.x] = 0;
    int i = blockIdx.x * blockDim.x + threadIdx.x;
    if (i >= n4) return;
    const float* in; __nv_bfloat16 *hi, *lo;
    switch (blockIdx.y) {
        case 0: in = i0; hi = h0; lo = l0; break;
        case 1: in = i1; hi = h1; lo = l1; break;
        case 2: in = i2; hi = h2; lo = l2; break;
        default: in = i3; hi = h3; lo = l3; break;
    }
    float4 v = reinterpret_cast<const float4*>(in)[i];
    uint32_t a0, b0, a1, b1;
    split2(v.x, v.y, a0, b0);
    split2(v.z, v.w, a1, b1);
    reinterpret_cast<uint2*>(hi)[i] = make_uint2(a0, a1);
    reinterpret_cast<uint2*>(lo)[i] = make_uint2(b0, b1);
}

// ---------------- mma.sync GEMM, batched over grid.z ----------------
struct GemmJob {
    const __nv_bfloat16 *Ah, *Al, *Wh, *Wl;
    const float* bias;
    float* Cf;
    __half *Chi, *Clo;
    float scale;
};

#define GSTR 80
#define G_A_L 10240
#define G_W_H 20480
#define G_W_L 30720
#define GSTG 40960
#define GEMM_SMEM (2*GSTG)   // 81920

__global__ void __launch_bounds__(256, 2) gemm_mma(GemmJob j0, GemmJob j1, GemmJob j2)
{
    const GemmJob j = (blockIdx.z == 0) ? j0 : (blockIdx.z == 1) ? j1 : j2;
    extern __shared__ __align__(1024) char sm[];
    const uint32_t sb = smem_to_u32(sm);
    const int tid = threadIdx.x;
    const int warp = tid >> 5, lane = tid & 31;
    const int g = lane >> 2, tg = lane & 3;
    const int wm = warp >> 1, wn = warp & 1;
    const int bm = blockIdx.y * 128, bn = blockIdx.x * 128;
    const int lt = lane >> 3, lr = lane & 7;

    auto load_stage = [&](int kt) {
        const uint32_t base = sb + (kt & 1) * GSTG;
        const int kofs = kt * 32;
        #pragma unroll
        for (int t = tid; t < 512; t += 256) {
            int r = t >> 2, c = t & 3;
            uint32_t da = base + r * GSTR + c * 16;
            size_t ga = (size_t)(bm + r) * DD + kofs + c * 8;
            size_t gw = (size_t)(bn + r) * DD + kofs + c * 8;
            CP_ASYNC16(da,         j.Ah + ga);
            CP_ASYNC16(da + G_A_L, j.Al + ga);
            uint32_t dw = base + G_W_H + r * GSTR + c * 16;
            CP_ASYNC16(dw,                 j.Wh + gw);
            CP_ASYNC16(dw + (G_W_L-G_W_H), j.Wl + gw);
        }
    };

    float acc[2][8][4];
    #pragma unroll
    for (int mi = 0; mi < 2; mi++)
        #pragma unroll
        for (int ni = 0; ni < 8; ni++)
            #pragma unroll
            for (int q = 0; q < 4; q++) acc[mi][ni][q] = 0.f;

    load_stage(0); CP_COMMIT();
    load_stage(1); CP_COMMIT();

    const int NT = 32;
    for (int kt = 0; kt < NT; kt++) {
        if (kt == NT - 1) { CP_WAIT0(); } else { CP_WAIT1(); }
        __syncthreads();
        const uint32_t base = sb + (kt & 1) * GSTG;

        #pragma unroll
        for (int kc = 0; kc < 2; kc++) {
            uint32_t ah[2][4], al[2][4], bh[4][4], bl[4][4];
            #pragma unroll
            for (int mi = 0; mi < 2; mi++) {
                uint32_t ar = base + (wm*32 + mi*16 + (lt&1)*8 + lr) * GSTR
                            + kc*32 + (lt>>1)*16;
                ldsm4(ah[mi][0], ah[mi][1], ah[mi][2], ah[mi][3], ar);
                ldsm4(al[mi][0], al[mi][1], al[mi][2], al[mi][3], ar + G_A_L);
            }
            #pragma unroll
            for (int ngp = 0; ngp < 4; ngp++) {
                uint32_t br = base + G_W_H + (wn*64 + ngp*16 + (lt>>1)*8 + lr) * GSTR
                            + kc*32 + (lt&1)*16;
                ldsm4(bh[ngp][0], bh[ngp][1], bh[ngp][2], bh[ngp][3], br);
                ldsm4(bl[ngp][0], bl[ngp][1], bl[ngp][2], bl[ngp][3], br + (G_W_L-G_W_H));
            }
            #pragma unroll
            for (int mi = 0; mi < 2; mi++)
                #pragma unroll
                for (int ngp = 0; ngp < 4; ngp++) {
                    mma16816(acc[mi][2*ngp],   ah[mi], bh[ngp][0], bh[ngp][1]);
                    mma16816(acc[mi][2*ngp+1], ah[mi], bh[ngp][2], bh[ngp][3]);
                }
            #pragma unroll
            for (int mi = 0; mi < 2; mi++)
                #pragma unroll
                for (int ngp = 0; ngp < 4; ngp++) {
                    mma16816(acc[mi][2*ngp],   ah[mi], bl[ngp][0], bl[ngp][1]);
                    mma16816(acc[mi][2*ngp+1], ah[mi], bl[ngp][2], bl[ngp][3]);
                }
            #pragma unroll
            for (int mi = 0; mi < 2; mi++)
                #pragma unroll
                for (int ngp = 0; ngp < 4; ngp++) {
                    mma16816(acc[mi][2*ngp],   al[mi], bh[ngp][0], bh[ngp][1]);
                    mma16816(acc[mi][2*ngp+1], al[mi], bh[ngp][2], bh[ngp][3]);
                }
        }
        __syncthreads();
        if (kt + 2 < NT) { load_stage(kt + 2); CP_COMMIT(); }
    }

    #pragma unroll
    for (int mi = 0; mi < 2; mi++) {
        int row = bm + wm*32 + mi*16 + g;
        #pragma unroll
        for (int ni = 0; ni < 8; ni++) {
            int col = bn + wn*64 + ni*8 + tg*2;
            float b0 = j.bias[col], b1 = j.bias[col + 1];
            float v0 = acc[mi][ni][0] + b0, v1 = acc[mi][ni][1] + b1;
            float v2 = acc[mi][ni][2] + b0, v3 = acc[mi][ni][3] + b1;
            if (j.Cf) {
                *reinterpret_cast<float2*>(&j.Cf[(size_t)row * DD + col])     = make_float2(v0, v1);
                *reinterpret_cast<float2*>(&j.Cf[(size_t)(row+8) * DD + col]) = make_float2(v2, v3);
            } else {
                uint32_t h01, l01, h23, l23;
                split2h(v0 * j.scale, v1 * j.scale, h01, l01);
                split2h(v2 * j.scale, v3 * j.scale, h23, l23);
                *reinterpret_cast<uint32_t*>(&j.Chi[(size_t)row * DD + col])     = h01;
                *reinterpret_cast<uint32_t*>(&j.Clo[(size_t)row * DD + col])     = l01;
                *reinterpret_cast<uint32_t*>(&j.Chi[(size_t)(row+8) * DD + col]) = h23;
                *reinterpret_cast<uint32_t*>(&j.Clo[(size_t)(row+8) * DD + col]) = l23;
            }
        }
    }
}

// ---------------- fused attention + recurrence ----------------
// H double-buffered (hi+lo), V triple-buffered (single fp16).
// Deferred-PV pipeline: iter kt does S(kt), PV(kt-1), softmax(kt).
#define ASTR 144
#define A_HL 9216
#define AH_STG 18432             // per H stage (Hh + Hl)
#define AV_BASE (2*AH_STG)       // 36864
#define AV_STG 9216
#define ATT_SMEM (AV_BASE + 3*AV_STG)   // 64512

__device__ __forceinline__ void wait_chunk(int bh, int need) {
    if (threadIdx.x == 0) {
        volatile int* p = &g_prog[bh];
        while (*p < need) __nanosleep(64);
        __threadfence();
    }
    __syncthreads();
}

__global__ void __launch_bounds__(128, 3) attn_mma(const float* __restrict__ WhIn) {
    const int tid = threadIdx.x;

    // ======== producer blocks: recurrence -> fp16 hi/lo H ========
    if (blockIdx.x < BB*HH) {
        const int bh = blockIdx.x;
        const int b = bh >> 4, h = bh & 15;
        const int d = tid;
        float w = 0.f, st = 0.f;
        const float* Rp = g_Rp + ((size_t)b * SK) * DD + h * DK + d;
        size_t ho = ((size_t)b * SK) * DD + h * DK + d;
        if (d < DK) {
            const float* wp = WhIn + (size_t)h * DK * DK + (size_t)d * DK;
            #pragma unroll
            for (int k = 0; k < DK; k++) w += wp[k];
        }
        for (int c = 0; c < SK/64; c++) {
            if (d < DK) {
                #pragma unroll 1
                for (int tt = 0; tt < 64; tt += 8) {
                    int t = c*64 + tt;
                    float r[8];
                    #pragma unroll
                    for (int i = 0; i < 8; i++) r[i] = Rp[(size_t)(t + i) * DD];
                    #pragma unroll
                    for (int i = 0; i < 8; i++) {
                        st = tanhf(st * w + r[i]);
                        __half hh = __float2half_rn(st);
                        __half hl = __float2half_rn(st - __half2float(hh));
                        g_Hh[ho + (size_t)(t + i) * DD] = hh;
                        g_Hl[ho + (size_t)(t + i) * DD] = hl;
                    }
                }
            }
            __syncthreads();
            if (tid == 0) { __threadfence(); atomicExch(&g_prog[bh], c + 1); }
        }
        return;
    }

    // ======== consumer blocks: flash attention ========
    const int flat = blockIdx.x - BB*HH;
    const int bh = flat >> 5;
    const int b = bh >> 4, h = bh & 15;
    const int q0 = (flat & 31) * 64;
    const int warp = tid >> 5, lane = tid & 31;
    const int g = lane >> 2, tg = lane & 3;
    const int lt = lane >> 3, lr = lane & 7;

    extern __shared__ __align__(1024) char sm[];
    const uint32_t sb = smem_to_u32(sm);

    const size_t qbase = (size_t)(b * SQ + q0);
    const size_t kbase = (size_t)(b * SK);
    const int hofs = h * DK;

    uint32_t qh[4][4], ql[4][4];
    {
        size_t r0 = (qbase + warp*16 + g) * DD + hofs;
        size_t r1 = r0 + 8 * DD;
        #pragma unroll
        for (int kc = 0; kc < 4; kc++) {
            int c0 = kc*16 + tg*2;
            qh[kc][0] = *reinterpret_cast<const uint32_t*>(g_Qh + r0 + c0);
            qh[kc][1] = *reinterpret_cast<const uint32_t*>(g_Qh + r1 + c0);
            qh[kc][2] = *reinterpret_cast<const uint32_t*>(g_Qh + r0 + c0 + 8);
            qh[kc][3] = *reinterpret_cast<const uint32_t*>(g_Qh + r1 + c0 + 8);
            ql[kc][0] = *reinterpret_cast<const uint32_t*>(g_Ql + r0 + c0);
            ql[kc][1] = *reinterpret_cast<const uint32_t*>(g_Ql + r1 + c0);
            ql[kc][2] = *reinterpret_cast<const uint32_t*>(g_Ql + r0 + c0 + 8);
            ql[kc][3] = *reinterpret_cast<const uint32_t*>(g_Ql + r1 + c0 + 8);
        }
    }

    auto load_stage = [&](int kt) {
        const uint32_t hb = sb + (kt & 1) * AH_STG;
        const uint32_t vb = sb + AV_BASE + (kt % 3) * AV_STG;
        const int k0 = kt * 64;
        #pragma unroll
        for (int t = tid; t < 512; t += 128) {
            int r = t >> 3, c = t & 7;
            uint32_t ro = r * ASTR + c * 16;
            size_t src = (kbase + k0 + r) * DD + hofs + c * 8;
            CP_ASYNC16(hb + ro,        g_Hh + src);
            CP_ASYNC16(hb + ro + A_HL, g_Hl + src);
            CP_ASYNC16(vb + ro,        g_Vh + src);
        }
    };

    wait_chunk(bh, 1);
    load_stage(0); CP_COMMIT();
    wait_chunk(bh, 2);
    load_stage(1); CP_COMMIT();

    float acc[8][4];
    #pragma unroll
    for (int n = 0; n < 8; n++)
        #pragma unroll
        for (int q = 0; q < 4; q++) acc[n][q] = 0.f;
    float mrow0 = -1e30f, mrow1 = -1e30f, lrow0 = 0.f, lrow1 = 0.f;
    uint32_t pa[4][4];   // P fragments of PREVIOUS iteration (fp16)

    // deferred PV body (reads V stage vs with fragments pa)
    auto pv_pass = [&](uint32_t vbase) {
        #pragma unroll
        for (int kc = 0; kc < 4; kc++) {
            uint32_t vh[4][4];
            #pragma unroll
            for (int ndgp = 0; ndgp < 4; ndgp++) {
                uint32_t vr = vbase + (kc*16 + (lt&1)*8 + lr) * ASTR
                            + (ndgp*16 + (lt>>1)*8) * 2;
                ldsm4t(vh[ndgp][0], vh[ndgp][1], vh[ndgp][2], vh[ndgp][3], vr);
            }
            #pragma unroll
            for (int ndgp = 0; ndgp < 4; ndgp++) {
                mma16816h(acc[2*ndgp],   pa[kc], vh[ndgp][0], vh[ndgp][1]);
                mma16816h(acc[2*ndgp+1], pa[kc], vh[ndgp][2], vh[ndgp][3]);
            }
        }
    };

    const int NT = SK / 64;   // 32
    for (int kt = 0; kt < NT; kt++) {
        if (kt < NT - 1) { CP_WAIT1(); } else { CP_WAIT0(); }
        __syncthreads();
        const uint32_t hbase = sb + (kt & 1) * AH_STG;

        // ---- S = Q . H^T  (fp16 3-pass) ----
        float s[8][4];
        #pragma unroll
        for (int n = 0; n < 8; n++)
            #pragma unroll
            for (int q = 0; q < 4; q++) s[n][q] = 0.f;

        #pragma unroll
        for (int kc = 0; kc < 4; kc++) {
            uint32_t hb[4][4], lb[4][4];
            #pragma unroll
            for (int ngp = 0; ngp < 4; ngp++) {
                uint32_t br = hbase + (ngp*16 + (lt>>1)*8 + lr) * ASTR + kc*32 + (lt&1)*16;
                ldsm4(hb[ngp][0], hb[ngp][1], hb[ngp][2], hb[ngp][3], br);
                ldsm4(lb[ngp][0], lb[ngp][1], lb[ngp][2], lb[ngp][3], br + A_HL);
            }
            #pragma unroll
            for (int ngp = 0; ngp < 4; ngp++) {
                mma16816h(s[2*ngp],   qh[kc], hb[ngp][0], hb[ngp][1]);
                mma16816h(s[2*ngp+1], qh[kc], hb[ngp][2], hb[ngp][3]);
            }
            #pragma unroll
            for (int ngp = 0; ngp < 4; ngp++) {
                mma16816h(s[2*ngp],   qh[kc], lb[ngp][0], lb[ngp][1]);
                mma16816h(s[2*ngp+1], qh[kc], lb[ngp][2], lb[ngp][3]);
            }
            #pragma unroll
            for (int ngp = 0; ngp < 4; ngp++) {
                mma16816h(s[2*ngp],   ql[kc], hb[ngp][0], hb[ngp][1]);
                mma16816h(s[2*ngp+1], ql[kc], hb[ngp][2], hb[ngp][3]);
            }
        }

        // ---- deferred PV(kt-1): V stage (kt-1)%3 == (kt+2)%3 ----
        if (kt > 0) pv_pass(sb + AV_BASE + ((kt + 2) % 3) * AV_STG);

        // ---- online softmax (base-2): rescale acc AFTER the deferred PV ----
        float tm0 = mrow0, tm1 = mrow1;
        #pragma unroll
        for (int n = 0; n < 8; n++) {
            tm0 = fmaxf(tm0, fmaxf(s[n][0], s[n][1]));
            tm1 = fmaxf(tm1, fmaxf(s[n][2], s[n][3]));
        }
        tm0 = fmaxf(tm0, __shfl_xor_sync(0xffffffffu, tm0, 1));
        tm0 = fmaxf(tm0, __shfl_xor_sync(0xffffffffu, tm0, 2));
        tm1 = fmaxf(tm1, __shfl_xor_sync(0xffffffffu, tm1, 1));
        tm1 = fmaxf(tm1, __shfl_xor_sync(0xffffffffu, tm1, 2));
        float corr0 = ex2f(mrow0 - tm0), corr1 = ex2f(mrow1 - tm1);
        mrow0 = tm0; mrow1 = tm1;
        lrow0 *= corr0; lrow1 *= corr1;

        #pragma unroll
        for (int n = 0; n < 8; n++) {
            float p0 = ex2f(s[n][0] - tm0), p1 = ex2f(s[n][1] - tm0);
            float p2 = ex2f(s[n][2] - tm1), p3 = ex2f(s[n][3] - tm1);
            lrow0 += p0 + p1; lrow1 += p2 + p3;
            int kc = n >> 1, hf = (n & 1) * 2;
            pa[kc][hf]     = packh2(p0, p1);
            pa[kc][hf + 1] = packh2(p2, p3);
        }
        #pragma unroll
        for (int n = 0; n < 8; n++) {
            acc[n][0] *= corr0; acc[n][1] *= corr0;
            acc[n][2] *= corr1; acc[n][3] *= corr1;
        }

        __syncthreads();
        if (kt + 2 < NT) {
            wait_chunk(bh, kt + 3);
            load_stage(kt + 2); CP_COMMIT();
        }
    }

    // final PV(NT-1): V stage (NT-1)%3 still resident
    pv_pass(sb + AV_BASE + ((NT - 1) % 3) * AV_STG);

    // epilogue: normalize, split to bf16 hi/lo for the Wo GEMM
    lrow0 += __shfl_xor_sync(0xffffffffu, lrow0, 1);
    lrow0 += __shfl_xor_sync(0xffffffffu, lrow0, 2);
    lrow1 += __shfl_xor_sync(0xffffffffu, lrow1, 1);
    lrow1 += __shfl_xor_sync(0xffffffffu, lrow1, 2);
    float inv0 = 1.f / lrow0, inv1 = 1.f / lrow1;
    size_t row = qbase + warp*16 + g;
    #pragma unroll
    for (int nd = 0; nd < 8; nd++) {
        int col = hofs + nd*8 + tg*2;
        uint32_t h01, l01, h23, l23;
        split2(acc[nd][0] * inv0, acc[nd][1] * inv0, h01, l01);
        split2(acc[nd][2] * inv1, acc[nd][3] * inv1, h23, l23);
        *reinterpret_cast<uint32_t*>(&g_Aqh[row * DD + col])       = h01;
        *reinterpret_cast<uint32_t*>(&g_Aql[row * DD + col])       = l01;
        *reinterpret_cast<uint32_t*>(&g_Aqh[(row + 8) * DD + col]) = h23;
        *reinterpret_cast<uint32_t*>(&g_Aql[(row + 8) * DD + col]) = l23;
    }
}

// ---------------- launch ----------------
extern "C" void kernel_launch(void* const* d_in, const int* in_sizes, int n_in,
                              void* d_out, int out_size) {
    const float* query = (const float*)d_in[0];
    // d_in[1] = key : unused by the reference computation
    const float* value = (const float*)d_in[2];
    const float* Rin   = (const float*)d_in[3];
    const float* Wq    = (const float*)d_in[4];
    const float* bq    = (const float*)d_in[5];
    const float* Wv    = (const float*)d_in[6];
    const float* bv    = (const float*)d_in[7];
    const float* Wr    = (const float*)d_in[8];
    const float* br    = (const float*)d_in[9];
    const float* Wh    = (const float*)d_in[10];
    const float* Wo    = (const float*)d_in[11];
    const float* bo    = (const float*)d_in[12];
    float* out = (float*)d_out;

    float* Rp;
    __nv_bfloat16 *Aqh, *Aql, *Avh, *Avl, *Arh, *Arl;
    __nv_bfloat16 *Wqh, *Wql, *Wvh, *Wvl, *Wrh, *Wrl, *Woh, *Wol;
    __half *Qh, *Ql, *Vh, *Vl;
    cudaGetSymbolAddress((void**)&Rp, g_Rp);
    cudaGetSymbolAddress((void**)&Aqh, g_Aqh); cudaGetSymbolAddress((void**)&Aql, g_Aql);
    cudaGetSymbolAddress((void**)&Avh, g_Avh); cudaGetSymbolAddress((void**)&Avl, g_Avl);
    cudaGetSymbolAddress((void**)&Arh, g_Arh); cudaGetSymbolAddress((void**)&Arl, g_Arl);
    cudaGetSymbolAddress((void**)&Wqh, g_Wqh); cudaGetSymbolAddress((void**)&Wql, g_Wql);
    cudaGetSymbolAddress((void**)&Wvh, g_Wvh); cudaGetSymbolAddress((void**)&Wvl, g_Wvl);
    cudaGetSymbolAddress((void**)&Wrh, g_Wrh); cudaGetSymbolAddress((void**)&Wrl, g_Wrl);
    cudaGetSymbolAddress((void**)&Woh, g_Woh); cudaGetSymbolAddress((void**)&Wol, g_Wol);
    cudaGetSymbolAddress((void**)&Qh, g_Qh);   cudaGetSymbolAddress((void**)&Ql, g_Ql);
    cudaGetSymbolAddress((void**)&Vh, g_Vh);   cudaGetSymbolAddress((void**)&Vl, g_Vl);

    cudaFuncSetAttribute(gemm_mma,
                         cudaFuncAttributeMaxDynamicSharedMemorySize, GEMM_SMEM);
    cudaFuncSetAttribute(attn_mma,
                         cudaFuncAttributeMaxDynamicSharedMemorySize, ATT_SMEM);

    const int nA4 = MROWS * DD / 4;
    const int nW4 = DD * DD / 4;

    conv_split4<<<dim3(nA4 / 256, 3), 256>>>(query, value, Rin, query,
                                             Aqh, Aql, Avh, Avl, Arh, Arl, Aqh, Aql, nA4);
    conv_split4<<<dim3(nW4 / 256, 4), 256>>>(Wq, Wv, Wr, Wo,
                                             Wqh, Wql, Wvh, Wvl, Wrh, Wrl, Woh, Wol, nW4);

    GemmJob jq = { Aqh, Aql, Wqh, Wql, bq, nullptr, Qh, Ql, QK_SCALE };
    GemmJob jv = { Avh, Avl, Wvh, Wvl, bv, nullptr, Vh, Vl, 1.0f };
    GemmJob jr = { Arh, Arl, Wrh, Wrl, br, Rp, nullptr, nullptr, 1.0f };
    gemm_mma<<<dim3(DD/128, MROWS/128, 3), 256, GEMM_SMEM>>>(jq, jv, jr);

    attn_mma<<<BB*HH + BB*HH*(SQ/64), 128, ATT_SMEM>>>(Wh);

    GemmJob jo = { Aqh, Aql, Woh, Wol, bo, out, nullptr, nullptr, 1.0f };
    gemm_mma<<<dim3(DD/128, MROWS/128, 1), 256, GEMM_SMEM>>>(jo, jo, jo);
}

// round 17
// speedup vs baseline: 3.6175x; 1.1164x over previous
#include <cuda_runtime.h>
#include <cuda_bf16.h>
#include <cuda_fp16.h>
#include <math.h>
#include <stdint.h>

#define BB 2
#define SQ 2048
#define SK 2048
#define DD 1024
#define HH 16
#define DK 64
#define MROWS (BB*SQ)   // 4096

#define QK_SCALE (0.125f * 1.4426950408889634f)

// ---------------- scratch (device globals; no allocation allowed) ----------------
__device__ float g_Rp[BB*SK*DD];
__device__ int   g_prog[BB*HH];
__device__ __nv_bfloat16 g_Aqh[MROWS*DD], g_Aql[MROWS*DD];   // bf16 A splits / attn out
__device__ __nv_bfloat16 g_Avh[MROWS*DD], g_Avl[MROWS*DD];
__device__ __nv_bfloat16 g_Arh[MROWS*DD], g_Arl[MROWS*DD];
__device__ __nv_bfloat16 g_Wqh[DD*DD], g_Wql[DD*DD];
__device__ __nv_bfloat16 g_Wvh[DD*DD], g_Wvl[DD*DD];
__device__ __nv_bfloat16 g_Wrh[DD*DD], g_Wrl[DD*DD];
__device__ __nv_bfloat16 g_Woh[DD*DD], g_Wol[DD*DD];
// fp16 operands for the attention datapath (Q and V single fp16; H hi/lo)
__device__ __half g_Qh[MROWS*DD], g_Ql[MROWS*DD];
__device__ __half g_Vh[MROWS*DD], g_Vl[MROWS*DD];
__device__ __half g_Hh[MROWS*DD], g_Hl[MROWS*DD];

// ---------------- helpers ----------------
__device__ __forceinline__ uint32_t smem_to_u32(const void* p) {
    uint32_t a;
    asm("{ .reg .u64 t; cvta.to.shared.u64 t, %1; cvt.u32.u64 %0, t; }" : "=r"(a) : "l"(p));
    return a;
}
__device__ __forceinline__ float ex2f(float x) {
    float r; asm("ex2.approx.f32 %0, %1;" : "=f"(r) : "f"(x)); return r;
}
__device__ __forceinline__ void ldsm4(uint32_t& r0, uint32_t& r1, uint32_t& r2, uint32_t& r3,
                                      uint32_t addr) {
    asm volatile("ldmatrix.sync.aligned.m8n8.x4.shared.b16 {%0,%1,%2,%3}, [%4];"
        : "=r"(r0), "=r"(r1), "=r"(r2), "=r"(r3) : "r"(addr));
}
__device__ __forceinline__ void ldsm4t(uint32_t& r0, uint32_t& r1, uint32_t& r2, uint32_t& r3,
                                       uint32_t addr) {
    asm volatile("ldmatrix.sync.aligned.m8n8.x4.trans.shared.b16 {%0,%1,%2,%3}, [%4];"
        : "=r"(r0), "=r"(r1), "=r"(r2), "=r"(r3) : "r"(addr));
}
#define CP_ASYNC16(dst, src) \
    asm volatile("cp.async.cg.shared.global [%0], [%1], 16;" :: "r"(dst), "l"(src) : "memory")
#define CP_COMMIT() asm volatile("cp.async.commit_group;" ::: "memory")
#define CP_WAIT1() asm volatile("cp.async.wait_group 1;" ::: "memory")
#define CP_WAIT0() asm volatile("cp.async.wait_group 0;" ::: "memory")

// bf16 mma (GEMMs)
__device__ __forceinline__ void mma16816(float* d, const uint32_t* a, uint32_t b0, uint32_t b1) {
    asm volatile("mma.sync.aligned.m16n8k16.row.col.f32.bf16.bf16.f32 "
        "{%0,%1,%2,%3}, {%4,%5,%6,%7}, {%8,%9}, {%0,%1,%2,%3};"
        : "+f"(d[0]), "+f"(d[1]), "+f"(d[2]), "+f"(d[3])
        : "r"(a[0]), "r"(a[1]), "r"(a[2]), "r"(a[3]), "r"(b0), "r"(b1));
}
// fp16 mma (attention)
__device__ __forceinline__ void mma16816h(float* d, const uint32_t* a, uint32_t b0, uint32_t b1) {
    asm volatile("mma.sync.aligned.m16n8k16.row.col.f32.f16.f16.f32 "
        "{%0,%1,%2,%3}, {%4,%5,%6,%7}, {%8,%9}, {%0,%1,%2,%3};"
        : "+f"(d[0]), "+f"(d[1]), "+f"(d[2]), "+f"(d[3])
        : "r"(a[0]), "r"(a[1]), "r"(a[2]), "r"(a[3]), "r"(b0), "r"(b1));
}

__device__ __forceinline__ void split2(float x, float y, uint32_t& hi, uint32_t& lo) {
    __nv_bfloat16 xh = __float2bfloat16_rn(x), yh = __float2bfloat16_rn(y);
    float xr = x - __bfloat162float(xh), yr = y - __bfloat162float(yh);
    __nv_bfloat16 xl = __float2bfloat16_rn(xr), yl = __float2bfloat16_rn(yr);
    hi = ((uint32_t)__bfloat16_as_ushort(yh) << 16) | __bfloat16_as_ushort(xh);
    lo = ((uint32_t)__bfloat16_as_ushort(yl) << 16) | __bfloat16_as_ushort(xl);
}
__device__ __forceinline__ void split2h(float x, float y, uint32_t& hi, uint32_t& lo) {
    __half xh = __float2half_rn(x), yh = __float2half_rn(y);
    float xr = x - __half2float(xh), yr = y - __half2float(yh);
    __half xl = __float2half_rn(xr), yl = __float2half_rn(yr);
    hi = ((uint32_t)__half_as_ushort(yh) << 16) | __half_as_ushort(xh);
    lo = ((uint32_t)__half_as_ushort(yl) << 16) | __half_as_ushort(xl);
}
__device__ __forceinline__ uint32_t packh2(float x, float y) {
    uint32_t r; asm("cvt.rn.f16x2.f32 %0, %1, %2;" : "=r"(r) : "f"(y), "f"(x)); return r;
}

// ---------------- batched f32 -> bf16 hi/lo split (also resets g_prog) ----------------
__global__ void conv_split4(const float* i0, const float* i1, const float* i2, const float* i3,
                            __nv_bfloat16* h0, __nv_bfloat16* l0,
                            __nv_bfloat16* h1, __nv_bfloat16* l1,
                            __nv_bfloat16* h2, __nv_bfloat16* l2,
                            __nv_bfloat16* h3, __nv_bfloat16* l3, int n4) {
    if (blockIdx.x == 0 && blockIdx.y == 0 && threadIdx.x < BB*HH)
        g_prog[threadIdx.x] = 0;
    int i = blockIdx.x * blockDim.x + threadIdx.x;
    if (i >= n4) return;
    const float* in; __nv_bfloat16 *hi, *lo;
    switch (blockIdx.y) {
        case 0: in = i0; hi = h0; lo = l0; break;
        case 1: in = i1; hi = h1; lo = l1; break;
        case 2: in = i2; hi = h2; lo = l2; break;
        default: in = i3; hi = h3; lo = l3; break;
    }
    float4 v = reinterpret_cast<const float4*>(in)[i];
    uint32_t a0, b0, a1, b1;
    split2(v.x, v.y, a0, b0);
    split2(v.z, v.w, a1, b1);
    reinterpret_cast<uint2*>(hi)[i] = make_uint2(a0, a1);
    reinterpret_cast<uint2*>(lo)[i] = make_uint2(b0, b1);
}

// ---------------- mma.sync GEMM, batched over grid.z ----------------
struct GemmJob {
    const __nv_bfloat16 *Ah, *Al, *Wh, *Wl;
    const float* bias;
    float* Cf;
    __half *Chi, *Clo;
    float scale;
};

#define GSTR 80
#define G_A_L 10240
#define G_W_H 20480
#define G_W_L 30720
#define GSTG 40960
#define GEMM_SMEM (2*GSTG)   // 81920

__global__ void __launch_bounds__(256, 2) gemm_mma(GemmJob j0, GemmJob j1, GemmJob j2)
{
    const GemmJob j = (blockIdx.z == 0) ? j0 : (blockIdx.z == 1) ? j1 : j2;
    extern __shared__ __align__(1024) char sm[];
    const uint32_t sb = smem_to_u32(sm);
    const int tid = threadIdx.x;
    const int warp = tid >> 5, lane = tid & 31;
    const int g = lane >> 2, tg = lane & 3;
    const int wm = warp >> 1, wn = warp & 1;
    const int bm = blockIdx.y * 128, bn = blockIdx.x * 128;
    const int lt = lane >> 3, lr = lane & 7;

    auto load_stage = [&](int kt) {
        const uint32_t base = sb + (kt & 1) * GSTG;
        const int kofs = kt * 32;
        #pragma unroll
        for (int t = tid; t < 512; t += 256) {
            int r = t >> 2, c = t & 3;
            uint32_t da = base + r * GSTR + c * 16;
            size_t ga = (size_t)(bm + r) * DD + kofs + c * 8;
            size_t gw = (size_t)(bn + r) * DD + kofs + c * 8;
            CP_ASYNC16(da,         j.Ah + ga);
            CP_ASYNC16(da + G_A_L, j.Al + ga);
            uint32_t dw = base + G_W_H + r * GSTR + c * 16;
            CP_ASYNC16(dw,                 j.Wh + gw);
            CP_ASYNC16(dw + (G_W_L-G_W_H), j.Wl + gw);
        }
    };

    float acc[2][8][4];
    #pragma unroll
    for (int mi = 0; mi < 2; mi++)
        #pragma unroll
        for (int ni = 0; ni < 8; ni++)
            #pragma unroll
            for (int q = 0; q < 4; q++) acc[mi][ni][q] = 0.f;

    load_stage(0); CP_COMMIT();
    load_stage(1); CP_COMMIT();

    const int NT = 32;
    for (int kt = 0; kt < NT; kt++) {
        if (kt == NT - 1) { CP_WAIT0(); } else { CP_WAIT1(); }
        __syncthreads();
        const uint32_t base = sb + (kt & 1) * GSTG;

        #pragma unroll
        for (int kc = 0; kc < 2; kc++) {
            uint32_t ah[2][4], al[2][4], bh[4][4], bl[4][4];
            #pragma unroll
            for (int mi = 0; mi < 2; mi++) {
                uint32_t ar = base + (wm*32 + mi*16 + (lt&1)*8 + lr) * GSTR
                            + kc*32 + (lt>>1)*16;
                ldsm4(ah[mi][0], ah[mi][1], ah[mi][2], ah[mi][3], ar);
                ldsm4(al[mi][0], al[mi][1], al[mi][2], al[mi][3], ar + G_A_L);
            }
            #pragma unroll
            for (int ngp = 0; ngp < 4; ngp++) {
                uint32_t br = base + G_W_H + (wn*64 + ngp*16 + (lt>>1)*8 + lr) * GSTR
                            + kc*32 + (lt&1)*16;
                ldsm4(bh[ngp][0], bh[ngp][1], bh[ngp][2], bh[ngp][3], br);
                ldsm4(bl[ngp][0], bl[ngp][1], bl[ngp][2], bl[ngp][3], br + (G_W_L-G_W_H));
            }
            #pragma unroll
            for (int mi = 0; mi < 2; mi++)
                #pragma unroll
                for (int ngp = 0; ngp < 4; ngp++) {
                    mma16816(acc[mi][2*ngp],   ah[mi], bh[ngp][0], bh[ngp][1]);
                    mma16816(acc[mi][2*ngp+1], ah[mi], bh[ngp][2], bh[ngp][3]);
                }
            #pragma unroll
            for (int mi = 0; mi < 2; mi++)
                #pragma unroll
                for (int ngp = 0; ngp < 4; ngp++) {
                    mma16816(acc[mi][2*ngp],   ah[mi], bl[ngp][0], bl[ngp][1]);
                    mma16816(acc[mi][2*ngp+1], ah[mi], bl[ngp][2], bl[ngp][3]);
                }
            #pragma unroll
            for (int mi = 0; mi < 2; mi++)
                #pragma unroll
                for (int ngp = 0; ngp < 4; ngp++) {
                    mma16816(acc[mi][2*ngp],   al[mi], bh[ngp][0], bh[ngp][1]);
                    mma16816(acc[mi][2*ngp+1], al[mi], bh[ngp][2], bh[ngp][3]);
                }
        }
        __syncthreads();
        if (kt + 2 < NT) { load_stage(kt + 2); CP_COMMIT(); }
    }

    #pragma unroll
    for (int mi = 0; mi < 2; mi++) {
        int row = bm + wm*32 + mi*16 + g;
        #pragma unroll
        for (int ni = 0; ni < 8; ni++) {
            int col = bn + wn*64 + ni*8 + tg*2;
            float b0 = j.bias[col], b1 = j.bias[col + 1];
            float v0 = acc[mi][ni][0] + b0, v1 = acc[mi][ni][1] + b1;
            float v2 = acc[mi][ni][2] + b0, v3 = acc[mi][ni][3] + b1;
            if (j.Cf) {
                *reinterpret_cast<float2*>(&j.Cf[(size_t)row * DD + col])     = make_float2(v0, v1);
                *reinterpret_cast<float2*>(&j.Cf[(size_t)(row+8) * DD + col]) = make_float2(v2, v3);
            } else {
                uint32_t h01, l01, h23, l23;
                split2h(v0 * j.scale, v1 * j.scale, h01, l01);
                split2h(v2 * j.scale, v3 * j.scale, h23, l23);
                *reinterpret_cast<uint32_t*>(&j.Chi[(size_t)row * DD + col])     = h01;
                *reinterpret_cast<uint32_t*>(&j.Clo[(size_t)row * DD + col])     = l01;
                *reinterpret_cast<uint32_t*>(&j.Chi[(size_t)(row+8) * DD + col]) = h23;
                *reinterpret_cast<uint32_t*>(&j.Clo[(size_t)(row+8) * DD + col]) = l23;
            }
        }
    }
}

// ---------------- fused attention + recurrence ----------------
// H double-buffered (hi+lo), V double-buffered (single fp16). 4 CTAs/SM target.
#define ASTR 144
#define A_HL 9216
#define AH_STG 18432             // per H stage (Hh + Hl)
#define AV_BASE (2*AH_STG)       // 36864
#define AV_STG 9216
#define ATT_SMEM (AV_BASE + 2*AV_STG)   // 55296

__device__ __forceinline__ void wait_chunk(int bh, int need) {
    if (threadIdx.x == 0) {
        volatile int* p = &g_prog[bh];
        while (*p < need) __nanosleep(64);
        __threadfence();
    }
    __syncthreads();
}

__global__ void __launch_bounds__(128, 4) attn_mma(const float* __restrict__ WhIn) {
    const int tid = threadIdx.x;

    // ======== producer blocks: recurrence -> fp16 hi/lo H ========
    if (blockIdx.x < BB*HH) {
        const int bh = blockIdx.x;
        const int b = bh >> 4, h = bh & 15;
        const int d = tid;
        float w = 0.f, st = 0.f;
        const float* Rp = g_Rp + ((size_t)b * SK) * DD + h * DK + d;
        size_t ho = ((size_t)b * SK) * DD + h * DK + d;
        if (d < DK) {
            const float* wp = WhIn + (size_t)h * DK * DK + (size_t)d * DK;
            #pragma unroll
            for (int k = 0; k < DK; k++) w += wp[k];
        }
        for (int c = 0; c < SK/64; c++) {
            if (d < DK) {
                #pragma unroll 1
                for (int tt = 0; tt < 64; tt += 8) {
                    int t = c*64 + tt;
                    float r[8];
                    #pragma unroll
                    for (int i = 0; i < 8; i++) r[i] = Rp[(size_t)(t + i) * DD];
                    #pragma unroll
                    for (int i = 0; i < 8; i++) {
                        st = tanhf(st * w + r[i]);
                        __half hh = __float2half_rn(st);
                        __half hl = __float2half_rn(st - __half2float(hh));
                        g_Hh[ho + (size_t)(t + i) * DD] = hh;
                        g_Hl[ho + (size_t)(t + i) * DD] = hl;
                    }
                }
            }
            __syncthreads();
            if (tid == 0) { __threadfence(); atomicExch(&g_prog[bh], c + 1); }
        }
        return;
    }

    // ======== consumer blocks: flash attention ========
    const int flat = blockIdx.x - BB*HH;
    const int bh = flat >> 5;
    const int b = bh >> 4, h = bh & 15;
    const int q0 = (flat & 31) * 64;
    const int warp = tid >> 5, lane = tid & 31;
    const int g = lane >> 2, tg = lane & 3;
    const int lt = lane >> 3, lr = lane & 7;

    extern __shared__ __align__(1024) char sm[];
    const uint32_t sb = smem_to_u32(sm);

    const size_t qbase = (size_t)(b * SQ + q0);
    const size_t kbase = (size_t)(b * SK);
    const int hofs = h * DK;

    // Q fragments: single fp16, preloaded into registers
    uint32_t qh[4][4];
    {
        size_t r0 = (qbase + warp*16 + g) * DD + hofs;
        size_t r1 = r0 + 8 * DD;
        #pragma unroll
        for (int kc = 0; kc < 4; kc++) {
            int c0 = kc*16 + tg*2;
            qh[kc][0] = *reinterpret_cast<const uint32_t*>(g_Qh + r0 + c0);
            qh[kc][1] = *reinterpret_cast<const uint32_t*>(g_Qh + r1 + c0);
            qh[kc][2] = *reinterpret_cast<const uint32_t*>(g_Qh + r0 + c0 + 8);
            qh[kc][3] = *reinterpret_cast<const uint32_t*>(g_Qh + r1 + c0 + 8);
        }
    }

    auto load_stage = [&](int kt) {
        const uint32_t hb = sb + (kt & 1) * AH_STG;
        const uint32_t vb = sb + AV_BASE + (kt & 1) * AV_STG;
        const int k0 = kt * 64;
        #pragma unroll
        for (int t = tid; t < 512; t += 128) {
            int r = t >> 3, c = t & 7;
            uint32_t ro = r * ASTR + c * 16;
            size_t src = (kbase + k0 + r) * DD + hofs + c * 8;
            CP_ASYNC16(hb + ro,        g_Hh + src);
            CP_ASYNC16(hb + ro + A_HL, g_Hl + src);
            CP_ASYNC16(vb + ro,        g_Vh + src);
        }
    };

    wait_chunk(bh, 1);
    load_stage(0); CP_COMMIT();
    wait_chunk(bh, 2);
    load_stage(1); CP_COMMIT();

    float acc[8][4];
    #pragma unroll
    for (int n = 0; n < 8; n++)
        #pragma unroll
        for (int q = 0; q < 4; q++) acc[n][q] = 0.f;
    float mrow0 = -1e30f, mrow1 = -1e30f, lrow0 = 0.f, lrow1 = 0.f;

    const int NT = SK / 64;   // 32
    for (int kt = 0; kt < NT; kt++) {
        if (kt < NT - 1) { CP_WAIT1(); } else { CP_WAIT0(); }
        __syncthreads();
        const uint32_t hbase = sb + (kt & 1) * AH_STG;

        // ---- S = Q . H^T  (2-pass: Qh x Hh, Qh x Hl) ----
        float s[8][4];
        #pragma unroll
        for (int n = 0; n < 8; n++)
            #pragma unroll
            for (int q = 0; q < 4; q++) s[n][q] = 0.f;

        #pragma unroll
        for (int kc = 0; kc < 4; kc++) {
            uint32_t hb[4][4], lb[4][4];
            #pragma unroll
            for (int ngp = 0; ngp < 4; ngp++) {
                uint32_t br = hbase + (ngp*16 + (lt>>1)*8 + lr) * ASTR + kc*32 + (lt&1)*16;
                ldsm4(hb[ngp][0], hb[ngp][1], hb[ngp][2], hb[ngp][3], br);
                ldsm4(lb[ngp][0], lb[ngp][1], lb[ngp][2], lb[ngp][3], br + A_HL);
            }
            #pragma unroll
            for (int ngp = 0; ngp < 4; ngp++) {
                mma16816h(s[2*ngp],   qh[kc], hb[ngp][0], hb[ngp][1]);
                mma16816h(s[2*ngp+1], qh[kc], hb[ngp][2], hb[ngp][3]);
            }
            #pragma unroll
            for (int ngp = 0; ngp < 4; ngp++) {
                mma16816h(s[2*ngp],   qh[kc], lb[ngp][0], lb[ngp][1]);
                mma16816h(s[2*ngp+1], qh[kc], lb[ngp][2], lb[ngp][3]);
            }
        }

        // ---- online softmax (base-2); P -> single fp16 ----
        float tm0 = mrow0, tm1 = mrow1;
        #pragma unroll
        for (int n = 0; n < 8; n++) {
            tm0 = fmaxf(tm0, fmaxf(s[n][0], s[n][1]));
            tm1 = fmaxf(tm1, fmaxf(s[n][2], s[n][3]));
        }
        tm0 = fmaxf(tm0, __shfl_xor_sync(0xffffffffu, tm0, 1));
        tm0 = fmaxf(tm0, __shfl_xor_sync(0xffffffffu, tm0, 2));
        tm1 = fmaxf(tm1, __shfl_xor_sync(0xffffffffu, tm1, 1));
        tm1 = fmaxf(tm1, __shfl_xor_sync(0xffffffffu, tm1, 2));
        float corr0 = ex2f(mrow0 - tm0), corr1 = ex2f(mrow1 - tm1);
        mrow0 = tm0; mrow1 = tm1;
        lrow0 *= corr0; lrow1 *= corr1;

        uint32_t pa[4][4];
        #pragma unroll
        for (int n = 0; n < 8; n++) {
            float p0 = ex2f(s[n][0] - tm0), p1 = ex2f(s[n][1] - tm0);
            float p2 = ex2f(s[n][2] - tm1), p3 = ex2f(s[n][3] - tm1);
            lrow0 += p0 + p1; lrow1 += p2 + p3;
            int kc = n >> 1, hf = (n & 1) * 2;
            pa[kc][hf]     = packh2(p0, p1);
            pa[kc][hf + 1] = packh2(p2, p3);
        }
        #pragma unroll
        for (int n = 0; n < 8; n++) {
            acc[n][0] *= corr0; acc[n][1] *= corr0;
            acc[n][2] *= corr1; acc[n][3] *= corr1;
        }

        // ---- acc += P . V  (single-pass fp16, V via ldmatrix.trans) ----
        {
            const uint32_t vbase = sb + AV_BASE + (kt & 1) * AV_STG;
            #pragma unroll
            for (int kc = 0; kc < 4; kc++) {
                uint32_t vh[4][4];
                #pragma unroll
                for (int ndgp = 0; ndgp < 4; ndgp++) {
                    uint32_t vr = vbase + (kc*16 + (lt&1)*8 + lr) * ASTR
                                + (ndgp*16 + (lt>>1)*8) * 2;
                    ldsm4t(vh[ndgp][0], vh[ndgp][1], vh[ndgp][2], vh[ndgp][3], vr);
                }
                #pragma unroll
                for (int ndgp = 0; ndgp < 4; ndgp++) {
                    mma16816h(acc[2*ndgp],   pa[kc], vh[ndgp][0], vh[ndgp][1]);
                    mma16816h(acc[2*ndgp+1], pa[kc], vh[ndgp][2], vh[ndgp][3]);
                }
            }
        }

        __syncthreads();
        if (kt + 2 < NT) {
            wait_chunk(bh, kt + 3);
            load_stage(kt + 2); CP_COMMIT();
        }
    }

    // epilogue: normalize, split to bf16 hi/lo for the Wo GEMM
    lrow0 += __shfl_xor_sync(0xffffffffu, lrow0, 1);
    lrow0 += __shfl_xor_sync(0xffffffffu, lrow0, 2);
    lrow1 += __shfl_xor_sync(0xffffffffu, lrow1, 1);
    lrow1 += __shfl_xor_sync(0xffffffffu, lrow1, 2);
    float inv0 = 1.f / lrow0, inv1 = 1.f / lrow1;
    size_t row = qbase + warp*16 + g;
    #pragma unroll
    for (int nd = 0; nd < 8; nd++) {
        int col = hofs + nd*8 + tg*2;
        uint32_t h01, l01, h23, l23;
        split2(acc[nd][0] * inv0, acc[nd][1] * inv0, h01, l01);
        split2(acc[nd][2] * inv1, acc[nd][3] * inv1, h23, l23);
        *reinterpret_cast<uint32_t*>(&g_Aqh[row * DD + col])       = h01;
        *reinterpret_cast<uint32_t*>(&g_Aql[row * DD + col])       = l01;
        *reinterpret_cast<uint32_t*>(&g_Aqh[(row + 8) * DD + col]) = h23;
        *reinterpret_cast<uint32_t*>(&g_Aql[(row + 8) * DD + col]) = l23;
    }
}

// ---------------- launch ----------------
extern "C" void kernel_launch(void* const* d_in, const int* in_sizes, int n_in,
                              void* d_out, int out_size) {
    const float* query = (const float*)d_in[0];
    // d_in[1] = key : unused by the reference computation
    const float* value = (const float*)d_in[2];
    const float* Rin   = (const float*)d_in[3];
    const float* Wq    = (const float*)d_in[4];
    const float* bq    = (const float*)d_in[5];
    const float* Wv    = (const float*)d_in[6];
    const float* bv    = (const float*)d_in[7];
    const float* Wr    = (const float*)d_in[8];
    const float* br    = (const float*)d_in[9];
    const float* Wh    = (const float*)d_in[10];
    const float* Wo    = (const float*)d_in[11];
    const float* bo    = (const float*)d_in[12];
    float* out = (float*)d_out;

    float* Rp;
    __nv_bfloat16 *Aqh, *Aql, *Avh, *Avl, *Arh, *Arl;
    __nv_bfloat16 *Wqh, *Wql, *Wvh, *Wvl, *Wrh, *Wrl, *Woh, *Wol;
    __half *Qh, *Ql, *Vh, *Vl;
    cudaGetSymbolAddress((void**)&Rp, g_Rp);
    cudaGetSymbolAddress((void**)&Aqh, g_Aqh); cudaGetSymbolAddress((void**)&Aql, g_Aql);
    cudaGetSymbolAddress((void**)&Avh, g_Avh); cudaGetSymbolAddress((void**)&Avl, g_Avl);
    cudaGetSymbolAddress((void**)&Arh, g_Arh); cudaGetSymbolAddress((void**)&Arl, g_Arl);
    cudaGetSymbolAddress((void**)&Wqh, g_Wqh); cudaGetSymbolAddress((void**)&Wql, g_Wql);
    cudaGetSymbolAddress((void**)&Wvh, g_Wvh); cudaGetSymbolAddress((void**)&Wvl, g_Wvl);
    cudaGetSymbolAddress((void**)&Wrh, g_Wrh); cudaGetSymbolAddress((void**)&Wrl, g_Wrl);
    cudaGetSymbolAddress((void**)&Woh, g_Woh); cudaGetSymbolAddress((void**)&Wol, g_Wol);
    cudaGetSymbolAddress((void**)&Qh, g_Qh);   cudaGetSymbolAddress((void**)&Ql, g_Ql);
    cudaGetSymbolAddress((void**)&Vh, g_Vh);   cudaGetSymbolAddress((void**)&Vl, g_Vl);

    cudaFuncSetAttribute(gemm_mma,
                         cudaFuncAttributeMaxDynamicSharedMemorySize, GEMM_SMEM);
    cudaFuncSetAttribute(attn_mma,
                         cudaFuncAttributeMaxDynamicSharedMemorySize, ATT_SMEM);

    const int nA4 = MROWS * DD / 4;
    const int nW4 = DD * DD / 4;

    conv_split4<<<dim3(nA4 / 256, 3), 256>>>(query, value, Rin, query,
                                             Aqh, Aql, Avh, Avl, Arh, Arl, Aqh, Aql, nA4);
    conv_split4<<<dim3(nW4 / 256, 4), 256>>>(Wq, Wv, Wr, Wo,
                                             Wqh, Wql, Wvh, Wvl, Wrh, Wrl, Woh, Wol, nW4);

    GemmJob jq = { Aqh, Aql, Wqh, Wql, bq, nullptr, Qh, Ql, QK_SCALE };
    GemmJob jv = { Avh, Avl, Wvh, Wvl, bv, nullptr, Vh, Vl, 1.0f };
    GemmJob jr = { Arh, Arl, Wrh, Wrl, br, Rp, nullptr, nullptr, 1.0f };
    gemm_mma<<<dim3(DD/128, MROWS/128, 3), 256, GEMM_SMEM>>>(jq, jv, jr);

    attn_mma<<<BB*HH + BB*HH*(SQ/64), 128, ATT_SMEM>>>(Wh);

    GemmJob jo = { Aqh, Aql, Woh, Wol, bo, out, nullptr, nullptr, 1.0f };
    gemm_mma<<<dim3(DD/128, MROWS/128, 1), 256, GEMM_SMEM>>>(jo, jo, jo);
}